// round 1
// baseline (speedup 1.0000x reference)
#include <cuda_runtime.h>
#include <math.h>

#define NN 16
#define CC 256
#define HH 64
#define WW 64
#define LL 4096
#define KK 32
#define EPSV 1e-12f

// ---------------- scratch (device globals; no allocation) ----------------
__device__ float g_xn[NN * CC * LL];     // 64 MB: l2-normalized feature
__device__ float g_sa[NN * KK * LL];     // 8 MB : softmax assignment
__device__ float g_ssum[NN * KK];        // sum_l sa
__device__ float g_up0[NN * KK * CC];    // raw einsum result
__device__ float g_bias1[NN * CC];       // effective t1 bias per (n, outc)

// ---------------- kernel 1: per-pixel L2 norm over C ----------------
__global__ __launch_bounds__(256) void k_l2norm(const float* __restrict__ f) {
    int t = blockIdx.x * 256 + threadIdx.x;   // 16384 threads, 4 pixels each
    int n = t >> 10;                           // LL/4 = 1024
    int l4 = (t & 1023) << 2;
    size_t base = (size_t)n * CC * LL + l4;
    float sx = 0.f, sy = 0.f, sz = 0.f, sw = 0.f;
    for (int c = 0; c < CC; c++) {
        float4 v = *(const float4*)(f + base + (size_t)c * LL);
        sx += v.x * v.x; sy += v.y * v.y; sz += v.z * v.z; sw += v.w * v.w;
    }
    float ix = 1.f / fmaxf(sqrtf(sx), EPSV);
    float iy = 1.f / fmaxf(sqrtf(sy), EPSV);
    float iz = 1.f / fmaxf(sqrtf(sz), EPSV);
    float iw = 1.f / fmaxf(sqrtf(sw), EPSV);
    for (int c = 0; c < CC; c++) {
        float4 v = *(const float4*)(f + base + (size_t)c * LL);
        v.x *= ix; v.y *= iy; v.z *= iz; v.w *= iw;
        *(float4*)(g_xn + base + (size_t)c * LL) = v;
    }
}

// ---------------- kernel 2: 3x3 conv (256->32, pad 1) + softmax over K ----------------
// block = one 16x16 pixel tile; 128 threads, 2 pixels per thread, 32 accumulators each.
__global__ __launch_bounds__(128) void k_conv_softmax(const float* __restrict__ w,
                                                      const float* __restrict__ bias) {
    __shared__ float xs[8][18][20];   // 8-channel chunk, 18x18 halo tile, padded row
    __shared__ float ws[8][9][32];    // weights: [cc][r*3+s][k] (k contiguous -> float4)
    __shared__ float bsm[32];
    int n = blockIdx.z;
    int ty0 = blockIdx.y * 16, tx0 = blockIdx.x * 16;
    int tid = threadIdx.x;
    int lx = tid & 15, ly = tid >> 4;   // ly in 0..7
    if (tid < 32) bsm[tid] = bias[tid];

    float acc0[32], acc1[32];
#pragma unroll
    for (int k = 0; k < 32; k++) { acc0[k] = 0.f; acc1[k] = 0.f; }

    for (int c0 = 0; c0 < CC; c0 += 8) {
        __syncthreads();
        // load 8 x 18 x 18 halo tile of g_xn (zero-padded)
        for (int i = tid; i < 8 * 18 * 18; i += 128) {
            int cc = i / 324; int rem = i - cc * 324;
            int yy = rem / 18; int xx = rem - yy * 18;
            int gy = ty0 + yy - 1, gx = tx0 + xx - 1;
            float v = 0.f;
            if ((unsigned)gy < 64u && (unsigned)gx < 64u)
                v = g_xn[(n * CC + c0 + cc) * LL + gy * 64 + gx];
            xs[cc][yy][xx] = v;
        }
        // load weight chunk, transposed to k-contiguous
        for (int i = tid; i < 8 * 9 * 32; i += 128) {
            int k = i & 31; int rs = (i >> 5) % 9; int cc = i / 288;
            ws[cc][rs][k] = w[(k * CC + c0 + cc) * 9 + rs];
        }
        __syncthreads();
#pragma unroll 2
        for (int cc = 0; cc < 8; cc++) {
#pragma unroll
            for (int r = 0; r < 3; r++) {
#pragma unroll
                for (int s = 0; s < 3; s++) {
                    float x0 = xs[cc][ly + r][lx + s];
                    float x1 = xs[cc][ly + 8 + r][lx + s];
                    const float4* wp = (const float4*)&ws[cc][r * 3 + s][0];
#pragma unroll
                    for (int k4 = 0; k4 < 8; k4++) {
                        float4 wv = wp[k4];
                        acc0[k4 * 4 + 0] += wv.x * x0; acc0[k4 * 4 + 1] += wv.y * x0;
                        acc0[k4 * 4 + 2] += wv.z * x0; acc0[k4 * 4 + 3] += wv.w * x0;
                        acc1[k4 * 4 + 0] += wv.x * x1; acc1[k4 * 4 + 1] += wv.y * x1;
                        acc1[k4 * 4 + 2] += wv.z * x1; acc1[k4 * 4 + 3] += wv.w * x1;
                    }
                }
            }
        }
    }
    // softmax over K per pixel (fully thread-local)
    int px = tx0 + lx;
    {
        int py = ty0 + ly;
        float m = -1e30f;
#pragma unroll
        for (int k = 0; k < 32; k++) { acc0[k] += bsm[k]; m = fmaxf(m, acc0[k]); }
        float s = 0.f;
#pragma unroll
        for (int k = 0; k < 32; k++) { acc0[k] = __expf(acc0[k] - m); s += acc0[k]; }
        float inv = 1.f / s;
#pragma unroll
        for (int k = 0; k < 32; k++)
            g_sa[(n * KK + k) * LL + py * 64 + px] = acc0[k] * inv;
    }
    {
        int py = ty0 + ly + 8;
        float m = -1e30f;
#pragma unroll
        for (int k = 0; k < 32; k++) { acc1[k] += bsm[k]; m = fmaxf(m, acc1[k]); }
        float s = 0.f;
#pragma unroll
        for (int k = 0; k < 32; k++) { acc1[k] = __expf(acc1[k] - m); s += acc1[k]; }
        float inv = 1.f / s;
#pragma unroll
        for (int k = 0; k < 32; k++)
            g_sa[(n * KK + k) * LL + py * 64 + px] = acc1[k] * inv;
    }
}

// ---------------- kernel 3: ssum[n,k] = sum_l sa[n,k,l] ----------------
__global__ __launch_bounds__(256) void k_ssum() {
    int bk = blockIdx.x;   // n*KK + k
    float s = 0.f;
    for (int i = threadIdx.x; i < LL; i += 256) s += g_sa[bk * LL + i];
    __shared__ float red[8];
    for (int off = 16; off; off >>= 1) s += __shfl_xor_sync(0xffffffffu, s, off);
    int lane = threadIdx.x & 31, wp = threadIdx.x >> 5;
    if (!lane) red[wp] = s;
    __syncthreads();
    if (threadIdx.x == 0) {
        float t = 0.f;
        for (int i = 0; i < 8; i++) t += red[i];
        g_ssum[bk] = t;
    }
}

// ---------------- kernel 4: up0[n,k,c] = sum_l sa[n,k,l] * xn[n,c,l] ----------------
// block = (n, 64-wide c tile); 256 threads; microtile 2k x 4c per thread.
__global__ __launch_bounds__(256) void k_up0() {
    int n = blockIdx.y;
    int c0 = blockIdx.x * 64;
    __shared__ float sas[64][33];   // [l][k]
    __shared__ float xns[64][65];   // [l][c]
    int tid = threadIdx.x;
    int kt = tid >> 4, ct = tid & 15;
    float acc[2][4] = {{0.f, 0.f, 0.f, 0.f}, {0.f, 0.f, 0.f, 0.f}};
    for (int l0 = 0; l0 < LL; l0 += 64) {
        __syncthreads();
        for (int i = tid; i < 2048; i += 256) {
            int k = i >> 6, l = i & 63;
            sas[l][k] = g_sa[(n * KK + k) * LL + l0 + l];
        }
        for (int i = tid; i < 4096; i += 256) {
            int c = i >> 6, l = i & 63;
            xns[l][c] = g_xn[(n * CC + c0 + c) * LL + l0 + l];
        }
        __syncthreads();
#pragma unroll 4
        for (int l = 0; l < 64; l++) {
            float a0 = sas[l][kt], a1 = sas[l][kt + 16];
#pragma unroll
            for (int j = 0; j < 4; j++) {
                float bv = xns[l][ct + 16 * j];
                acc[0][j] += a0 * bv;
                acc[1][j] += a1 * bv;
            }
        }
    }
#pragma unroll
    for (int i = 0; i < 2; i++)
#pragma unroll
        for (int j = 0; j < 4; j++)
            g_up0[(n * KK + kt + 16 * i) * CC + c0 + ct + 16 * j] = acc[i][j];
}

// ---------------- kernel 5: centroid-sub, row norm, global norm, FC, effective bias ----------------
__global__ __launch_bounds__(256) void k_upfc(const float* __restrict__ cent,
                                              const float* __restrict__ wfc,
                                              const float* __restrict__ bfc,
                                              const float* __restrict__ t1w,
                                              const float* __restrict__ t1b) {
    int n = blockIdx.x;
    int tid = threadIdx.x;
    int lane = tid & 31, wp = tid >> 5;
    __shared__ float upn[KK * CC];   // 8192 floats
    __shared__ float rn[KK];
    __shared__ float red[8];
    __shared__ float ufc[CC];
    __shared__ float gtot;

    // step 1: u = up0 - ssum*centroid, row (per-k) L2 norm
    for (int k = wp; k < KK; k += 8) {
        float sk = g_ssum[n * KK + k];
        float vals[8];
        float sq = 0.f;
#pragma unroll
        for (int j = 0; j < 8; j++) {
            int c = lane + 32 * j;
            float u = g_up0[(n * KK + k) * CC + c] - sk * cent[k * CC + c];
            vals[j] = u;
            sq += u * u;
        }
        for (int off = 16; off; off >>= 1) sq += __shfl_xor_sync(0xffffffffu, sq, off);
        float inv = 1.f / fmaxf(sqrtf(sq), EPSV);
#pragma unroll
        for (int j = 0; j < 8; j++) upn[k * CC + lane + 32 * j] = vals[j] * inv;
    }
    __syncthreads();
    // step 2: global L2 norm over all 8192
    float gs = 0.f;
#pragma unroll 4
    for (int j = 0; j < 32; j++) {
        float v = upn[j * 256 + tid];
        gs += v * v;
    }
    for (int off = 16; off; off >>= 1) gs += __shfl_xor_sync(0xffffffffu, gs, off);
    if (!lane) red[wp] = gs;
    __syncthreads();
    if (tid == 0) {
        float t = 0.f;
        for (int i = 0; i < 8; i++) t += red[i];
        gtot = 1.f / fmaxf(sqrtf(t), EPSV);
    }
    __syncthreads();
    float ginv = gtot;
#pragma unroll 4
    for (int j = 0; j < 32; j++) upn[j * 256 + tid] *= ginv;
    __syncthreads();
    // step 3: FC  ufc[o] = sum_j upn[j]*wfc[o,j] + bfc[o]   (warp per o)
    for (int it = 0; it < 32; it++) {
        int o = it * 8 + wp;
        const float4* wr = (const float4*)(wfc + (size_t)o * (KK * CC));
        const float4* ur = (const float4*)upn;
        float s = 0.f;
        for (int m = lane; m < (KK * CC) / 4; m += 32) {
            float4 a = wr[m], u = ur[m];
            s += a.x * u.x + a.y * u.y + a.z * u.z + a.w * u.w;
        }
        for (int off = 16; off; off >>= 1) s += __shfl_xor_sync(0xffffffffu, s, off);
        if (!lane) ufc[o] = s + bfc[o];
    }
    __syncthreads();
    // step 4: effective t1 bias: bias1[n,o] = t1_b[o] + sum_c t1_w[o, 256+c] * ufc[c]
    for (int it = 0; it < 32; it++) {
        int o = it * 8 + wp;
        float s = 0.f;
#pragma unroll
        for (int m = lane; m < 256; m += 32)
            s += t1w[(size_t)o * 512 + 256 + m] * ufc[m];
        for (int off = 16; off; off >>= 1) s += __shfl_xor_sync(0xffffffffu, s, off);
        if (!lane) g_bias1[n * CC + o] = t1b[o] + s;
    }
}

// ---------------- kernel 6: fused relu(t1) -> relu(t2), per 64-pixel tile ----------------
#define AS_PITCH 260
__global__ __launch_bounds__(256) void k_transform(const float* __restrict__ feat,
                                                   const float* __restrict__ t1w,
                                                   const float* __restrict__ t2w,
                                                   const float* __restrict__ t2b,
                                                   float* __restrict__ out) {
    extern __shared__ float sm[];
    float* hbuf = sm;                       // 256 x 64
    float* As = sm + 256 * 64;              // 16 x AS_PITCH  (A^T tile: [c'][o])
    float* Bs = As + 16 * AS_PITCH;         // 16 x 64
    int n = blockIdx.y;
    int p0 = blockIdx.x * 64;
    int tid = threadIdx.x;
    int ot = tid >> 3, pt = tid & 7;        // 32 x 8 thread grid
    int o0 = ot * 8, pp = pt * 8;

    float acc[8][8];
    // -------- phase 1: h = relu(t1_w1 @ feature_tile + bias1) --------
#pragma unroll
    for (int i = 0; i < 8; i++) {
        float bv = g_bias1[n * CC + o0 + i];
#pragma unroll
        for (int j = 0; j < 8; j++) acc[i][j] = bv;
    }
    for (int k0 = 0; k0 < 256; k0 += 16) {
        __syncthreads();
        {   // load A tile (t1_w, first 256 input channels), coalesced, store transposed
            int o = tid >> 2;
            int c4 = (tid & 3) * 4;
#pragma unroll
            for (int it = 0; it < 4; it++) {
                int oo = o + 64 * it;
                float4 v = *(const float4*)(t1w + (size_t)oo * 512 + k0 + c4);
                As[(c4 + 0) * AS_PITCH + oo] = v.x;
                As[(c4 + 1) * AS_PITCH + oo] = v.y;
                As[(c4 + 2) * AS_PITCH + oo] = v.z;
                As[(c4 + 3) * AS_PITCH + oo] = v.w;
            }
        }
        {   // load B tile (feature)
            int c = tid >> 4;
            int p4 = (tid & 15) * 4;
            float4 v = *(const float4*)(feat + (size_t)(n * CC + k0 + c) * LL + p0 + p4);
            *(float4*)(Bs + c * 64 + p4) = v;
        }
        __syncthreads();
#pragma unroll
        for (int kk = 0; kk < 16; kk++) {
            float4 a0 = *(const float4*)(As + kk * AS_PITCH + o0);
            float4 a1 = *(const float4*)(As + kk * AS_PITCH + o0 + 4);
            float4 b0 = *(const float4*)(Bs + kk * 64 + pp);
            float4 b1 = *(const float4*)(Bs + kk * 64 + pp + 4);
            float av[8] = {a0.x, a0.y, a0.z, a0.w, a1.x, a1.y, a1.z, a1.w};
            float bv[8] = {b0.x, b0.y, b0.z, b0.w, b1.x, b1.y, b1.z, b1.w};
#pragma unroll
            for (int i = 0; i < 8; i++)
#pragma unroll
                for (int j = 0; j < 8; j++)
                    acc[i][j] += av[i] * bv[j];
        }
    }
    __syncthreads();
#pragma unroll
    for (int i = 0; i < 8; i++)
#pragma unroll
        for (int j = 0; j < 8; j++)
            hbuf[(o0 + i) * 64 + pp + j] = fmaxf(acc[i][j], 0.f);
    __syncthreads();

    // -------- phase 2: out = relu(t2_w @ h + t2_b) --------
#pragma unroll
    for (int i = 0; i < 8; i++) {
        float bv = t2b[o0 + i];
#pragma unroll
        for (int j = 0; j < 8; j++) acc[i][j] = bv;
    }
    for (int k0 = 0; k0 < 256; k0 += 16) {
        __syncthreads();
        {
            int o = tid >> 2;
            int c4 = (tid & 3) * 4;
#pragma unroll
            for (int it = 0; it < 4; it++) {
                int oo = o + 64 * it;
                float4 v = *(const float4*)(t2w + (size_t)oo * 256 + k0 + c4);
                As[(c4 + 0) * AS_PITCH + oo] = v.x;
                As[(c4 + 1) * AS_PITCH + oo] = v.y;
                As[(c4 + 2) * AS_PITCH + oo] = v.z;
                As[(c4 + 3) * AS_PITCH + oo] = v.w;
            }
        }
        __syncthreads();
#pragma unroll
        for (int kk = 0; kk < 16; kk++) {
            float4 a0 = *(const float4*)(As + kk * AS_PITCH + o0);
            float4 a1 = *(const float4*)(As + kk * AS_PITCH + o0 + 4);
            float4 b0 = *(const float4*)(hbuf + (k0 + kk) * 64 + pp);
            float4 b1 = *(const float4*)(hbuf + (k0 + kk) * 64 + pp + 4);
            float av[8] = {a0.x, a0.y, a0.z, a0.w, a1.x, a1.y, a1.z, a1.w};
            float bv[8] = {b0.x, b0.y, b0.z, b0.w, b1.x, b1.y, b1.z, b1.w};
#pragma unroll
            for (int i = 0; i < 8; i++)
#pragma unroll
                for (int j = 0; j < 8; j++)
                    acc[i][j] += av[i] * bv[j];
        }
    }
#pragma unroll
    for (int i = 0; i < 8; i++) {
        float4 v0, v1;
        v0.x = fmaxf(acc[i][0], 0.f); v0.y = fmaxf(acc[i][1], 0.f);
        v0.z = fmaxf(acc[i][2], 0.f); v0.w = fmaxf(acc[i][3], 0.f);
        v1.x = fmaxf(acc[i][4], 0.f); v1.y = fmaxf(acc[i][5], 0.f);
        v1.z = fmaxf(acc[i][6], 0.f); v1.w = fmaxf(acc[i][7], 0.f);
        *(float4*)(out + (size_t)(n * CC + o0 + i) * LL + p0 + pp) = v0;
        *(float4*)(out + (size_t)(n * CC + o0 + i) * LL + p0 + pp + 4) = v1;
    }
}

// ---------------- launch ----------------
extern "C" void kernel_launch(void* const* d_in, const int* in_sizes, int n_in,
                              void* d_out, int out_size) {
    (void)in_sizes; (void)n_in; (void)out_size;
    const float* feature   = (const float*)d_in[0];
    const float* conv_up_w = (const float*)d_in[1];
    const float* conv_up_b = (const float*)d_in[2];
    const float* centroids = (const float*)d_in[3];
    const float* upfc_w    = (const float*)d_in[4];
    const float* upfc_b    = (const float*)d_in[5];
    const float* t1_w      = (const float*)d_in[6];
    const float* t1_b      = (const float*)d_in[7];
    const float* t2_w      = (const float*)d_in[8];
    const float* t2_b      = (const float*)d_in[9];
    float* out = (float*)d_out;

    const int SMEM6 = (256 * 64 + 16 * AS_PITCH + 16 * 64) * 4;
    cudaFuncSetAttribute(k_transform, cudaFuncAttributeMaxDynamicSharedMemorySize, SMEM6);

    k_l2norm<<<64, 256>>>(feature);
    k_conv_softmax<<<dim3(4, 4, 16), 128>>>(conv_up_w, conv_up_b);
    k_ssum<<<NN * KK, 256>>>();
    k_up0<<<dim3(4, 16), 256>>>();
    k_upfc<<<NN, 256>>>(centroids, upfc_w, upfc_b, t1_w, t1_b);
    k_transform<<<dim3(64, 16), 256, SMEM6>>>(feature, t1_w, t2_w, t2_b, out);
}

// round 2
// speedup vs baseline: 1.2627x; 1.2627x over previous
#include <cuda_runtime.h>
#include <math.h>

#define NN 16
#define CC 256
#define HH 64
#define WW 64
#define LL 4096
#define KK 32
#define EPSV 1e-12f
#define SPL 16   // L-splits for k_up0

// ---------------- scratch (device globals; no allocation) ----------------
__device__ float g_xn[NN * CC * LL];          // 64 MB: l2-normalized feature
__device__ float g_sa[NN * KK * LL];          // 8 MB : softmax assignment
__device__ float g_ssum[NN * KK];             // sum_l sa
__device__ float g_up0p[SPL * NN * KK * CC];  // 8 MB : einsum partials per L-split
__device__ float g_up0[NN * KK * CC];         // reduced einsum result
__device__ float g_bias1[NN * CC];            // effective t1 bias per (n, outc)

// ---------------- kernel 1: per-pixel L2 norm over C ----------------
// grid (16 pixel-chunks, 16 n), 256 threads, 1 pixel/thread. Coalesced scalar
// loads; second pass re-reads from L2 (concurrent slab ~64MB < 126MB L2).
__global__ __launch_bounds__(256) void k_l2norm(const float* __restrict__ f) {
    int n = blockIdx.y;
    int l = blockIdx.x * 256 + threadIdx.x;
    size_t base = (size_t)n * CC * LL + l;
    float s = 0.f;
#pragma unroll 8
    for (int c = 0; c < CC; c++) {
        float v = f[base + (size_t)c * LL];
        s += v * v;
    }
    float inv = 1.f / fmaxf(sqrtf(s), EPSV);
#pragma unroll 8
    for (int c = 0; c < CC; c++)
        g_xn[base + (size_t)c * LL] = f[base + (size_t)c * LL] * inv;
}

// ---------------- kernel 2: 3x3 conv (256->32, pad 1) + softmax over K ----------------
__global__ __launch_bounds__(128) void k_conv_softmax(const float* __restrict__ w,
                                                      const float* __restrict__ bias) {
    __shared__ float xs[8][18][20];   // 8-channel chunk, 18x18 halo tile, padded row
    __shared__ float ws[8][9][32];    // weights: [cc][r*3+s][k]
    __shared__ float bsm[32];
    int n = blockIdx.z;
    int ty0 = blockIdx.y * 16, tx0 = blockIdx.x * 16;
    int tid = threadIdx.x;
    int lx = tid & 15, ly = tid >> 4;   // ly in 0..7
    if (tid < 32) bsm[tid] = bias[tid];

    float acc0[32], acc1[32];
#pragma unroll
    for (int k = 0; k < 32; k++) { acc0[k] = 0.f; acc1[k] = 0.f; }

    for (int c0 = 0; c0 < CC; c0 += 8) {
        __syncthreads();
        for (int i = tid; i < 8 * 18 * 18; i += 128) {
            int cc = i / 324; int rem = i - cc * 324;
            int yy = rem / 18; int xx = rem - yy * 18;
            int gy = ty0 + yy - 1, gx = tx0 + xx - 1;
            float v = 0.f;
            if ((unsigned)gy < 64u && (unsigned)gx < 64u)
                v = g_xn[(n * CC + c0 + cc) * LL + gy * 64 + gx];
            xs[cc][yy][xx] = v;
        }
        for (int i = tid; i < 8 * 9 * 32; i += 128) {
            int k = i & 31; int rs = (i >> 5) % 9; int cc = i / 288;
            ws[cc][rs][k] = w[(k * CC + c0 + cc) * 9 + rs];
        }
        __syncthreads();
#pragma unroll 2
        for (int cc = 0; cc < 8; cc++) {
#pragma unroll
            for (int r = 0; r < 3; r++) {
#pragma unroll
                for (int s = 0; s < 3; s++) {
                    float x0 = xs[cc][ly + r][lx + s];
                    float x1 = xs[cc][ly + 8 + r][lx + s];
                    const float4* wp = (const float4*)&ws[cc][r * 3 + s][0];
#pragma unroll
                    for (int k4 = 0; k4 < 8; k4++) {
                        float4 wv = wp[k4];
                        acc0[k4 * 4 + 0] += wv.x * x0; acc0[k4 * 4 + 1] += wv.y * x0;
                        acc0[k4 * 4 + 2] += wv.z * x0; acc0[k4 * 4 + 3] += wv.w * x0;
                        acc1[k4 * 4 + 0] += wv.x * x1; acc1[k4 * 4 + 1] += wv.y * x1;
                        acc1[k4 * 4 + 2] += wv.z * x1; acc1[k4 * 4 + 3] += wv.w * x1;
                    }
                }
            }
        }
    }
    int px = tx0 + lx;
    {
        int py = ty0 + ly;
        float m = -1e30f;
#pragma unroll
        for (int k = 0; k < 32; k++) { acc0[k] += bsm[k]; m = fmaxf(m, acc0[k]); }
        float s = 0.f;
#pragma unroll
        for (int k = 0; k < 32; k++) { acc0[k] = __expf(acc0[k] - m); s += acc0[k]; }
        float inv = 1.f / s;
#pragma unroll
        for (int k = 0; k < 32; k++)
            g_sa[(n * KK + k) * LL + py * 64 + px] = acc0[k] * inv;
    }
    {
        int py = ty0 + ly + 8;
        float m = -1e30f;
#pragma unroll
        for (int k = 0; k < 32; k++) { acc1[k] += bsm[k]; m = fmaxf(m, acc1[k]); }
        float s = 0.f;
#pragma unroll
        for (int k = 0; k < 32; k++) { acc1[k] = __expf(acc1[k] - m); s += acc1[k]; }
        float inv = 1.f / s;
#pragma unroll
        for (int k = 0; k < 32; k++)
            g_sa[(n * KK + k) * LL + py * 64 + px] = acc1[k] * inv;
    }
}

// ---------------- kernel 3: ssum[n,k] = sum_l sa[n,k,l] ----------------
__global__ __launch_bounds__(256) void k_ssum() {
    int bk = blockIdx.x;   // n*KK + k
    float s = 0.f;
    for (int i = threadIdx.x; i < LL; i += 256) s += g_sa[bk * LL + i];
    __shared__ float red[8];
    for (int off = 16; off; off >>= 1) s += __shfl_xor_sync(0xffffffffu, s, off);
    int lane = threadIdx.x & 31, wp = threadIdx.x >> 5;
    if (!lane) red[wp] = s;
    __syncthreads();
    if (threadIdx.x == 0) {
        float t = 0.f;
        for (int i = 0; i < 8; i++) t += red[i];
        g_ssum[bk] = t;
    }
}

// ---------------- kernel 4: up0p[sp,n,k,c] = sum_{l in split} sa[n,k,l]*xn[n,c,l] ----------------
// grid (4 c-tiles, 16 n, 16 L-splits) = 1024 CTAs; 256 threads; 2k x 4c microtile.
__global__ __launch_bounds__(256) void k_up0() {
    int n = blockIdx.y;
    int c0 = blockIdx.x * 64;
    int sp = blockIdx.z;
    int lbase = sp * (LL / SPL);   // 256 l's per split
    __shared__ float sas[64][33];   // [l][k]
    __shared__ float xns[64][65];   // [l][c]
    int tid = threadIdx.x;
    int kt = tid >> 4, ct = tid & 15;
    float acc[2][4] = {{0.f, 0.f, 0.f, 0.f}, {0.f, 0.f, 0.f, 0.f}};
    for (int l0 = lbase; l0 < lbase + (LL / SPL); l0 += 64) {
        __syncthreads();
        for (int i = tid; i < 2048; i += 256) {
            int k = i >> 6, l = i & 63;
            sas[l][k] = g_sa[(n * KK + k) * LL + l0 + l];
        }
        for (int i = tid; i < 4096; i += 256) {
            int c = i >> 6, l = i & 63;
            xns[l][c] = g_xn[(n * CC + c0 + c) * LL + l0 + l];
        }
        __syncthreads();
#pragma unroll 4
        for (int l = 0; l < 64; l++) {
            float a0 = sas[l][kt], a1 = sas[l][kt + 16];
#pragma unroll
            for (int j = 0; j < 4; j++) {
                float bv = xns[l][ct + 16 * j];
                acc[0][j] += a0 * bv;
                acc[1][j] += a1 * bv;
            }
        }
    }
#pragma unroll
    for (int i = 0; i < 2; i++)
#pragma unroll
        for (int j = 0; j < 4; j++)
            g_up0p[((size_t)sp * NN + n) * (KK * CC) + (kt + 16 * i) * CC + c0 + ct + 16 * j]
                = acc[i][j];
}

// ---------------- kernel 4b: deterministic reduce of L-split partials ----------------
__global__ __launch_bounds__(256) void k_up0red() {
    int i = blockIdx.x * 256 + threadIdx.x;   // NN*KK*CC = 131072 elems
    float s = 0.f;
#pragma unroll
    for (int sp = 0; sp < SPL; sp++)
        s += g_up0p[(size_t)sp * (NN * KK * CC) + i];
    g_up0[i] = s;
}

// ---------------- kernel 5: centroid-sub, row norm, global norm, FC, effective bias ----------------
__global__ __launch_bounds__(256) void k_upfc(const float* __restrict__ cent,
                                              const float* __restrict__ wfc,
                                              const float* __restrict__ bfc,
                                              const float* __restrict__ t1w,
                                              const float* __restrict__ t1b) {
    int n = blockIdx.x;
    int tid = threadIdx.x;
    int lane = tid & 31, wp = tid >> 5;
    __shared__ float upn[KK * CC];   // 8192 floats
    __shared__ float red[8];
    __shared__ float ufc[CC];
    __shared__ float gtot;

    for (int k = wp; k < KK; k += 8) {
        float sk = g_ssum[n * KK + k];
        float vals[8];
        float sq = 0.f;
#pragma unroll
        for (int j = 0; j < 8; j++) {
            int c = lane + 32 * j;
            float u = g_up0[(n * KK + k) * CC + c] - sk * cent[k * CC + c];
            vals[j] = u;
            sq += u * u;
        }
        for (int off = 16; off; off >>= 1) sq += __shfl_xor_sync(0xffffffffu, sq, off);
        float inv = 1.f / fmaxf(sqrtf(sq), EPSV);
#pragma unroll
        for (int j = 0; j < 8; j++) upn[k * CC + lane + 32 * j] = vals[j] * inv;
    }
    __syncthreads();
    float gs = 0.f;
#pragma unroll 4
    for (int j = 0; j < 32; j++) {
        float v = upn[j * 256 + tid];
        gs += v * v;
    }
    for (int off = 16; off; off >>= 1) gs += __shfl_xor_sync(0xffffffffu, gs, off);
    if (!lane) red[wp] = gs;
    __syncthreads();
    if (tid == 0) {
        float t = 0.f;
        for (int i = 0; i < 8; i++) t += red[i];
        gtot = 1.f / fmaxf(sqrtf(t), EPSV);
    }
    __syncthreads();
    float ginv = gtot;
#pragma unroll 4
    for (int j = 0; j < 32; j++) upn[j * 256 + tid] *= ginv;
    __syncthreads();
    for (int it = 0; it < 32; it++) {
        int o = it * 8 + wp;
        const float4* wr = (const float4*)(wfc + (size_t)o * (KK * CC));
        const float4* ur = (const float4*)upn;
        float s = 0.f;
        for (int m = lane; m < (KK * CC) / 4; m += 32) {
            float4 a = wr[m], u = ur[m];
            s += a.x * u.x + a.y * u.y + a.z * u.z + a.w * u.w;
        }
        for (int off = 16; off; off >>= 1) s += __shfl_xor_sync(0xffffffffu, s, off);
        if (!lane) ufc[o] = s + bfc[o];
    }
    __syncthreads();
    for (int it = 0; it < 32; it++) {
        int o = it * 8 + wp;
        float s = 0.f;
#pragma unroll
        for (int m = lane; m < 256; m += 32)
            s += t1w[(size_t)o * 512 + 256 + m] * ufc[m];
        for (int off = 16; off; off >>= 1) s += __shfl_xor_sync(0xffffffffu, s, off);
        if (!lane) g_bias1[n * CC + o] = t1b[o] + s;
    }
}

// ---------------- kernel 6: fused relu(t1) -> relu(t2), per 64-pixel tile ----------------
#define AS_PITCH 260
__global__ __launch_bounds__(256) void k_transform(const float* __restrict__ feat,
                                                   const float* __restrict__ t1w,
                                                   const float* __restrict__ t2w,
                                                   const float* __restrict__ t2b,
                                                   float* __restrict__ out) {
    extern __shared__ float sm[];
    float* hbuf = sm;                       // 256 x 64
    float* As = sm + 256 * 64;              // 16 x AS_PITCH  (A^T tile: [c'][o])
    float* Bs = As + 16 * AS_PITCH;         // 16 x 64
    int n = blockIdx.y;
    int p0 = blockIdx.x * 64;
    int tid = threadIdx.x;
    int ot = tid >> 3, pt = tid & 7;        // 32 x 8 thread grid
    int o0 = ot * 8, pp = pt * 8;

    float acc[8][8];
#pragma unroll
    for (int i = 0; i < 8; i++) {
        float bv = g_bias1[n * CC + o0 + i];
#pragma unroll
        for (int j = 0; j < 8; j++) acc[i][j] = bv;
    }
    for (int k0 = 0; k0 < 256; k0 += 16) {
        __syncthreads();
        {
            int o = tid >> 2;
            int c4 = (tid & 3) * 4;
#pragma unroll
            for (int it = 0; it < 4; it++) {
                int oo = o + 64 * it;
                float4 v = *(const float4*)(t1w + (size_t)oo * 512 + k0 + c4);
                As[(c4 + 0) * AS_PITCH + oo] = v.x;
                As[(c4 + 1) * AS_PITCH + oo] = v.y;
                As[(c4 + 2) * AS_PITCH + oo] = v.z;
                As[(c4 + 3) * AS_PITCH + oo] = v.w;
            }
        }
        {
            int c = tid >> 4;
            int p4 = (tid & 15) * 4;
            float4 v = *(const float4*)(feat + (size_t)(n * CC + k0 + c) * LL + p0 + p4);
            *(float4*)(Bs + c * 64 + p4) = v;
        }
        __syncthreads();
#pragma unroll
        for (int kk = 0; kk < 16; kk++) {
            float4 a0 = *(const float4*)(As + kk * AS_PITCH + o0);
            float4 a1 = *(const float4*)(As + kk * AS_PITCH + o0 + 4);
            float4 b0 = *(const float4*)(Bs + kk * 64 + pp);
            float4 b1 = *(const float4*)(Bs + kk * 64 + pp + 4);
            float av[8] = {a0.x, a0.y, a0.z, a0.w, a1.x, a1.y, a1.z, a1.w};
            float bv[8] = {b0.x, b0.y, b0.z, b0.w, b1.x, b1.y, b1.z, b1.w};
#pragma unroll
            for (int i = 0; i < 8; i++)
#pragma unroll
                for (int j = 0; j < 8; j++)
                    acc[i][j] += av[i] * bv[j];
        }
    }
    __syncthreads();
#pragma unroll
    for (int i = 0; i < 8; i++)
#pragma unroll
        for (int j = 0; j < 8; j++)
            hbuf[(o0 + i) * 64 + pp + j] = fmaxf(acc[i][j], 0.f);
    __syncthreads();

#pragma unroll
    for (int i = 0; i < 8; i++) {
        float bv = t2b[o0 + i];
#pragma unroll
        for (int j = 0; j < 8; j++) acc[i][j] = bv;
    }
    for (int k0 = 0; k0 < 256; k0 += 16) {
        __syncthreads();
        {
            int o = tid >> 2;
            int c4 = (tid & 3) * 4;
#pragma unroll
            for (int it = 0; it < 4; it++) {
                int oo = o + 64 * it;
                float4 v = *(const float4*)(t2w + (size_t)oo * 256 + k0 + c4);
                As[(c4 + 0) * AS_PITCH + oo] = v.x;
                As[(c4 + 1) * AS_PITCH + oo] = v.y;
                As[(c4 + 2) * AS_PITCH + oo] = v.z;
                As[(c4 + 3) * AS_PITCH + oo] = v.w;
            }
        }
        __syncthreads();
#pragma unroll
        for (int kk = 0; kk < 16; kk++) {
            float4 a0 = *(const float4*)(As + kk * AS_PITCH + o0);
            float4 a1 = *(const float4*)(As + kk * AS_PITCH + o0 + 4);
            float4 b0 = *(const float4*)(hbuf + (k0 + kk) * 64 + pp);
            float4 b1 = *(const float4*)(hbuf + (k0 + kk) * 64 + pp + 4);
            float av[8] = {a0.x, a0.y, a0.z, a0.w, a1.x, a1.y, a1.z, a1.w};
            float bv[8] = {b0.x, b0.y, b0.z, b0.w, b1.x, b1.y, b1.z, b1.w};
#pragma unroll
            for (int i = 0; i < 8; i++)
#pragma unroll
                for (int j = 0; j < 8; j++)
                    acc[i][j] += av[i] * bv[j];
        }
    }
#pragma unroll
    for (int i = 0; i < 8; i++) {
        float4 v0, v1;
        v0.x = fmaxf(acc[i][0], 0.f); v0.y = fmaxf(acc[i][1], 0.f);
        v0.z = fmaxf(acc[i][2], 0.f); v0.w = fmaxf(acc[i][3], 0.f);
        v1.x = fmaxf(acc[i][4], 0.f); v1.y = fmaxf(acc[i][5], 0.f);
        v1.z = fmaxf(acc[i][6], 0.f); v1.w = fmaxf(acc[i][7], 0.f);
        *(float4*)(out + (size_t)(n * CC + o0 + i) * LL + p0 + pp) = v0;
        *(float4*)(out + (size_t)(n * CC + o0 + i) * LL + p0 + pp + 4) = v1;
    }
}

// ---------------- launch ----------------
extern "C" void kernel_launch(void* const* d_in, const int* in_sizes, int n_in,
                              void* d_out, int out_size) {
    (void)in_sizes; (void)n_in; (void)out_size;
    const float* feature   = (const float*)d_in[0];
    const float* conv_up_w = (const float*)d_in[1];
    const float* conv_up_b = (const float*)d_in[2];
    const float* centroids = (const float*)d_in[3];
    const float* upfc_w    = (const float*)d_in[4];
    const float* upfc_b    = (const float*)d_in[5];
    const float* t1_w      = (const float*)d_in[6];
    const float* t1_b      = (const float*)d_in[7];
    const float* t2_w      = (const float*)d_in[8];
    const float* t2_b      = (const float*)d_in[9];
    float* out = (float*)d_out;

    const int SMEM6 = (256 * 64 + 16 * AS_PITCH + 16 * 64) * 4;
    cudaFuncSetAttribute(k_transform, cudaFuncAttributeMaxDynamicSharedMemorySize, SMEM6);

    k_l2norm<<<dim3(16, 16), 256>>>(feature);
    k_conv_softmax<<<dim3(4, 4, 16), 128>>>(conv_up_w, conv_up_b);
    k_ssum<<<NN * KK, 256>>>();
    k_up0<<<dim3(4, 16, SPL), 256>>>();
    k_up0red<<<NN * KK * CC / 256, 256>>>();
    k_upfc<<<NN, 256>>>(centroids, upfc_w, upfc_b, t1_w, t1_b);
    k_transform<<<dim3(64, 16), 256, SMEM6>>>(feature, t1_w, t2_w, t2_b, out);
}

// round 4
// speedup vs baseline: 1.4414x; 1.1415x over previous
#include <cuda_runtime.h>
#include <cuda_bf16.h>
#include <cstdint>
#include <math.h>

#define NN 16
#define CC 256
#define HH 64
#define WW 64
#define LL 4096
#define KK 32
#define EPSV 1e-12f
#define SPL 16   // L-splits for k_up0

// ---------------- scratch (device globals; no allocation) ----------------
__device__ float g_xn[NN * CC * LL];          // 64 MB: l2-normalized feature
__device__ float g_sa[NN * KK * LL];          // 8 MB : softmax assignment
__device__ float g_ssum[NN * KK];             // sum_l sa
__device__ float g_up0p[SPL * NN * KK * CC];  // 8 MB : einsum partials per L-split
__device__ float g_up0[NN * KK * CC];         // reduced einsum result
__device__ float g_bias1[NN * CC];            // effective t1 bias per (n, outc)
__device__ __nv_bfloat16 g_w1hi[CC * CC];     // t1_w (first 256 in-chans) split
__device__ __nv_bfloat16 g_w1lo[CC * CC];
__device__ __nv_bfloat16 g_w2hi[CC * CC];     // t2_w split
__device__ __nv_bfloat16 g_w2lo[CC * CC];

static __device__ __forceinline__ uint32_t pk2(__nv_bfloat16 a, __nv_bfloat16 b) {
    return (uint32_t)__bfloat16_as_ushort(a) | ((uint32_t)__bfloat16_as_ushort(b) << 16);
}
// bf16 mma m16n8k16, fp32 accum (sm_80+, valid on baseline sm_103)
static __device__ __forceinline__ void mma16816(float* d,
                                                uint32_t a0, uint32_t a1, uint32_t a2, uint32_t a3,
                                                uint32_t b0, uint32_t b1) {
    asm volatile("mma.sync.aligned.m16n8k16.row.col.f32.bf16.bf16.f32 "
                 "{%0,%1,%2,%3}, {%4,%5,%6,%7}, {%8,%9}, {%0,%1,%2,%3};"
                 : "+f"(d[0]), "+f"(d[1]), "+f"(d[2]), "+f"(d[3])
                 : "r"(a0), "r"(a1), "r"(a2), "r"(a3), "r"(b0), "r"(b1));
}

// ---------------- kernel 1: per-pixel L2 norm over C ----------------
__global__ __launch_bounds__(256) void k_l2norm(const float* __restrict__ f) {
    int n = blockIdx.y;
    int l = blockIdx.x * 256 + threadIdx.x;
    size_t base = (size_t)n * CC * LL + l;
    float s = 0.f;
#pragma unroll 8
    for (int c = 0; c < CC; c++) {
        float v = f[base + (size_t)c * LL];
        s += v * v;
    }
    float inv = 1.f / fmaxf(sqrtf(s), EPSV);
#pragma unroll 8
    for (int c = 0; c < CC; c++)
        g_xn[base + (size_t)c * LL] = f[base + (size_t)c * LL] * inv;
}

// ---------------- kernel 2: 3x3 conv (256->32, pad 1) + softmax over K ----------------
__global__ __launch_bounds__(128) void k_conv_softmax(const float* __restrict__ w,
                                                      const float* __restrict__ bias) {
    __shared__ float xs[8][18][20];
    __shared__ float ws[8][9][32];
    __shared__ float bsm[32];
    int n = blockIdx.z;
    int ty0 = blockIdx.y * 16, tx0 = blockIdx.x * 16;
    int tid = threadIdx.x;
    int lx = tid & 15, ly = tid >> 4;
    if (tid < 32) bsm[tid] = bias[tid];

    float acc0[32], acc1[32];
#pragma unroll
    for (int k = 0; k < 32; k++) { acc0[k] = 0.f; acc1[k] = 0.f; }

    for (int c0 = 0; c0 < CC; c0 += 8) {
        __syncthreads();
        for (int i = tid; i < 8 * 18 * 18; i += 128) {
            int cc = i / 324; int rem = i - cc * 324;
            int yy = rem / 18; int xx = rem - yy * 18;
            int gy = ty0 + yy - 1, gx = tx0 + xx - 1;
            float v = 0.f;
            if ((unsigned)gy < 64u && (unsigned)gx < 64u)
                v = g_xn[(n * CC + c0 + cc) * LL + gy * 64 + gx];
            xs[cc][yy][xx] = v;
        }
        for (int i = tid; i < 8 * 9 * 32; i += 128) {
            int k = i & 31; int rs = (i >> 5) % 9; int cc = i / 288;
            ws[cc][rs][k] = w[(k * CC + c0 + cc) * 9 + rs];
        }
        __syncthreads();
#pragma unroll 2
        for (int cc = 0; cc < 8; cc++) {
#pragma unroll
            for (int r = 0; r < 3; r++) {
#pragma unroll
                for (int s = 0; s < 3; s++) {
                    float x0 = xs[cc][ly + r][lx + s];
                    float x1 = xs[cc][ly + 8 + r][lx + s];
                    const float4* wp = (const float4*)&ws[cc][r * 3 + s][0];
#pragma unroll
                    for (int k4 = 0; k4 < 8; k4++) {
                        float4 wv = wp[k4];
                        acc0[k4 * 4 + 0] += wv.x * x0; acc0[k4 * 4 + 1] += wv.y * x0;
                        acc0[k4 * 4 + 2] += wv.z * x0; acc0[k4 * 4 + 3] += wv.w * x0;
                        acc1[k4 * 4 + 0] += wv.x * x1; acc1[k4 * 4 + 1] += wv.y * x1;
                        acc1[k4 * 4 + 2] += wv.z * x1; acc1[k4 * 4 + 3] += wv.w * x1;
                    }
                }
            }
        }
    }
    int px = tx0 + lx;
    {
        int py = ty0 + ly;
        float m = -1e30f;
#pragma unroll
        for (int k = 0; k < 32; k++) { acc0[k] += bsm[k]; m = fmaxf(m, acc0[k]); }
        float s = 0.f;
#pragma unroll
        for (int k = 0; k < 32; k++) { acc0[k] = __expf(acc0[k] - m); s += acc0[k]; }
        float inv = 1.f / s;
#pragma unroll
        for (int k = 0; k < 32; k++)
            g_sa[(n * KK + k) * LL + py * 64 + px] = acc0[k] * inv;
    }
    {
        int py = ty0 + ly + 8;
        float m = -1e30f;
#pragma unroll
        for (int k = 0; k < 32; k++) { acc1[k] += bsm[k]; m = fmaxf(m, acc1[k]); }
        float s = 0.f;
#pragma unroll
        for (int k = 0; k < 32; k++) { acc1[k] = __expf(acc1[k] - m); s += acc1[k]; }
        float inv = 1.f / s;
#pragma unroll
        for (int k = 0; k < 32; k++)
            g_sa[(n * KK + k) * LL + py * 64 + px] = acc1[k] * inv;
    }
}

// ---------------- kernel 3: ssum ----------------
__global__ __launch_bounds__(256) void k_ssum() {
    int bk = blockIdx.x;
    float s = 0.f;
    for (int i = threadIdx.x; i < LL; i += 256) s += g_sa[bk * LL + i];
    __shared__ float red[8];
    for (int off = 16; off; off >>= 1) s += __shfl_xor_sync(0xffffffffu, s, off);
    int lane = threadIdx.x & 31, wp = threadIdx.x >> 5;
    if (!lane) red[wp] = s;
    __syncthreads();
    if (threadIdx.x == 0) {
        float t = 0.f;
        for (int i = 0; i < 8; i++) t += red[i];
        g_ssum[bk] = t;
    }
}

// ---------------- kernel 4: einsum partials ----------------
__global__ __launch_bounds__(256) void k_up0() {
    int n = blockIdx.y;
    int c0 = blockIdx.x * 64;
    int sp = blockIdx.z;
    int lbase = sp * (LL / SPL);
    __shared__ float sas[64][33];
    __shared__ float xns[64][65];
    int tid = threadIdx.x;
    int kt = tid >> 4, ct = tid & 15;
    float acc[2][4] = {{0.f, 0.f, 0.f, 0.f}, {0.f, 0.f, 0.f, 0.f}};
    for (int l0 = lbase; l0 < lbase + (LL / SPL); l0 += 64) {
        __syncthreads();
        for (int i = tid; i < 2048; i += 256) {
            int k = i >> 6, l = i & 63;
            sas[l][k] = g_sa[(n * KK + k) * LL + l0 + l];
        }
        for (int i = tid; i < 4096; i += 256) {
            int c = i >> 6, l = i & 63;
            xns[l][c] = g_xn[(n * CC + c0 + c) * LL + l0 + l];
        }
        __syncthreads();
#pragma unroll 4
        for (int l = 0; l < 64; l++) {
            float a0 = sas[l][kt], a1 = sas[l][kt + 16];
#pragma unroll
            for (int j = 0; j < 4; j++) {
                float bv = xns[l][ct + 16 * j];
                acc[0][j] += a0 * bv;
                acc[1][j] += a1 * bv;
            }
        }
    }
#pragma unroll
    for (int i = 0; i < 2; i++)
#pragma unroll
        for (int j = 0; j < 4; j++)
            g_up0p[((size_t)sp * NN + n) * (KK * CC) + (kt + 16 * i) * CC + c0 + ct + 16 * j]
                = acc[i][j];
}

__global__ __launch_bounds__(256) void k_up0red() {
    int i = blockIdx.x * 256 + threadIdx.x;
    float s = 0.f;
#pragma unroll
    for (int sp = 0; sp < SPL; sp++)
        s += g_up0p[(size_t)sp * (NN * KK * CC) + i];
    g_up0[i] = s;
}

// ---------------- kernel 5: norms + FC + effective bias ----------------
__global__ __launch_bounds__(256) void k_upfc(const float* __restrict__ cent,
                                              const float* __restrict__ wfc,
                                              const float* __restrict__ bfc,
                                              const float* __restrict__ t1w,
                                              const float* __restrict__ t1b) {
    int n = blockIdx.x;
    int tid = threadIdx.x;
    int lane = tid & 31, wp = tid >> 5;
    __shared__ float upn[KK * CC];
    __shared__ float red[8];
    __shared__ float ufc[CC];
    __shared__ float gtot;

    for (int k = wp; k < KK; k += 8) {
        float sk = g_ssum[n * KK + k];
        float vals[8];
        float sq = 0.f;
#pragma unroll
        for (int j = 0; j < 8; j++) {
            int c = lane + 32 * j;
            float u = g_up0[(n * KK + k) * CC + c] - sk * cent[k * CC + c];
            vals[j] = u;
            sq += u * u;
        }
        for (int off = 16; off; off >>= 1) sq += __shfl_xor_sync(0xffffffffu, sq, off);
        float inv = 1.f / fmaxf(sqrtf(sq), EPSV);
#pragma unroll
        for (int j = 0; j < 8; j++) upn[k * CC + lane + 32 * j] = vals[j] * inv;
    }
    __syncthreads();
    float gs = 0.f;
#pragma unroll 4
    for (int j = 0; j < 32; j++) {
        float v = upn[j * 256 + tid];
        gs += v * v;
    }
    for (int off = 16; off; off >>= 1) gs += __shfl_xor_sync(0xffffffffu, gs, off);
    if (!lane) red[wp] = gs;
    __syncthreads();
    if (tid == 0) {
        float t = 0.f;
        for (int i = 0; i < 8; i++) t += red[i];
        gtot = 1.f / fmaxf(sqrtf(t), EPSV);
    }
    __syncthreads();
    float ginv = gtot;
#pragma unroll 4
    for (int j = 0; j < 32; j++) upn[j * 256 + tid] *= ginv;
    __syncthreads();
    for (int it = 0; it < 32; it++) {
        int o = it * 8 + wp;
        const float4* wr = (const float4*)(wfc + (size_t)o * (KK * CC));
        const float4* ur = (const float4*)upn;
        float s = 0.f;
        for (int m = lane; m < (KK * CC) / 4; m += 32) {
            float4 a = wr[m], u = ur[m];
            s += a.x * u.x + a.y * u.y + a.z * u.z + a.w * u.w;
        }
        for (int off = 16; off; off >>= 1) s += __shfl_xor_sync(0xffffffffu, s, off);
        if (!lane) ufc[o] = s + bfc[o];
    }
    __syncthreads();
    for (int it = 0; it < 32; it++) {
        int o = it * 8 + wp;
        float s = 0.f;
#pragma unroll
        for (int m = lane; m < 256; m += 32)
            s += t1w[(size_t)o * 512 + 256 + m] * ufc[m];
        for (int off = 16; off; off >>= 1) s += __shfl_xor_sync(0xffffffffu, s, off);
        if (!lane) g_bias1[n * CC + o] = t1b[o] + s;
    }
}

// ---------------- prep: split t1/t2 weights to bf16 hi/lo ----------------
__global__ __launch_bounds__(256) void k_wsplit(const float* __restrict__ t1w,
                                                const float* __restrict__ t2w) {
    int i = blockIdx.x * 256 + threadIdx.x;   // 65536
    int o = i >> 8, c = i & 255;
    {
        float x = t1w[(size_t)o * 512 + c];
        __nv_bfloat16 h = __float2bfloat16_rn(x);
        g_w1hi[i] = h;
        g_w1lo[i] = __float2bfloat16_rn(x - __bfloat162float(h));
    }
    {
        float x = t2w[i];
        __nv_bfloat16 h = __float2bfloat16_rn(x);
        g_w2hi[i] = h;
        g_w2lo[i] = __float2bfloat16_rn(x - __bfloat162float(h));
    }
}

// ---------------- kernel 6: mma.sync fused transform ----------------
// CTA = (n, 64-px tile). 8 warps = 4 o-tiles x 2 px-tiles; warp = 64o x 32px.
// Stage1: D1[o,px] = W1 @ X (bf16 split, 3-term). h = relu(D1+bias1) -> smem.
// Stage2: D2 = W2 @ h. Epilogue: relu(D2+t2b) staged -> coalesced out.
// SMEM layout (bytes):
#define SM_B1   0          // bias1 f32[256]
#define SM_B2   1024       // t2b   f32[256]
#define SM_WHI  2048       // W chunk hi: 256 rows x 144B (64 bf16 + pad)
#define SM_WLO  38912
#define SM_XHI  75776      // X chunk hi: 64 rows x 144B
#define SM_XLO  84992
#define SM_STG  94208      // staging f32: 64c x 68px
#define SM_H    111616     // h hi (64px x 528B) + h lo; union epi f32 256x272B
#define SM_TOT  181248
#define WPITCH  144
#define HPITCH  528

__global__ __launch_bounds__(256, 1) void k_transform_mma(const float* __restrict__ feat,
                                                          const float* __restrict__ t2b,
                                                          float* __restrict__ out) {
    extern __shared__ char sm[];
    float* b1s = (float*)(sm + SM_B1);
    float* b2s = (float*)(sm + SM_B2);
    float* stg = (float*)(sm + SM_STG);
    int tid = threadIdx.x;
    int wid = tid >> 5, lane = tid & 31;
    int g = lane >> 2, c4 = lane & 3;
    int ow = (wid >> 1) * 64;      // warp o-offset
    int pxw = (wid & 1) * 32;      // warp px-offset
    int n = blockIdx.y;
    int p0 = blockIdx.x * 64;

    b1s[tid] = g_bias1[n * CC + tid];
    b2s[tid] = t2b[tid];

    float d[4][4][4];
#pragma unroll
    for (int mt = 0; mt < 4; mt++)
#pragma unroll
        for (int nt = 0; nt < 4; nt++)
#pragma unroll
            for (int e = 0; e < 4; e++) d[mt][nt][e] = 0.f;

    // ================= stage 1: D1 = W1 @ X =================
#pragma unroll 1
    for (int kc = 0; kc < 4; kc++) {
        int k0 = kc * 64;
        __syncthreads();
        // load feature chunk [64c][64px] f32 coalesced (float4)
        for (int i = tid; i < 1024; i += 256) {
            int c = i >> 4, p4 = (i & 15) << 2;
            float4 v = *(const float4*)(feat + (size_t)(n * CC + k0 + c) * LL + p0 + p4);
            *(float4*)(stg + c * 68 + p4) = v;
        }
        // load W1 chunk [256o][64c] hi/lo (uint4)
        for (int i = tid; i < 2048; i += 256) {
            int row = i >> 3, j = i & 7;
            *(uint4*)(sm + SM_WHI + row * WPITCH + j * 16) =
                ((const uint4*)g_w1hi)[row * 32 + (k0 >> 3) + j];
            *(uint4*)(sm + SM_WLO + row * WPITCH + j * 16) =
                ((const uint4*)g_w1lo)[row * 32 + (k0 >> 3) + j];
        }
        __syncthreads();
        // transpose + split X -> [px][c] bf16 hi/lo
        {
            int px = tid & 63, q = tid >> 6;
#pragma unroll
            for (int jj = 0; jj < 8; jj++) {
                float x0 = stg[(q * 16 + 2 * jj) * 68 + px];
                float x1 = stg[(q * 16 + 2 * jj + 1) * 68 + px];
                __nv_bfloat16 h0 = __float2bfloat16_rn(x0), h1 = __float2bfloat16_rn(x1);
                __nv_bfloat16 l0 = __float2bfloat16_rn(x0 - __bfloat162float(h0));
                __nv_bfloat16 l1 = __float2bfloat16_rn(x1 - __bfloat162float(h1));
                *(uint32_t*)(sm + SM_XHI + px * WPITCH + q * 32 + jj * 4) = pk2(h0, h1);
                *(uint32_t*)(sm + SM_XLO + px * WPITCH + q * 32 + jj * 4) = pk2(l0, l1);
            }
        }
        __syncthreads();
        // mma over 4 k16 steps
#pragma unroll
        for (int kk = 0; kk < 4; kk++) {
            int kb = kk * 32 + c4 * 4;
            uint32_t bh[4][2], bl[4][2];
#pragma unroll
            for (int nt = 0; nt < 4; nt++) {
                int prow = pxw + nt * 8 + g;
                bh[nt][0] = *(const uint32_t*)(sm + SM_XHI + prow * WPITCH + kb);
                bh[nt][1] = *(const uint32_t*)(sm + SM_XHI + prow * WPITCH + kb + 16);
                bl[nt][0] = *(const uint32_t*)(sm + SM_XLO + prow * WPITCH + kb);
                bl[nt][1] = *(const uint32_t*)(sm + SM_XLO + prow * WPITCH + kb + 16);
            }
#pragma unroll
            for (int mt = 0; mt < 4; mt++) {
                int orow = ow + mt * 16 + g;
                const char* wh = sm + SM_WHI + orow * WPITCH + kb;
                const char* wl = sm + SM_WLO + orow * WPITCH + kb;
                uint32_t ah0 = *(const uint32_t*)(wh);
                uint32_t ah1 = *(const uint32_t*)(wh + 8 * WPITCH);
                uint32_t ah2 = *(const uint32_t*)(wh + 16);
                uint32_t ah3 = *(const uint32_t*)(wh + 8 * WPITCH + 16);
                uint32_t al0 = *(const uint32_t*)(wl);
                uint32_t al1 = *(const uint32_t*)(wl + 8 * WPITCH);
                uint32_t al2 = *(const uint32_t*)(wl + 16);
                uint32_t al3 = *(const uint32_t*)(wl + 8 * WPITCH + 16);
#pragma unroll
                for (int nt = 0; nt < 4; nt++) {
                    mma16816(d[mt][nt], ah0, ah1, ah2, ah3, bh[nt][0], bh[nt][1]);
                    mma16816(d[mt][nt], ah0, ah1, ah2, ah3, bl[nt][0], bl[nt][1]);
                    mma16816(d[mt][nt], al0, al1, al2, al3, bh[nt][0], bh[nt][1]);
                }
            }
        }
    }
    __syncthreads();
    // h = relu(D1 + bias1) -> smem [px][o] bf16 hi/lo
    {
        __nv_bfloat16* hh = (__nv_bfloat16*)(sm + SM_H);
        __nv_bfloat16* hl = (__nv_bfloat16*)(sm + SM_H + 64 * HPITCH);
#pragma unroll
        for (int mt = 0; mt < 4; mt++) {
#pragma unroll
            for (int nt = 0; nt < 4; nt++) {
                int oa = ow + mt * 16 + g, ob = oa + 8;
                int pa = pxw + nt * 8 + 2 * c4, pb = pa + 1;
                float v0 = fmaxf(d[mt][nt][0] + b1s[oa], 0.f);
                float v1 = fmaxf(d[mt][nt][1] + b1s[oa], 0.f);
                float v2 = fmaxf(d[mt][nt][2] + b1s[ob], 0.f);
                float v3 = fmaxf(d[mt][nt][3] + b1s[ob], 0.f);
                __nv_bfloat16 h0 = __float2bfloat16_rn(v0);
                __nv_bfloat16 h1 = __float2bfloat16_rn(v1);
                __nv_bfloat16 h2 = __float2bfloat16_rn(v2);
                __nv_bfloat16 h3 = __float2bfloat16_rn(v3);
                hh[pa * (HPITCH / 2) + oa] = h0;
                hh[pb * (HPITCH / 2) + oa] = h1;
                hh[pa * (HPITCH / 2) + ob] = h2;
                hh[pb * (HPITCH / 2) + ob] = h3;
                hl[pa * (HPITCH / 2) + oa] = __float2bfloat16_rn(v0 - __bfloat162float(h0));
                hl[pb * (HPITCH / 2) + oa] = __float2bfloat16_rn(v1 - __bfloat162float(h1));
                hl[pa * (HPITCH / 2) + ob] = __float2bfloat16_rn(v2 - __bfloat162float(h2));
                hl[pb * (HPITCH / 2) + ob] = __float2bfloat16_rn(v3 - __bfloat162float(h3));
                d[mt][nt][0] = 0.f; d[mt][nt][1] = 0.f;
                d[mt][nt][2] = 0.f; d[mt][nt][3] = 0.f;
            }
        }
    }

    // ================= stage 2: D2 = W2 @ h =================
#pragma unroll 1
    for (int kc = 0; kc < 4; kc++) {
        int k0 = kc * 64;
        __syncthreads();
        for (int i = tid; i < 2048; i += 256) {
            int row = i >> 3, j = i & 7;
            *(uint4*)(sm + SM_WHI + row * WPITCH + j * 16) =
                ((const uint4*)g_w2hi)[row * 32 + (k0 >> 3) + j];
            *(uint4*)(sm + SM_WLO + row * WPITCH + j * 16) =
                ((const uint4*)g_w2lo)[row * 32 + (k0 >> 3) + j];
        }
        __syncthreads();
#pragma unroll
        for (int kk = 0; kk < 4; kk++) {
            int kb = k0 * 2 + kk * 32 + c4 * 4;   // byte offset within h row
            uint32_t bh[4][2], bl[4][2];
#pragma unroll
            for (int nt = 0; nt < 4; nt++) {
                int prow = pxw + nt * 8 + g;
                bh[nt][0] = *(const uint32_t*)(sm + SM_H + prow * HPITCH + kb);
                bh[nt][1] = *(const uint32_t*)(sm + SM_H + prow * HPITCH + kb + 16);
                bl[nt][0] = *(const uint32_t*)(sm + SM_H + 64 * HPITCH + prow * HPITCH + kb);
                bl[nt][1] = *(const uint32_t*)(sm + SM_H + 64 * HPITCH + prow * HPITCH + kb + 16);
            }
            int kbw = kk * 32 + c4 * 4;
#pragma unroll
            for (int mt = 0; mt < 4; mt++) {
                int orow = ow + mt * 16 + g;
                const char* wh = sm + SM_WHI + orow * WPITCH + kbw;
                const char* wl = sm + SM_WLO + orow * WPITCH + kbw;
                uint32_t ah0 = *(const uint32_t*)(wh);
                uint32_t ah1 = *(const uint32_t*)(wh + 8 * WPITCH);
                uint32_t ah2 = *(const uint32_t*)(wh + 16);
                uint32_t ah3 = *(const uint32_t*)(wh + 8 * WPITCH + 16);
                uint32_t al0 = *(const uint32_t*)(wl);
                uint32_t al1 = *(const uint32_t*)(wl + 8 * WPITCH);
                uint32_t al2 = *(const uint32_t*)(wl + 16);
                uint32_t al3 = *(const uint32_t*)(wl + 8 * WPITCH + 16);
#pragma unroll
                for (int nt = 0; nt < 4; nt++) {
                    mma16816(d[mt][nt], ah0, ah1, ah2, ah3, bh[nt][0], bh[nt][1]);
                    mma16816(d[mt][nt], ah0, ah1, ah2, ah3, bl[nt][0], bl[nt][1]);
                    mma16816(d[mt][nt], al0, al1, al2, al3, bh[nt][0], bh[nt][1]);
                }
            }
        }
    }
    __syncthreads();   // all mma done reading h before epi overwrites it
    // epilogue: relu(D2 + t2b) -> staging [o][px] f32 -> coalesced out
    {
        float* epi = (float*)(sm + SM_H);
#pragma unroll
        for (int mt = 0; mt < 4; mt++) {
#pragma unroll
            for (int nt = 0; nt < 4; nt++) {
                int oa = ow + mt * 16 + g, ob = oa + 8;
                int pa = pxw + nt * 8 + 2 * c4, pb = pa + 1;
                epi[oa * 68 + pa] = fmaxf(d[mt][nt][0] + b2s[oa], 0.f);
                epi[oa * 68 + pb] = fmaxf(d[mt][nt][1] + b2s[oa], 0.f);
                epi[ob * 68 + pa] = fmaxf(d[mt][nt][2] + b2s[ob], 0.f);
                epi[ob * 68 + pb] = fmaxf(d[mt][nt][3] + b2s[ob], 0.f);
            }
        }
        __syncthreads();
        for (int i = tid; i < 16384; i += 256) {
            int o = i >> 6, px = i & 63;
            out[(size_t)(n * CC + o) * LL + p0 + px] = epi[o * 68 + px];
        }
    }
}

// ---------------- launch ----------------
extern "C" void kernel_launch(void* const* d_in, const int* in_sizes, int n_in,
                              void* d_out, int out_size) {
    (void)in_sizes; (void)n_in; (void)out_size;
    const float* feature   = (const float*)d_in[0];
    const float* conv_up_w = (const float*)d_in[1];
    const float* conv_up_b = (const float*)d_in[2];
    const float* centroids = (const float*)d_in[3];
    const float* upfc_w    = (const float*)d_in[4];
    const float* upfc_b    = (const float*)d_in[5];
    const float* t1_w      = (const float*)d_in[6];
    const float* t1_b      = (const float*)d_in[7];
    const float* t2_w      = (const float*)d_in[8];
    const float* t2_b      = (const float*)d_in[9];
    float* out = (float*)d_out;

    cudaFuncSetAttribute(k_transform_mma, cudaFuncAttributeMaxDynamicSharedMemorySize, SM_TOT);

    k_l2norm<<<dim3(16, 16), 256>>>(feature);
    k_conv_softmax<<<dim3(4, 4, 16), 128>>>(conv_up_w, conv_up_b);
    k_ssum<<<NN * KK, 256>>>();
    k_up0<<<dim3(4, 16, SPL), 256>>>();
    k_up0red<<<NN * KK * CC / 256, 256>>>();
    k_upfc<<<NN, 256>>>(centroids, upfc_w, upfc_b, t1_w, t1_b);
    k_wsplit<<<256, 256>>>(t1_w, t2_w);
    k_transform_mma<<<dim3(64, 16), 256, SM_TOT>>>(feature, t2_b, out);
}

// round 5
// speedup vs baseline: 1.9899x; 1.3805x over previous
#include <cuda_runtime.h>
#include <cuda_bf16.h>
#include <cstdint>
#include <math.h>

#define NN 16
#define CC 256
#define HH 64
#define WW 64
#define LL 4096
#define KK 32
#define EPSV 1e-12f
#define SPL 16   // L-splits for k_up0
#define JS  32   // j-splits for FC

// ---------------- scratch (device globals; no allocation) ----------------
__device__ float g_xn[NN * CC * LL];          // 64 MB: l2-normalized feature
__device__ float g_sa[NN * KK * LL];          // 8 MB : softmax assignment
__device__ float g_cvp[2 * NN * KK * LL];     // 16 MB: conv logit partials (2 c-splits)
__device__ float g_ssum[NN * KK];             // sum_l sa
__device__ float g_up0p[SPL * NN * KK * CC];  // 8 MB : einsum partials per L-split
__device__ float g_up0[NN * KK * CC];         // reduced einsum result
__device__ float g_upn[NN * KK * CC];         // fully normalized up (per-n 8192 vec)
__device__ float g_fcp[JS * NN * CC];         // FC partials
__device__ float g_ufc[NN * CC];              // FC result
__device__ float g_bias1[NN * CC];            // effective t1 bias per (n, outc)
__device__ __nv_bfloat16 g_w1hi[CC * CC];     // t1_w (first 256 in-chans) split
__device__ __nv_bfloat16 g_w1lo[CC * CC];
__device__ __nv_bfloat16 g_w2hi[CC * CC];     // t2_w split
__device__ __nv_bfloat16 g_w2lo[CC * CC];

static __device__ __forceinline__ uint32_t pk2(__nv_bfloat16 a, __nv_bfloat16 b) {
    return (uint32_t)__bfloat16_as_ushort(a) | ((uint32_t)__bfloat16_as_ushort(b) << 16);
}
// bf16 mma m16n8k16, fp32 accum (sm_80+, valid on baseline sm_103)
static __device__ __forceinline__ void mma16816(float* d,
                                                uint32_t a0, uint32_t a1, uint32_t a2, uint32_t a3,
                                                uint32_t b0, uint32_t b1) {
    asm volatile("mma.sync.aligned.m16n8k16.row.col.f32.bf16.bf16.f32 "
                 "{%0,%1,%2,%3}, {%4,%5,%6,%7}, {%8,%9}, {%0,%1,%2,%3};"
                 : "+f"(d[0]), "+f"(d[1]), "+f"(d[2]), "+f"(d[3])
                 : "r"(a0), "r"(a1), "r"(a2), "r"(a3), "r"(b0), "r"(b1));
}

// ---------------- kernel 1: per-pixel L2 norm over C ----------------
__global__ __launch_bounds__(256) void k_l2norm(const float* __restrict__ f) {
    int n = blockIdx.y;
    int l = blockIdx.x * 256 + threadIdx.x;
    size_t base = (size_t)n * CC * LL + l;
    float s = 0.f;
#pragma unroll 8
    for (int c = 0; c < CC; c++) {
        float v = f[base + (size_t)c * LL];
        s += v * v;
    }
    float inv = 1.f / fmaxf(sqrtf(s), EPSV);
#pragma unroll 8
    for (int c = 0; c < CC; c++)
        g_xn[base + (size_t)c * LL] = f[base + (size_t)c * LL] * inv;
}

// ---------------- kernel 2a: 3x3 conv partial (128 channels per split) ----------------
__global__ __launch_bounds__(128) void k_conv(const float* __restrict__ w) {
    __shared__ float xs[8][18][20];
    __shared__ float ws[8][9][32];
    int z = blockIdx.z;
    int n = z >> 1, cs = z & 1;
    int cbase = cs * 128;
    int ty0 = blockIdx.y * 16, tx0 = blockIdx.x * 16;
    int tid = threadIdx.x;
    int lx = tid & 15, ly = tid >> 4;

    float acc0[32], acc1[32];
#pragma unroll
    for (int k = 0; k < 32; k++) { acc0[k] = 0.f; acc1[k] = 0.f; }

    for (int cc0 = 0; cc0 < 128; cc0 += 8) {
        int c0 = cbase + cc0;
        __syncthreads();
        for (int i = tid; i < 8 * 18 * 18; i += 128) {
            int cc = i / 324; int rem = i - cc * 324;
            int yy = rem / 18; int xx = rem - yy * 18;
            int gy = ty0 + yy - 1, gx = tx0 + xx - 1;
            float v = 0.f;
            if ((unsigned)gy < 64u && (unsigned)gx < 64u)
                v = g_xn[(n * CC + c0 + cc) * LL + gy * 64 + gx];
            xs[cc][yy][xx] = v;
        }
        for (int i = tid; i < 8 * 9 * 32; i += 128) {
            int k = i & 31; int rs = (i >> 5) % 9; int cc = i / 288;
            ws[cc][rs][k] = w[(k * CC + c0 + cc) * 9 + rs];
        }
        __syncthreads();
#pragma unroll 2
        for (int cc = 0; cc < 8; cc++) {
#pragma unroll
            for (int r = 0; r < 3; r++) {
#pragma unroll
                for (int s = 0; s < 3; s++) {
                    float x0 = xs[cc][ly + r][lx + s];
                    float x1 = xs[cc][ly + 8 + r][lx + s];
                    const float4* wp = (const float4*)&ws[cc][r * 3 + s][0];
#pragma unroll
                    for (int k4 = 0; k4 < 8; k4++) {
                        float4 wv = wp[k4];
                        acc0[k4 * 4 + 0] += wv.x * x0; acc0[k4 * 4 + 1] += wv.y * x0;
                        acc0[k4 * 4 + 2] += wv.z * x0; acc0[k4 * 4 + 3] += wv.w * x0;
                        acc1[k4 * 4 + 0] += wv.x * x1; acc1[k4 * 4 + 1] += wv.y * x1;
                        acc1[k4 * 4 + 2] += wv.z * x1; acc1[k4 * 4 + 3] += wv.w * x1;
                    }
                }
            }
        }
    }
    int px = tx0 + lx;
    size_t base = ((size_t)(cs * NN + n) * KK) * LL;
#pragma unroll
    for (int k = 0; k < 32; k++)
        g_cvp[base + (size_t)k * LL + (ty0 + ly) * 64 + px] = acc0[k];
#pragma unroll
    for (int k = 0; k < 32; k++)
        g_cvp[base + (size_t)k * LL + (ty0 + ly + 8) * 64 + px] = acc1[k];
}

// ---------------- kernel 2b: reduce partials + bias + softmax over K ----------------
__global__ __launch_bounds__(256) void k_softmax(const float* __restrict__ bias) {
    int n = blockIdx.y;
    int l = blockIdx.x * 256 + threadIdx.x;
    float v[32];
    float m = -1e30f;
#pragma unroll
    for (int k = 0; k < 32; k++) {
        float a = g_cvp[((size_t)(n * KK + k)) * LL + l]
                + g_cvp[((size_t)((NN + n) * KK + k)) * LL + l] + bias[k];
        v[k] = a;
        m = fmaxf(m, a);
    }
    float s = 0.f;
#pragma unroll
    for (int k = 0; k < 32; k++) { v[k] = __expf(v[k] - m); s += v[k]; }
    float inv = 1.f / s;
#pragma unroll
    for (int k = 0; k < 32; k++)
        g_sa[(size_t)(n * KK + k) * LL + l] = v[k] * inv;
}

// ---------------- kernel 3: ssum ----------------
__global__ __launch_bounds__(256) void k_ssum() {
    int bk = blockIdx.x;
    float s = 0.f;
    for (int i = threadIdx.x; i < LL; i += 256) s += g_sa[bk * LL + i];
    __shared__ float red[8];
    for (int off = 16; off; off >>= 1) s += __shfl_xor_sync(0xffffffffu, s, off);
    int lane = threadIdx.x & 31, wp = threadIdx.x >> 5;
    if (!lane) red[wp] = s;
    __syncthreads();
    if (threadIdx.x == 0) {
        float t = 0.f;
        for (int i = 0; i < 8; i++) t += red[i];
        g_ssum[bk] = t;
    }
}

// ---------------- kernel 4: einsum partials ----------------
__global__ __launch_bounds__(256) void k_up0() {
    int n = blockIdx.y;
    int c0 = blockIdx.x * 64;
    int sp = blockIdx.z;
    int lbase = sp * (LL / SPL);
    __shared__ float sas[64][33];
    __shared__ float xns[64][65];
    int tid = threadIdx.x;
    int kt = tid >> 4, ct = tid & 15;
    float acc[2][4] = {{0.f, 0.f, 0.f, 0.f}, {0.f, 0.f, 0.f, 0.f}};
    for (int l0 = lbase; l0 < lbase + (LL / SPL); l0 += 64) {
        __syncthreads();
        for (int i = tid; i < 2048; i += 256) {
            int k = i >> 6, l = i & 63;
            sas[l][k] = g_sa[(n * KK + k) * LL + l0 + l];
        }
        for (int i = tid; i < 4096; i += 256) {
            int c = i >> 6, l = i & 63;
            xns[l][c] = g_xn[(n * CC + c0 + c) * LL + l0 + l];
        }
        __syncthreads();
#pragma unroll 4
        for (int l = 0; l < 64; l++) {
            float a0 = sas[l][kt], a1 = sas[l][kt + 16];
#pragma unroll
            for (int j = 0; j < 4; j++) {
                float bv = xns[l][ct + 16 * j];
                acc[0][j] += a0 * bv;
                acc[1][j] += a1 * bv;
            }
        }
    }
#pragma unroll
    for (int i = 0; i < 2; i++)
#pragma unroll
        for (int j = 0; j < 4; j++)
            g_up0p[((size_t)sp * NN + n) * (KK * CC) + (kt + 16 * i) * CC + c0 + ct + 16 * j]
                = acc[i][j];
}

__global__ __launch_bounds__(256) void k_up0red() {
    int i = blockIdx.x * 256 + threadIdx.x;
    float s = 0.f;
#pragma unroll
    for (int sp = 0; sp < SPL; sp++)
        s += g_up0p[(size_t)sp * (NN * KK * CC) + i];
    g_up0[i] = s;
}

// ---------------- kernel 5a: centroid-sub + row norm + global norm -> g_upn ----------------
__global__ __launch_bounds__(256) void k_upnorm(const float* __restrict__ cent) {
    int n = blockIdx.x;
    int tid = threadIdx.x;
    int lane = tid & 31, wp = tid >> 5;
    __shared__ float upn[KK * CC];
    __shared__ float red[8];
    __shared__ float gtot;

    for (int k = wp; k < KK; k += 8) {
        float sk = g_ssum[n * KK + k];
        float vals[8];
        float sq = 0.f;
#pragma unroll
        for (int j = 0; j < 8; j++) {
            int c = lane + 32 * j;
            float u = g_up0[(n * KK + k) * CC + c] - sk * cent[k * CC + c];
            vals[j] = u;
            sq += u * u;
        }
        for (int off = 16; off; off >>= 1) sq += __shfl_xor_sync(0xffffffffu, sq, off);
        float inv = 1.f / fmaxf(sqrtf(sq), EPSV);
#pragma unroll
        for (int j = 0; j < 8; j++) upn[k * CC + lane + 32 * j] = vals[j] * inv;
    }
    __syncthreads();
    float gs = 0.f;
#pragma unroll 4
    for (int j = 0; j < 32; j++) {
        float v = upn[j * 256 + tid];
        gs += v * v;
    }
    for (int off = 16; off; off >>= 1) gs += __shfl_xor_sync(0xffffffffu, gs, off);
    if (!lane) red[wp] = gs;
    __syncthreads();
    if (tid == 0) {
        float t = 0.f;
        for (int i = 0; i < 8; i++) t += red[i];
        gtot = 1.f / fmaxf(sqrtf(t), EPSV);
    }
    __syncthreads();
    float ginv = gtot;
#pragma unroll 4
    for (int j = 0; j < 32; j++)
        g_upn[n * (KK * CC) + j * 256 + tid] = upn[j * 256 + tid] * ginv;
}

// ---------------- kernel 5b: FC partials — wfc tile read ONCE for all 16 n ----------------
// grid (16 o-tiles of 16, 32 j-splits of 256); block 256 = 16 o x 16 n.
#define FCP 264   // row pitch (floats), 16B aligned
__global__ __launch_bounds__(256) void k_fc(const float* __restrict__ wfc) {
    __shared__ float ws[16][FCP];
    __shared__ float us[16][FCP];
    int ot = blockIdx.x * 16;
    int j0 = blockIdx.y * 256;
    int tid = threadIdx.x;
    for (int i = tid; i < 16 * 64; i += 256) {
        int row = i >> 6, j4 = (i & 63) << 2;
        *(float4*)&ws[row][j4] = *(const float4*)(wfc + (size_t)(ot + row) * (KK * CC) + j0 + j4);
        *(float4*)&us[row][j4] = *(const float4*)(g_upn + (size_t)row * (KK * CC) + j0 + j4);
    }
    __syncthreads();
    int o = tid & 15, n = tid >> 4;
    float s = 0.f;
#pragma unroll 8
    for (int jj = 0; jj < 64; jj++) {
        float4 a = *(const float4*)&ws[o][jj * 4];
        float4 b = *(const float4*)&us[n][jj * 4];
        s += a.x * b.x + a.y * b.y + a.z * b.z + a.w * b.w;
    }
    g_fcp[(size_t)(blockIdx.y * NN + n) * CC + ot + o] = s;
}

// ---------------- kernel 5c: reduce FC partials + bias ----------------
__global__ __launch_bounds__(256) void k_fcred(const float* __restrict__ bfc) {
    int n = blockIdx.x, o = threadIdx.x;
    float s = 0.f;
#pragma unroll
    for (int js = 0; js < JS; js++)
        s += g_fcp[(size_t)(js * NN + n) * CC + o];
    g_ufc[n * CC + o] = s + bfc[o];
}

// ---------------- kernel 5d: effective t1 bias ----------------
// grid (8 o-tiles of 32, 16 n); thread = (o_local 32) x (c-group 8)
__global__ __launch_bounds__(256) void k_bias1(const float* __restrict__ t1w,
                                               const float* __restrict__ t1b) {
    int n = blockIdx.y;
    int o = blockIdx.x * 32 + (threadIdx.x >> 3);
    int grp = threadIdx.x & 7;
    float s = 0.f;
#pragma unroll
    for (int q = 0; q < 8; q++) {
        int c = grp * 32 + q * 4;
        float4 wv = *(const float4*)(t1w + (size_t)o * 512 + 256 + c);
        float4 uv = *(const float4*)(g_ufc + n * CC + c);
        s += wv.x * uv.x + wv.y * uv.y + wv.z * uv.z + wv.w * uv.w;
    }
#pragma unroll
    for (int off = 4; off; off >>= 1)
        s += __shfl_down_sync(0xffffffffu, s, off, 8);
    if (grp == 0) g_bias1[n * CC + o] = t1b[o] + s;
}

// ---------------- prep: split t1/t2 weights to bf16 hi/lo ----------------
__global__ __launch_bounds__(256) void k_wsplit(const float* __restrict__ t1w,
                                                const float* __restrict__ t2w) {
    int i = blockIdx.x * 256 + threadIdx.x;   // 65536
    int o = i >> 8, c = i & 255;
    {
        float x = t1w[(size_t)o * 512 + c];
        __nv_bfloat16 h = __float2bfloat16_rn(x);
        g_w1hi[i] = h;
        g_w1lo[i] = __float2bfloat16_rn(x - __bfloat162float(h));
    }
    {
        float x = t2w[i];
        __nv_bfloat16 h = __float2bfloat16_rn(x);
        g_w2hi[i] = h;
        g_w2lo[i] = __float2bfloat16_rn(x - __bfloat162float(h));
    }
}

// ---------------- kernel 6: mma.sync fused transform ----------------
#define SM_B1   0
#define SM_B2   1024
#define SM_WHI  2048
#define SM_WLO  38912
#define SM_XHI  75776
#define SM_XLO  84992
#define SM_STG  94208
#define SM_H    111616
#define SM_TOT  181248
#define WPITCH  144
#define HPITCH  528

__global__ __launch_bounds__(256, 1) void k_transform_mma(const float* __restrict__ feat,
                                                          const float* __restrict__ t2b,
                                                          float* __restrict__ out) {
    extern __shared__ char sm[];
    float* b1s = (float*)(sm + SM_B1);
    float* b2s = (float*)(sm + SM_B2);
    float* stg = (float*)(sm + SM_STG);
    int tid = threadIdx.x;
    int wid = tid >> 5, lane = tid & 31;
    int g = lane >> 2, c4 = lane & 3;
    int ow = (wid >> 1) * 64;
    int pxw = (wid & 1) * 32;
    int n = blockIdx.y;
    int p0 = blockIdx.x * 64;

    b1s[tid] = g_bias1[n * CC + tid];
    b2s[tid] = t2b[tid];

    float d[4][4][4];
#pragma unroll
    for (int mt = 0; mt < 4; mt++)
#pragma unroll
        for (int nt = 0; nt < 4; nt++)
#pragma unroll
            for (int e = 0; e < 4; e++) d[mt][nt][e] = 0.f;

#pragma unroll 1
    for (int kc = 0; kc < 4; kc++) {
        int k0 = kc * 64;
        __syncthreads();
        for (int i = tid; i < 1024; i += 256) {
            int c = i >> 4, p4 = (i & 15) << 2;
            float4 v = *(const float4*)(feat + (size_t)(n * CC + k0 + c) * LL + p0 + p4);
            *(float4*)(stg + c * 68 + p4) = v;
        }
        for (int i = tid; i < 2048; i += 256) {
            int row = i >> 3, j = i & 7;
            *(uint4*)(sm + SM_WHI + row * WPITCH + j * 16) =
                ((const uint4*)g_w1hi)[row * 32 + (k0 >> 3) + j];
            *(uint4*)(sm + SM_WLO + row * WPITCH + j * 16) =
                ((const uint4*)g_w1lo)[row * 32 + (k0 >> 3) + j];
        }
        __syncthreads();
        {
            int px = tid & 63, q = tid >> 6;
#pragma unroll
            for (int jj = 0; jj < 8; jj++) {
                float x0 = stg[(q * 16 + 2 * jj) * 68 + px];
                float x1 = stg[(q * 16 + 2 * jj + 1) * 68 + px];
                __nv_bfloat16 h0 = __float2bfloat16_rn(x0), h1 = __float2bfloat16_rn(x1);
                __nv_bfloat16 l0 = __float2bfloat16_rn(x0 - __bfloat162float(h0));
                __nv_bfloat16 l1 = __float2bfloat16_rn(x1 - __bfloat162float(h1));
                *(uint32_t*)(sm + SM_XHI + px * WPITCH + q * 32 + jj * 4) = pk2(h0, h1);
                *(uint32_t*)(sm + SM_XLO + px * WPITCH + q * 32 + jj * 4) = pk2(l0, l1);
            }
        }
        __syncthreads();
#pragma unroll
        for (int kk = 0; kk < 4; kk++) {
            int kb = kk * 32 + c4 * 4;
            uint32_t bh[4][2], bl[4][2];
#pragma unroll
            for (int nt = 0; nt < 4; nt++) {
                int prow = pxw + nt * 8 + g;
                bh[nt][0] = *(const uint32_t*)(sm + SM_XHI + prow * WPITCH + kb);
                bh[nt][1] = *(const uint32_t*)(sm + SM_XHI + prow * WPITCH + kb + 16);
                bl[nt][0] = *(const uint32_t*)(sm + SM_XLO + prow * WPITCH + kb);
                bl[nt][1] = *(const uint32_t*)(sm + SM_XLO + prow * WPITCH + kb + 16);
            }
#pragma unroll
            for (int mt = 0; mt < 4; mt++) {
                int orow = ow + mt * 16 + g;
                const char* wh = sm + SM_WHI + orow * WPITCH + kb;
                const char* wl = sm + SM_WLO + orow * WPITCH + kb;
                uint32_t ah0 = *(const uint32_t*)(wh);
                uint32_t ah1 = *(const uint32_t*)(wh + 8 * WPITCH);
                uint32_t ah2 = *(const uint32_t*)(wh + 16);
                uint32_t ah3 = *(const uint32_t*)(wh + 8 * WPITCH + 16);
                uint32_t al0 = *(const uint32_t*)(wl);
                uint32_t al1 = *(const uint32_t*)(wl + 8 * WPITCH);
                uint32_t al2 = *(const uint32_t*)(wl + 16);
                uint32_t al3 = *(const uint32_t*)(wl + 8 * WPITCH + 16);
#pragma unroll
                for (int nt = 0; nt < 4; nt++) {
                    mma16816(d[mt][nt], ah0, ah1, ah2, ah3, bh[nt][0], bh[nt][1]);
                    mma16816(d[mt][nt], ah0, ah1, ah2, ah3, bl[nt][0], bl[nt][1]);
                    mma16816(d[mt][nt], al0, al1, al2, al3, bh[nt][0], bh[nt][1]);
                }
            }
        }
    }
    __syncthreads();
    {
        __nv_bfloat16* hh = (__nv_bfloat16*)(sm + SM_H);
        __nv_bfloat16* hl = (__nv_bfloat16*)(sm + SM_H + 64 * HPITCH);
#pragma unroll
        for (int mt = 0; mt < 4; mt++) {
#pragma unroll
            for (int nt = 0; nt < 4; nt++) {
                int oa = ow + mt * 16 + g, ob = oa + 8;
                int pa = pxw + nt * 8 + 2 * c4, pb = pa + 1;
                float v0 = fmaxf(d[mt][nt][0] + b1s[oa], 0.f);
                float v1 = fmaxf(d[mt][nt][1] + b1s[oa], 0.f);
                float v2 = fmaxf(d[mt][nt][2] + b1s[ob], 0.f);
                float v3 = fmaxf(d[mt][nt][3] + b1s[ob], 0.f);
                __nv_bfloat16 h0 = __float2bfloat16_rn(v0);
                __nv_bfloat16 h1 = __float2bfloat16_rn(v1);
                __nv_bfloat16 h2 = __float2bfloat16_rn(v2);
                __nv_bfloat16 h3 = __float2bfloat16_rn(v3);
                hh[pa * (HPITCH / 2) + oa] = h0;
                hh[pb * (HPITCH / 2) + oa] = h1;
                hh[pa * (HPITCH / 2) + ob] = h2;
                hh[pb * (HPITCH / 2) + ob] = h3;
                hl[pa * (HPITCH / 2) + oa] = __float2bfloat16_rn(v0 - __bfloat162float(h0));
                hl[pb * (HPITCH / 2) + oa] = __float2bfloat16_rn(v1 - __bfloat162float(h1));
                hl[pa * (HPITCH / 2) + ob] = __float2bfloat16_rn(v2 - __bfloat162float(h2));
                hl[pb * (HPITCH / 2) + ob] = __float2bfloat16_rn(v3 - __bfloat162float(h3));
                d[mt][nt][0] = 0.f; d[mt][nt][1] = 0.f;
                d[mt][nt][2] = 0.f; d[mt][nt][3] = 0.f;
            }
        }
    }

#pragma unroll 1
    for (int kc = 0; kc < 4; kc++) {
        int k0 = kc * 64;
        __syncthreads();
        for (int i = tid; i < 2048; i += 256) {
            int row = i >> 3, j = i & 7;
            *(uint4*)(sm + SM_WHI + row * WPITCH + j * 16) =
                ((const uint4*)g_w2hi)[row * 32 + (k0 >> 3) + j];
            *(uint4*)(sm + SM_WLO + row * WPITCH + j * 16) =
                ((const uint4*)g_w2lo)[row * 32 + (k0 >> 3) + j];
        }
        __syncthreads();
#pragma unroll
        for (int kk = 0; kk < 4; kk++) {
            int kb = k0 * 2 + kk * 32 + c4 * 4;
            uint32_t bh[4][2], bl[4][2];
#pragma unroll
            for (int nt = 0; nt < 4; nt++) {
                int prow = pxw + nt * 8 + g;
                bh[nt][0] = *(const uint32_t*)(sm + SM_H + prow * HPITCH + kb);
                bh[nt][1] = *(const uint32_t*)(sm + SM_H + prow * HPITCH + kb + 16);
                bl[nt][0] = *(const uint32_t*)(sm + SM_H + 64 * HPITCH + prow * HPITCH + kb);
                bl[nt][1] = *(const uint32_t*)(sm + SM_H + 64 * HPITCH + prow * HPITCH + kb + 16);
            }
            int kbw = kk * 32 + c4 * 4;
#pragma unroll
            for (int mt = 0; mt < 4; mt++) {
                int orow = ow + mt * 16 + g;
                const char* wh = sm + SM_WHI + orow * WPITCH + kbw;
                const char* wl = sm + SM_WLO + orow * WPITCH + kbw;
                uint32_t ah0 = *(const uint32_t*)(wh);
                uint32_t ah1 = *(const uint32_t*)(wh + 8 * WPITCH);
                uint32_t ah2 = *(const uint32_t*)(wh + 16);
                uint32_t ah3 = *(const uint32_t*)(wh + 8 * WPITCH + 16);
                uint32_t al0 = *(const uint32_t*)(wl);
                uint32_t al1 = *(const uint32_t*)(wl + 8 * WPITCH);
                uint32_t al2 = *(const uint32_t*)(wl + 16);
                uint32_t al3 = *(const uint32_t*)(wl + 8 * WPITCH + 16);
#pragma unroll
                for (int nt = 0; nt < 4; nt++) {
                    mma16816(d[mt][nt], ah0, ah1, ah2, ah3, bh[nt][0], bh[nt][1]);
                    mma16816(d[mt][nt], ah0, ah1, ah2, ah3, bl[nt][0], bl[nt][1]);
                    mma16816(d[mt][nt], al0, al1, al2, al3, bh[nt][0], bh[nt][1]);
                }
            }
        }
    }
    __syncthreads();
    {
        float* epi = (float*)(sm + SM_H);
#pragma unroll
        for (int mt = 0; mt < 4; mt++) {
#pragma unroll
            for (int nt = 0; nt < 4; nt++) {
                int oa = ow + mt * 16 + g, ob = oa + 8;
                int pa = pxw + nt * 8 + 2 * c4, pb = pa + 1;
                epi[oa * 68 + pa] = fmaxf(d[mt][nt][0] + b2s[oa], 0.f);
                epi[oa * 68 + pb] = fmaxf(d[mt][nt][1] + b2s[oa], 0.f);
                epi[ob * 68 + pa] = fmaxf(d[mt][nt][2] + b2s[ob], 0.f);
                epi[ob * 68 + pb] = fmaxf(d[mt][nt][3] + b2s[ob], 0.f);
            }
        }
        __syncthreads();
        for (int i = tid; i < 16384; i += 256) {
            int o = i >> 6, px = i & 63;
            out[(size_t)(n * CC + o) * LL + p0 + px] = epi[o * 68 + px];
        }
    }
}

// ---------------- launch ----------------
extern "C" void kernel_launch(void* const* d_in, const int* in_sizes, int n_in,
                              void* d_out, int out_size) {
    (void)in_sizes; (void)n_in; (void)out_size;
    const float* feature   = (const float*)d_in[0];
    const float* conv_up_w = (const float*)d_in[1];
    const float* conv_up_b = (const float*)d_in[2];
    const float* centroids = (const float*)d_in[3];
    const float* upfc_w    = (const float*)d_in[4];
    const float* upfc_b    = (const float*)d_in[5];
    const float* t1_w      = (const float*)d_in[6];
    const float* t1_b      = (const float*)d_in[7];
    const float* t2_w      = (const float*)d_in[8];
    const float* t2_b      = (const float*)d_in[9];
    float* out = (float*)d_out;

    cudaFuncSetAttribute(k_transform_mma, cudaFuncAttributeMaxDynamicSharedMemorySize, SM_TOT);

    k_l2norm<<<dim3(16, 16), 256>>>(feature);
    k_conv<<<dim3(4, 4, 32), 128>>>(conv_up_w);
    k_softmax<<<dim3(16, 16), 256>>>(conv_up_b);
    k_ssum<<<NN * KK, 256>>>();
    k_up0<<<dim3(4, 16, SPL), 256>>>();
    k_up0red<<<NN * KK * CC / 256, 256>>>();
    k_upnorm<<<NN, 256>>>(centroids);
    k_fc<<<dim3(16, JS), 256>>>(upfc_w);
    k_fcred<<<NN, 256>>>(upfc_b);
    k_bias1<<<dim3(8, 16), 256>>>(t1_w, t1_b);
    k_wsplit<<<256, 256>>>(t1_w, t2_w);
    k_transform_mma<<<dim3(64, 16), 256, SM_TOT>>>(feature, t2_b, out);
}

// round 6
// speedup vs baseline: 2.6743x; 1.3440x over previous
#include <cuda_runtime.h>
#include <cuda_bf16.h>
#include <cstdint>
#include <math.h>

#define NN 16
#define CC 256
#define HH 64
#define WW 64
#define LL 4096
#define KK 32
#define EPSV 1e-12f
#define SPL 16   // L-splits for k_up0
#define JS  32   // j-splits for FC

// ---------------- scratch (device globals; no allocation) ----------------
__device__ float g_xn[NN * CC * LL];          // 64 MB: l2-normalized feature (planar)
__device__ __nv_bfloat16 g_xci_hi[(size_t)NN * LL * CC];  // 32 MB: xn bf16 hi, [n][l][c]
__device__ __nv_bfloat16 g_xci_lo[(size_t)NN * LL * CC];  // 32 MB: xn bf16 lo
__device__ float g_sa[NN * KK * LL];          // 8 MB : softmax assignment
__device__ float g_ssum[NN * KK];             // sum_l sa
__device__ float g_up0p[SPL * NN * KK * CC];  // 8 MB : einsum partials per L-split
__device__ float g_up0[NN * KK * CC];         // reduced einsum result
__device__ float g_upn[NN * KK * CC];         // fully normalized up
__device__ float g_fcp[JS * NN * CC];         // FC partials
__device__ float g_ufc[NN * CC];              // FC result
__device__ float g_bias1[NN * CC];            // effective t1 bias
__device__ __nv_bfloat16 g_cwhi[9 * 16 * 32 * 16];  // conv W split: [tap][chunk][m][k]
__device__ __nv_bfloat16 g_cwlo[9 * 16 * 32 * 16];
__device__ __nv_bfloat16 g_w1hi[CC * CC];     // t1_w (first 256 in-chans) split
__device__ __nv_bfloat16 g_w1lo[CC * CC];
__device__ __nv_bfloat16 g_w2hi[CC * CC];     // t2_w split
__device__ __nv_bfloat16 g_w2lo[CC * CC];

static __device__ __forceinline__ uint32_t pk2(__nv_bfloat16 a, __nv_bfloat16 b) {
    return (uint32_t)__bfloat16_as_ushort(a) | ((uint32_t)__bfloat16_as_ushort(b) << 16);
}
// bf16 mma m16n8k16, fp32 accum (sm_80+, valid on baseline sm_103)
static __device__ __forceinline__ void mma16816(float* d,
                                                uint32_t a0, uint32_t a1, uint32_t a2, uint32_t a3,
                                                uint32_t b0, uint32_t b1) {
    asm volatile("mma.sync.aligned.m16n8k16.row.col.f32.bf16.bf16.f32 "
                 "{%0,%1,%2,%3}, {%4,%5,%6,%7}, {%8,%9}, {%0,%1,%2,%3};"
                 : "+f"(d[0]), "+f"(d[1]), "+f"(d[2]), "+f"(d[3])
                 : "r"(a0), "r"(a1), "r"(a2), "r"(a3), "r"(b0), "r"(b1));
}

// ---------------- kernel 1: per-pixel L2 norm; emit planar f32 + interleaved bf16 ----------------
__global__ __launch_bounds__(256) void k_l2norm(const float* __restrict__ f) {
    int n = blockIdx.y;
    int l = blockIdx.x * 256 + threadIdx.x;
    size_t base = (size_t)n * CC * LL + l;
    float s = 0.f;
#pragma unroll 8
    for (int c = 0; c < CC; c++) {
        float v = f[base + (size_t)c * LL];
        s += v * v;
    }
    float inv = 1.f / fmaxf(sqrtf(s), EPSV);
    size_t cib = ((size_t)n * LL + l) * CC;
    __align__(16) unsigned short hbuf[16], lbuf[16];
#pragma unroll 4
    for (int c = 0; c < CC; c++) {
        float v = f[base + (size_t)c * LL] * inv;
        g_xn[base + (size_t)c * LL] = v;
        __nv_bfloat16 h = __float2bfloat16_rn(v);
        hbuf[c & 15] = __bfloat16_as_ushort(h);
        lbuf[c & 15] = __bfloat16_as_ushort(__float2bfloat16_rn(v - __bfloat162float(h)));
        if ((c & 15) == 15) {
            *(uint4*)(g_xci_hi + cib + c - 15) = *(uint4*)hbuf;
            *(uint4*)(g_xci_hi + cib + c - 7)  = *(uint4*)(hbuf + 8);
            *(uint4*)(g_xci_lo + cib + c - 15) = *(uint4*)lbuf;
            *(uint4*)(g_xci_lo + cib + c - 7)  = *(uint4*)(lbuf + 8);
        }
    }
}

// ---------------- prep: conv weights -> [tap][chunk][m][k] bf16 hi/lo ----------------
__global__ __launch_bounds__(256) void k_wprep(const float* __restrict__ w) {
    int i = blockIdx.x * 256 + threadIdx.x;   // 73728
    int t = i >> 13;                // / 8192
    int r = i & 8191;
    int chn = r >> 9;
    int m = (r >> 4) & 31;
    int kk = r & 15;
    int c = chn * 16 + kk;
    float x = w[((size_t)m * CC + c) * 9 + t];
    __nv_bfloat16 h = __float2bfloat16_rn(x);
    g_cwhi[i] = h;
    g_cwlo[i] = __float2bfloat16_rn(x - __bfloat162float(h));
}

// ---------------- kernel 2: 3x3 conv via mma.sync + fused softmax ----------------
// CTA = (n, 16x16 px). 8 warps; warp = 32 kout x 32 px. 9 taps x 16 ch-chunks.
__global__ __launch_bounds__(256) void k_conv_mma(const float* __restrict__ bias) {
    __shared__ __align__(16) __nv_bfloat16 hHi[18 * 18 * 16];
    __shared__ __align__(16) __nv_bfloat16 hLo[18 * 18 * 16];
    __shared__ __align__(16) __nv_bfloat16 wHi[9 * 32 * 16];
    __shared__ __align__(16) __nv_bfloat16 wLo[9 * 32 * 16];
    __shared__ float bsm[32];
    int n = blockIdx.z;
    int ty0 = blockIdx.y * 16, tx0 = blockIdx.x * 16;
    int tid = threadIdx.x, wid = tid >> 5, lane = tid & 31;
    int g = lane >> 2, c4 = lane & 3;
    if (tid < 32) bsm[tid] = bias[tid];

    float d[2][4][4];
#pragma unroll
    for (int mt = 0; mt < 2; mt++)
#pragma unroll
        for (int nt = 0; nt < 4; nt++)
#pragma unroll
            for (int e = 0; e < 4; e++) d[mt][nt][e] = 0.f;

#pragma unroll 1
    for (int chk = 0; chk < 16; chk++) {
        int c0 = chk * 16;
        __syncthreads();
        // halo: 18x18 px, 16 ch interleaved -> direct 16B copies from g_xci
        for (int i = tid; i < 648; i += 256) {
            int slot = i >> 1, half = i & 1;
            int y = slot / 18, x = slot - y * 18;
            int gy = ty0 + y - 1, gx = tx0 + x - 1;
            uint4 vh = make_uint4(0, 0, 0, 0), vl = make_uint4(0, 0, 0, 0);
            if ((unsigned)gy < 64u && (unsigned)gx < 64u) {
                size_t off = ((size_t)n * LL + gy * 64 + gx) * CC + c0 + half * 8;
                vh = *(const uint4*)(g_xci_hi + off);
                vl = *(const uint4*)(g_xci_lo + off);
            }
            *(uint4*)(hHi + slot * 16 + half * 8) = vh;
            *(uint4*)(hLo + slot * 16 + half * 8) = vl;
        }
        // weights: 9 taps x [32m][16k] per chunk, contiguous in prep layout
        for (int i = tid; i < 576; i += 256) {
            int t = i >> 6, r = i & 63;
            ((uint4*)wHi)[t * 64 + r] = ((const uint4*)g_cwhi)[(t * 16 + chk) * 64 + r];
            ((uint4*)wLo)[t * 64 + r] = ((const uint4*)g_cwlo)[(t * 16 + chk) * 64 + r];
        }
        __syncthreads();
#pragma unroll
        for (int tap = 0; tap < 9; tap++) {
            int r = tap / 3, s = tap - 3 * (tap / 3);
            uint32_t bh[4][2], bl[4][2];
#pragma unroll
            for (int nt = 0; nt < 4; nt++) {
                int pxl = wid * 32 + nt * 8 + g;
                int y = (pxl >> 4) + r, x = (pxl & 15) + s;
                const __nv_bfloat16* ph = hHi + (y * 18 + x) * 16 + 2 * c4;
                const __nv_bfloat16* pl = hLo + (y * 18 + x) * 16 + 2 * c4;
                bh[nt][0] = *(const uint32_t*)ph;
                bh[nt][1] = *(const uint32_t*)(ph + 8);
                bl[nt][0] = *(const uint32_t*)pl;
                bl[nt][1] = *(const uint32_t*)(pl + 8);
            }
#pragma unroll
            for (int mt = 0; mt < 2; mt++) {
                const __nv_bfloat16* qh = wHi + (tap * 32 + mt * 16 + g) * 16 + 2 * c4;
                const __nv_bfloat16* ql = wLo + (tap * 32 + mt * 16 + g) * 16 + 2 * c4;
                uint32_t ah0 = *(const uint32_t*)qh;
                uint32_t ah1 = *(const uint32_t*)(qh + 128);
                uint32_t ah2 = *(const uint32_t*)(qh + 8);
                uint32_t ah3 = *(const uint32_t*)(qh + 136);
                uint32_t al0 = *(const uint32_t*)ql;
                uint32_t al1 = *(const uint32_t*)(ql + 128);
                uint32_t al2 = *(const uint32_t*)(ql + 8);
                uint32_t al3 = *(const uint32_t*)(ql + 136);
#pragma unroll
                for (int nt = 0; nt < 4; nt++) {
                    mma16816(d[mt][nt], ah0, ah1, ah2, ah3, bh[nt][0], bh[nt][1]);
                    mma16816(d[mt][nt], ah0, ah1, ah2, ah3, bl[nt][0], bl[nt][1]);
                    mma16816(d[mt][nt], al0, al1, al2, al3, bh[nt][0], bh[nt][1]);
                }
            }
        }
    }
    // fused softmax over kout (32), per pixel; kout spread over g-lanes
#pragma unroll
    for (int mt = 0; mt < 2; mt++)
#pragma unroll
        for (int nt = 0; nt < 4; nt++)
#pragma unroll
            for (int e = 0; e < 4; e++)
                d[mt][nt][e] += bsm[mt * 16 + g + (e >> 1) * 8];
#pragma unroll
    for (int nt = 0; nt < 4; nt++) {
#pragma unroll
        for (int e1 = 0; e1 < 2; e1++) {
            float v00 = d[0][nt][e1], v01 = d[0][nt][e1 + 2];
            float v10 = d[1][nt][e1], v11 = d[1][nt][e1 + 2];
            float m = fmaxf(fmaxf(v00, v01), fmaxf(v10, v11));
            m = fmaxf(m, __shfl_xor_sync(0xffffffffu, m, 4));
            m = fmaxf(m, __shfl_xor_sync(0xffffffffu, m, 8));
            m = fmaxf(m, __shfl_xor_sync(0xffffffffu, m, 16));
            float e00 = __expf(v00 - m), e01 = __expf(v01 - m);
            float e10 = __expf(v10 - m), e11 = __expf(v11 - m);
            float s = e00 + e01 + e10 + e11;
            s += __shfl_xor_sync(0xffffffffu, s, 4);
            s += __shfl_xor_sync(0xffffffffu, s, 8);
            s += __shfl_xor_sync(0xffffffffu, s, 16);
            float inv = 1.f / s;
            int px = wid * 32 + nt * 8 + 2 * c4 + e1;
            int gy = ty0 + (px >> 4), gx = tx0 + (px & 15);
            size_t base = ((size_t)n * KK) * LL + gy * 64 + gx;
            g_sa[base + (size_t)g * LL]        = e00 * inv;
            g_sa[base + (size_t)(g + 8) * LL]  = e01 * inv;
            g_sa[base + (size_t)(g + 16) * LL] = e10 * inv;
            g_sa[base + (size_t)(g + 24) * LL] = e11 * inv;
        }
    }
}

// ---------------- kernel 3: ssum ----------------
__global__ __launch_bounds__(256) void k_ssum() {
    int bk = blockIdx.x;
    float s = 0.f;
    for (int i = threadIdx.x; i < LL; i += 256) s += g_sa[bk * LL + i];
    __shared__ float red[8];
    for (int off = 16; off; off >>= 1) s += __shfl_xor_sync(0xffffffffu, s, off);
    int lane = threadIdx.x & 31, wp = threadIdx.x >> 5;
    if (!lane) red[wp] = s;
    __syncthreads();
    if (threadIdx.x == 0) {
        float t = 0.f;
        for (int i = 0; i < 8; i++) t += red[i];
        g_ssum[bk] = t;
    }
}

// ---------------- kernel 4: einsum partials ----------------
__global__ __launch_bounds__(256) void k_up0() {
    int n = blockIdx.y;
    int c0 = blockIdx.x * 64;
    int sp = blockIdx.z;
    int lbase = sp * (LL / SPL);
    __shared__ float sas[64][33];
    __shared__ float xns[64][65];
    int tid = threadIdx.x;
    int kt = tid >> 4, ct = tid & 15;
    float acc[2][4] = {{0.f, 0.f, 0.f, 0.f}, {0.f, 0.f, 0.f, 0.f}};
    for (int l0 = lbase; l0 < lbase + (LL / SPL); l0 += 64) {
        __syncthreads();
        for (int i = tid; i < 2048; i += 256) {
            int k = i >> 6, l = i & 63;
            sas[l][k] = g_sa[(n * KK + k) * LL + l0 + l];
        }
        for (int i = tid; i < 4096; i += 256) {
            int c = i >> 6, l = i & 63;
            xns[l][c] = g_xn[(n * CC + c0 + c) * LL + l0 + l];
        }
        __syncthreads();
#pragma unroll 4
        for (int l = 0; l < 64; l++) {
            float a0 = sas[l][kt], a1 = sas[l][kt + 16];
#pragma unroll
            for (int j = 0; j < 4; j++) {
                float bv = xns[l][ct + 16 * j];
                acc[0][j] += a0 * bv;
                acc[1][j] += a1 * bv;
            }
        }
    }
#pragma unroll
    for (int i = 0; i < 2; i++)
#pragma unroll
        for (int j = 0; j < 4; j++)
            g_up0p[((size_t)sp * NN + n) * (KK * CC) + (kt + 16 * i) * CC + c0 + ct + 16 * j]
                = acc[i][j];
}

__global__ __launch_bounds__(256) void k_up0red() {
    int i = blockIdx.x * 256 + threadIdx.x;
    float s = 0.f;
#pragma unroll
    for (int sp = 0; sp < SPL; sp++)
        s += g_up0p[(size_t)sp * (NN * KK * CC) + i];
    g_up0[i] = s;
}

// ---------------- kernel 5a: centroid-sub + row norm + global norm -> g_upn ----------------
__global__ __launch_bounds__(256) void k_upnorm(const float* __restrict__ cent) {
    int n = blockIdx.x;
    int tid = threadIdx.x;
    int lane = tid & 31, wp = tid >> 5;
    __shared__ float upn[KK * CC];
    __shared__ float red[8];
    __shared__ float gtot;

    for (int k = wp; k < KK; k += 8) {
        float sk = g_ssum[n * KK + k];
        float vals[8];
        float sq = 0.f;
#pragma unroll
        for (int j = 0; j < 8; j++) {
            int c = lane + 32 * j;
            float u = g_up0[(n * KK + k) * CC + c] - sk * cent[k * CC + c];
            vals[j] = u;
            sq += u * u;
        }
        for (int off = 16; off; off >>= 1) sq += __shfl_xor_sync(0xffffffffu, sq, off);
        float inv = 1.f / fmaxf(sqrtf(sq), EPSV);
#pragma unroll
        for (int j = 0; j < 8; j++) upn[k * CC + lane + 32 * j] = vals[j] * inv;
    }
    __syncthreads();
    float gs = 0.f;
#pragma unroll 4
    for (int j = 0; j < 32; j++) {
        float v = upn[j * 256 + tid];
        gs += v * v;
    }
    for (int off = 16; off; off >>= 1) gs += __shfl_xor_sync(0xffffffffu, gs, off);
    if (!lane) red[wp] = gs;
    __syncthreads();
    if (tid == 0) {
        float t = 0.f;
        for (int i = 0; i < 8; i++) t += red[i];
        gtot = 1.f / fmaxf(sqrtf(t), EPSV);
    }
    __syncthreads();
    float ginv = gtot;
#pragma unroll 4
    for (int j = 0; j < 32; j++)
        g_upn[n * (KK * CC) + j * 256 + tid] = upn[j * 256 + tid] * ginv;
}

// ---------------- kernel 5b: FC partials — wfc tile read ONCE for all 16 n ----------------
#define FCP 264
__global__ __launch_bounds__(256) void k_fc(const float* __restrict__ wfc) {
    __shared__ float ws[16][FCP];
    __shared__ float us[16][FCP];
    int ot = blockIdx.x * 16;
    int j0 = blockIdx.y * 256;
    int tid = threadIdx.x;
    for (int i = tid; i < 16 * 64; i += 256) {
        int row = i >> 6, j4 = (i & 63) << 2;
        *(float4*)&ws[row][j4] = *(const float4*)(wfc + (size_t)(ot + row) * (KK * CC) + j0 + j4);
        *(float4*)&us[row][j4] = *(const float4*)(g_upn + (size_t)row * (KK * CC) + j0 + j4);
    }
    __syncthreads();
    int o = tid & 15, n = tid >> 4;
    float s = 0.f;
#pragma unroll 8
    for (int jj = 0; jj < 64; jj++) {
        float4 a = *(const float4*)&ws[o][jj * 4];
        float4 b = *(const float4*)&us[n][jj * 4];
        s += a.x * b.x + a.y * b.y + a.z * b.z + a.w * b.w;
    }
    g_fcp[(size_t)(blockIdx.y * NN + n) * CC + ot + o] = s;
}

__global__ __launch_bounds__(256) void k_fcred(const float* __restrict__ bfc) {
    int n = blockIdx.x, o = threadIdx.x;
    float s = 0.f;
#pragma unroll
    for (int js = 0; js < JS; js++)
        s += g_fcp[(size_t)(js * NN + n) * CC + o];
    g_ufc[n * CC + o] = s + bfc[o];
}

__global__ __launch_bounds__(256) void k_bias1(const float* __restrict__ t1w,
                                               const float* __restrict__ t1b) {
    int n = blockIdx.y;
    int o = blockIdx.x * 32 + (threadIdx.x >> 3);
    int grp = threadIdx.x & 7;
    float s = 0.f;
#pragma unroll
    for (int q = 0; q < 8; q++) {
        int c = grp * 32 + q * 4;
        float4 wv = *(const float4*)(t1w + (size_t)o * 512 + 256 + c);
        float4 uv = *(const float4*)(g_ufc + n * CC + c);
        s += wv.x * uv.x + wv.y * uv.y + wv.z * uv.z + wv.w * uv.w;
    }
#pragma unroll
    for (int off = 4; off; off >>= 1)
        s += __shfl_down_sync(0xffffffffu, s, off, 8);
    if (grp == 0) g_bias1[n * CC + o] = t1b[o] + s;
}

// ---------------- prep: split t1/t2 weights to bf16 hi/lo ----------------
__global__ __launch_bounds__(256) void k_wsplit(const float* __restrict__ t1w,
                                                const float* __restrict__ t2w) {
    int i = blockIdx.x * 256 + threadIdx.x;
    int o = i >> 8, c = i & 255;
    {
        float x = t1w[(size_t)o * 512 + c];
        __nv_bfloat16 h = __float2bfloat16_rn(x);
        g_w1hi[i] = h;
        g_w1lo[i] = __float2bfloat16_rn(x - __bfloat162float(h));
    }
    {
        float x = t2w[i];
        __nv_bfloat16 h = __float2bfloat16_rn(x);
        g_w2hi[i] = h;
        g_w2lo[i] = __float2bfloat16_rn(x - __bfloat162float(h));
    }
}

// ---------------- kernel 6: mma.sync fused transform ----------------
#define SM_B1   0
#define SM_B2   1024
#define SM_WHI  2048
#define SM_WLO  38912
#define SM_XHI  75776
#define SM_XLO  84992
#define SM_STG  94208
#define SM_H    111616
#define SM_TOT  181248
#define WPITCH  144
#define HPITCH  528

__global__ __launch_bounds__(256, 1) void k_transform_mma(const float* __restrict__ feat,
                                                          const float* __restrict__ t2b,
                                                          float* __restrict__ out) {
    extern __shared__ char sm[];
    float* b1s = (float*)(sm + SM_B1);
    float* b2s = (float*)(sm + SM_B2);
    float* stg = (float*)(sm + SM_STG);
    int tid = threadIdx.x;
    int wid = tid >> 5, lane = tid & 31;
    int g = lane >> 2, c4 = lane & 3;
    int ow = (wid >> 1) * 64;
    int pxw = (wid & 1) * 32;
    int n = blockIdx.y;
    int p0 = blockIdx.x * 64;

    b1s[tid] = g_bias1[n * CC + tid];
    b2s[tid] = t2b[tid];

    float d[4][4][4];
#pragma unroll
    for (int mt = 0; mt < 4; mt++)
#pragma unroll
        for (int nt = 0; nt < 4; nt++)
#pragma unroll
            for (int e = 0; e < 4; e++) d[mt][nt][e] = 0.f;

#pragma unroll 1
    for (int kc = 0; kc < 4; kc++) {
        int k0 = kc * 64;
        __syncthreads();
        for (int i = tid; i < 1024; i += 256) {
            int c = i >> 4, p4 = (i & 15) << 2;
            float4 v = *(const float4*)(feat + (size_t)(n * CC + k0 + c) * LL + p0 + p4);
            *(float4*)(stg + c * 68 + p4) = v;
        }
        for (int i = tid; i < 2048; i += 256) {
            int row = i >> 3, j = i & 7;
            *(uint4*)(sm + SM_WHI + row * WPITCH + j * 16) =
                ((const uint4*)g_w1hi)[row * 32 + (k0 >> 3) + j];
            *(uint4*)(sm + SM_WLO + row * WPITCH + j * 16) =
                ((const uint4*)g_w1lo)[row * 32 + (k0 >> 3) + j];
        }
        __syncthreads();
        {
            int px = tid & 63, q = tid >> 6;
#pragma unroll
            for (int jj = 0; jj < 8; jj++) {
                float x0 = stg[(q * 16 + 2 * jj) * 68 + px];
                float x1 = stg[(q * 16 + 2 * jj + 1) * 68 + px];
                __nv_bfloat16 h0 = __float2bfloat16_rn(x0), h1 = __float2bfloat16_rn(x1);
                __nv_bfloat16 l0 = __float2bfloat16_rn(x0 - __bfloat162float(h0));
                __nv_bfloat16 l1 = __float2bfloat16_rn(x1 - __bfloat162float(h1));
                *(uint32_t*)(sm + SM_XHI + px * WPITCH + q * 32 + jj * 4) = pk2(h0, h1);
                *(uint32_t*)(sm + SM_XLO + px * WPITCH + q * 32 + jj * 4) = pk2(l0, l1);
            }
        }
        __syncthreads();
#pragma unroll
        for (int kk = 0; kk < 4; kk++) {
            int kb = kk * 32 + c4 * 4;
            uint32_t bh[4][2], bl[4][2];
#pragma unroll
            for (int nt = 0; nt < 4; nt++) {
                int prow = pxw + nt * 8 + g;
                bh[nt][0] = *(const uint32_t*)(sm + SM_XHI + prow * WPITCH + kb);
                bh[nt][1] = *(const uint32_t*)(sm + SM_XHI + prow * WPITCH + kb + 16);
                bl[nt][0] = *(const uint32_t*)(sm + SM_XLO + prow * WPITCH + kb);
                bl[nt][1] = *(const uint32_t*)(sm + SM_XLO + prow * WPITCH + kb + 16);
            }
#pragma unroll
            for (int mt = 0; mt < 4; mt++) {
                int orow = ow + mt * 16 + g;
                const char* wh = sm + SM_WHI + orow * WPITCH + kb;
                const char* wl = sm + SM_WLO + orow * WPITCH + kb;
                uint32_t ah0 = *(const uint32_t*)(wh);
                uint32_t ah1 = *(const uint32_t*)(wh + 8 * WPITCH);
                uint32_t ah2 = *(const uint32_t*)(wh + 16);
                uint32_t ah3 = *(const uint32_t*)(wh + 8 * WPITCH + 16);
                uint32_t al0 = *(const uint32_t*)(wl);
                uint32_t al1 = *(const uint32_t*)(wl + 8 * WPITCH);
                uint32_t al2 = *(const uint32_t*)(wl + 16);
                uint32_t al3 = *(const uint32_t*)(wl + 8 * WPITCH + 16);
#pragma unroll
                for (int nt = 0; nt < 4; nt++) {
                    mma16816(d[mt][nt], ah0, ah1, ah2, ah3, bh[nt][0], bh[nt][1]);
                    mma16816(d[mt][nt], ah0, ah1, ah2, ah3, bl[nt][0], bl[nt][1]);
                    mma16816(d[mt][nt], al0, al1, al2, al3, bh[nt][0], bh[nt][1]);
                }
            }
        }
    }
    __syncthreads();
    {
        __nv_bfloat16* hh = (__nv_bfloat16*)(sm + SM_H);
        __nv_bfloat16* hl = (__nv_bfloat16*)(sm + SM_H + 64 * HPITCH);
#pragma unroll
        for (int mt = 0; mt < 4; mt++) {
#pragma unroll
            for (int nt = 0; nt < 4; nt++) {
                int oa = ow + mt * 16 + g, ob = oa + 8;
                int pa = pxw + nt * 8 + 2 * c4, pb = pa + 1;
                float v0 = fmaxf(d[mt][nt][0] + b1s[oa], 0.f);
                float v1 = fmaxf(d[mt][nt][1] + b1s[oa], 0.f);
                float v2 = fmaxf(d[mt][nt][2] + b1s[ob], 0.f);
                float v3 = fmaxf(d[mt][nt][3] + b1s[ob], 0.f);
                __nv_bfloat16 h0 = __float2bfloat16_rn(v0);
                __nv_bfloat16 h1 = __float2bfloat16_rn(v1);
                __nv_bfloat16 h2 = __float2bfloat16_rn(v2);
                __nv_bfloat16 h3 = __float2bfloat16_rn(v3);
                hh[pa * (HPITCH / 2) + oa] = h0;
                hh[pb * (HPITCH / 2) + oa] = h1;
                hh[pa * (HPITCH / 2) + ob] = h2;
                hh[pb * (HPITCH / 2) + ob] = h3;
                hl[pa * (HPITCH / 2) + oa] = __float2bfloat16_rn(v0 - __bfloat162float(h0));
                hl[pb * (HPITCH / 2) + oa] = __float2bfloat16_rn(v1 - __bfloat162float(h1));
                hl[pa * (HPITCH / 2) + ob] = __float2bfloat16_rn(v2 - __bfloat162float(h2));
                hl[pb * (HPITCH / 2) + ob] = __float2bfloat16_rn(v3 - __bfloat162float(h3));
                d[mt][nt][0] = 0.f; d[mt][nt][1] = 0.f;
                d[mt][nt][2] = 0.f; d[mt][nt][3] = 0.f;
            }
        }
    }

#pragma unroll 1
    for (int kc = 0; kc < 4; kc++) {
        int k0 = kc * 64;
        __syncthreads();
        for (int i = tid; i < 2048; i += 256) {
            int row = i >> 3, j = i & 7;
            *(uint4*)(sm + SM_WHI + row * WPITCH + j * 16) =
                ((const uint4*)g_w2hi)[row * 32 + (k0 >> 3) + j];
            *(uint4*)(sm + SM_WLO + row * WPITCH + j * 16) =
                ((const uint4*)g_w2lo)[row * 32 + (k0 >> 3) + j];
        }
        __syncthreads();
#pragma unroll
        for (int kk = 0; kk < 4; kk++) {
            int kb = k0 * 2 + kk * 32 + c4 * 4;
            uint32_t bh[4][2], bl[4][2];
#pragma unroll
            for (int nt = 0; nt < 4; nt++) {
                int prow = pxw + nt * 8 + g;
                bh[nt][0] = *(const uint32_t*)(sm + SM_H + prow * HPITCH + kb);
                bh[nt][1] = *(const uint32_t*)(sm + SM_H + prow * HPITCH + kb + 16);
                bl[nt][0] = *(const uint32_t*)(sm + SM_H + 64 * HPITCH + prow * HPITCH + kb);
                bl[nt][1] = *(const uint32_t*)(sm + SM_H + 64 * HPITCH + prow * HPITCH + kb + 16);
            }
            int kbw = kk * 32 + c4 * 4;
#pragma unroll
            for (int mt = 0; mt < 4; mt++) {
                int orow = ow + mt * 16 + g;
                const char* wh = sm + SM_WHI + orow * WPITCH + kbw;
                const char* wl = sm + SM_WLO + orow * WPITCH + kbw;
                uint32_t ah0 = *(const uint32_t*)(wh);
                uint32_t ah1 = *(const uint32_t*)(wh + 8 * WPITCH);
                uint32_t ah2 = *(const uint32_t*)(wh + 16);
                uint32_t ah3 = *(const uint32_t*)(wh + 8 * WPITCH + 16);
                uint32_t al0 = *(const uint32_t*)(wl);
                uint32_t al1 = *(const uint32_t*)(wl + 8 * WPITCH);
                uint32_t al2 = *(const uint32_t*)(wl + 16);
                uint32_t al3 = *(const uint32_t*)(wl + 8 * WPITCH + 16);
#pragma unroll
                for (int nt = 0; nt < 4; nt++) {
                    mma16816(d[mt][nt], ah0, ah1, ah2, ah3, bh[nt][0], bh[nt][1]);
                    mma16816(d[mt][nt], ah0, ah1, ah2, ah3, bl[nt][0], bl[nt][1]);
                    mma16816(d[mt][nt], al0, al1, al2, al3, bh[nt][0], bh[nt][1]);
                }
            }
        }
    }
    __syncthreads();
    {
        float* epi = (float*)(sm + SM_H);
#pragma unroll
        for (int mt = 0; mt < 4; mt++) {
#pragma unroll
            for (int nt = 0; nt < 4; nt++) {
                int oa = ow + mt * 16 + g, ob = oa + 8;
                int pa = pxw + nt * 8 + 2 * c4, pb = pa + 1;
                epi[oa * 68 + pa] = fmaxf(d[mt][nt][0] + b2s[oa], 0.f);
                epi[oa * 68 + pb] = fmaxf(d[mt][nt][1] + b2s[oa], 0.f);
                epi[ob * 68 + pa] = fmaxf(d[mt][nt][2] + b2s[ob], 0.f);
                epi[ob * 68 + pb] = fmaxf(d[mt][nt][3] + b2s[ob], 0.f);
            }
        }
        __syncthreads();
        for (int i = tid; i < 16384; i += 256) {
            int o = i >> 6, px = i & 63;
            out[(size_t)(n * CC + o) * LL + p0 + px] = epi[o * 68 + px];
        }
    }
}

// ---------------- launch ----------------
extern "C" void kernel_launch(void* const* d_in, const int* in_sizes, int n_in,
                              void* d_out, int out_size) {
    (void)in_sizes; (void)n_in; (void)out_size;
    const float* feature   = (const float*)d_in[0];
    const float* conv_up_w = (const float*)d_in[1];
    const float* conv_up_b = (const float*)d_in[2];
    const float* centroids = (const float*)d_in[3];
    const float* upfc_w    = (const float*)d_in[4];
    const float* upfc_b    = (const float*)d_in[5];
    const float* t1_w      = (const float*)d_in[6];
    const float* t1_b      = (const float*)d_in[7];
    const float* t2_w      = (const float*)d_in[8];
    const float* t2_b      = (const float*)d_in[9];
    float* out = (float*)d_out;

    cudaFuncSetAttribute(k_transform_mma, cudaFuncAttributeMaxDynamicSharedMemorySize, SM_TOT);

    k_wprep<<<288, 256>>>(conv_up_w);
    k_l2norm<<<dim3(16, 16), 256>>>(feature);
    k_conv_mma<<<dim3(4, 4, 16), 256>>>(conv_up_b);
    k_ssum<<<NN * KK, 256>>>();
    k_up0<<<dim3(4, 16, SPL), 256>>>();
    k_up0red<<<NN * KK * CC / 256, 256>>>();
    k_upnorm<<<NN, 256>>>(centroids);
    k_fc<<<dim3(16, JS), 256>>>(upfc_w);
    k_fcred<<<NN, 256>>>(upfc_b);
    k_bias1<<<dim3(8, 16), 256>>>(t1_w, t1_b);
    k_wsplit<<<256, 256>>>(t1_w, t2_w);
    k_transform_mma<<<dim3(64, 16), 256, SM_TOT>>>(feature, t2_b, out);
}

// round 8
// speedup vs baseline: 2.7668x; 1.0346x over previous
#include <cuda_runtime.h>
#include <cuda_bf16.h>
#include <cstdint>
#include <math.h>

#define NN 16
#define CC 256
#define HH 64
#define WW 64
#define LL 4096
#define KK 32
#define EPSV 1e-12f
#define SPL 16   // L-splits for k_up0
#define JS  32   // j-splits for FC

// ---------------- scratch (device globals; no allocation) ----------------
__device__ float g_xn[NN * CC * LL];          // 64 MB: l2-normalized feature (planar)
__device__ __nv_bfloat16 g_xci_hi[(size_t)NN * LL * CC];  // 32 MB: xn bf16 hi, [n][l][c]
__device__ __nv_bfloat16 g_xci_lo[(size_t)NN * LL * CC];  // 32 MB: xn bf16 lo
__device__ __nv_bfloat16 g_fci_hi[(size_t)NN * LL * CC];  // 32 MB: RAW feature bf16 hi, [n][l][c]
__device__ __nv_bfloat16 g_fci_lo[(size_t)NN * LL * CC];  // 32 MB: RAW feature bf16 lo
__device__ float g_sa[NN * KK * LL];          // 8 MB : softmax assignment
__device__ float g_ssump[SPL * NN * KK];      // ssum partials per L-split
__device__ float g_up0p[SPL * NN * KK * CC];  // 8 MB : einsum partials per L-split
__device__ float g_up0[NN * KK * CC];         // reduced einsum result
__device__ float g_upn[NN * KK * CC];         // fully normalized up
__device__ float g_fcp[JS * NN * CC];         // FC partials
__device__ float g_ufc[NN * CC];              // FC result
__device__ float g_bias1[NN * CC];            // effective t1 bias
__device__ __nv_bfloat16 g_cwhi[9 * 16 * 32 * 16];  // conv W split: [tap][chunk][m][k]
__device__ __nv_bfloat16 g_cwlo[9 * 16 * 32 * 16];
__device__ __nv_bfloat16 g_w1hi[CC * CC];     // t1_w (first 256 in-chans) split
__device__ __nv_bfloat16 g_w1lo[CC * CC];
__device__ __nv_bfloat16 g_w2hi[CC * CC];     // t2_w split
__device__ __nv_bfloat16 g_w2lo[CC * CC];

static __device__ __forceinline__ uint32_t pk2(__nv_bfloat16 a, __nv_bfloat16 b) {
    return (uint32_t)__bfloat16_as_ushort(a) | ((uint32_t)__bfloat16_as_ushort(b) << 16);
}
// bf16 mma m16n8k16, fp32 accum (sm_80+, valid on baseline sm_103)
static __device__ __forceinline__ void mma16816(float* d,
                                                uint32_t a0, uint32_t a1, uint32_t a2, uint32_t a3,
                                                uint32_t b0, uint32_t b1) {
    asm volatile("mma.sync.aligned.m16n8k16.row.col.f32.bf16.bf16.f32 "
                 "{%0,%1,%2,%3}, {%4,%5,%6,%7}, {%8,%9}, {%0,%1,%2,%3};"
                 : "+f"(d[0]), "+f"(d[1]), "+f"(d[2]), "+f"(d[3])
                 : "r"(a0), "r"(a1), "r"(a2), "r"(a3), "r"(b0), "r"(b1));
}

// ---------------- kernel 1: L2 norm; emit planar f32 xn + bf16 splits of xn AND raw feature ----------------
__global__ __launch_bounds__(256) void k_l2norm(const float* __restrict__ f) {
    int n = blockIdx.y;
    int l = blockIdx.x * 256 + threadIdx.x;
    size_t base = (size_t)n * CC * LL + l;
    float s = 0.f;
#pragma unroll 8
    for (int c = 0; c < CC; c++) {
        float v = f[base + (size_t)c * LL];
        s += v * v;
    }
    float inv = 1.f / fmaxf(sqrtf(s), EPSV);
    size_t cib = ((size_t)n * LL + l) * CC;
    __align__(16) unsigned short hbuf[16], lbuf[16], fhb[16], flb[16];
#pragma unroll 4
    for (int c = 0; c < CC; c++) {
        float vr = f[base + (size_t)c * LL];
        float v = vr * inv;
        g_xn[base + (size_t)c * LL] = v;
        __nv_bfloat16 h = __float2bfloat16_rn(v);
        hbuf[c & 15] = __bfloat16_as_ushort(h);
        lbuf[c & 15] = __bfloat16_as_ushort(__float2bfloat16_rn(v - __bfloat162float(h)));
        __nv_bfloat16 fh = __float2bfloat16_rn(vr);
        fhb[c & 15] = __bfloat16_as_ushort(fh);
        flb[c & 15] = __bfloat16_as_ushort(__float2bfloat16_rn(vr - __bfloat162float(fh)));
        if ((c & 15) == 15) {
            *(uint4*)(g_xci_hi + cib + c - 15) = *(uint4*)hbuf;
            *(uint4*)(g_xci_hi + cib + c - 7)  = *(uint4*)(hbuf + 8);
            *(uint4*)(g_xci_lo + cib + c - 15) = *(uint4*)lbuf;
            *(uint4*)(g_xci_lo + cib + c - 7)  = *(uint4*)(lbuf + 8);
            *(uint4*)(g_fci_hi + cib + c - 15) = *(uint4*)fhb;
            *(uint4*)(g_fci_hi + cib + c - 7)  = *(uint4*)(fhb + 8);
            *(uint4*)(g_fci_lo + cib + c - 15) = *(uint4*)flb;
            *(uint4*)(g_fci_lo + cib + c - 7)  = *(uint4*)(flb + 8);
        }
    }
}

// ---------------- prep: conv weights -> [tap][chunk][m][k] bf16 hi/lo ----------------
__global__ __launch_bounds__(256) void k_wprep(const float* __restrict__ w) {
    int i = blockIdx.x * 256 + threadIdx.x;   // 73728
    int t = i >> 13;
    int r = i & 8191;
    int chn = r >> 9;
    int m = (r >> 4) & 31;
    int kk = r & 15;
    int c = chn * 16 + kk;
    float x = w[((size_t)m * CC + c) * 9 + t];
    __nv_bfloat16 h = __float2bfloat16_rn(x);
    g_cwhi[i] = h;
    g_cwlo[i] = __float2bfloat16_rn(x - __bfloat162float(h));
}

// ---------------- kernel 2: 3x3 conv via mma.sync + fused softmax ----------------
__global__ __launch_bounds__(256) void k_conv_mma(const float* __restrict__ bias) {
    __shared__ __align__(16) __nv_bfloat16 hHi[18 * 18 * 16];
    __shared__ __align__(16) __nv_bfloat16 hLo[18 * 18 * 16];
    __shared__ __align__(16) __nv_bfloat16 wHi[9 * 32 * 16];
    __shared__ __align__(16) __nv_bfloat16 wLo[9 * 32 * 16];
    __shared__ float bsm[32];
    int n = blockIdx.z;
    int ty0 = blockIdx.y * 16, tx0 = blockIdx.x * 16;
    int tid = threadIdx.x, wid = tid >> 5, lane = tid & 31;
    int g = lane >> 2, c4 = lane & 3;
    if (tid < 32) bsm[tid] = bias[tid];

    float d[2][4][4];
#pragma unroll
    for (int mt = 0; mt < 2; mt++)
#pragma unroll
        for (int nt = 0; nt < 4; nt++)
#pragma unroll
            for (int e = 0; e < 4; e++) d[mt][nt][e] = 0.f;

#pragma unroll 1
    for (int chk = 0; chk < 16; chk++) {
        int c0 = chk * 16;
        __syncthreads();
        for (int i = tid; i < 648; i += 256) {
            int slot = i >> 1, half = i & 1;
            int y = slot / 18, x = slot - y * 18;
            int gy = ty0 + y - 1, gx = tx0 + x - 1;
            uint4 vh = make_uint4(0, 0, 0, 0), vl = make_uint4(0, 0, 0, 0);
            if ((unsigned)gy < 64u && (unsigned)gx < 64u) {
                size_t off = ((size_t)n * LL + gy * 64 + gx) * CC + c0 + half * 8;
                vh = *(const uint4*)(g_xci_hi + off);
                vl = *(const uint4*)(g_xci_lo + off);
            }
            *(uint4*)(hHi + slot * 16 + half * 8) = vh;
            *(uint4*)(hLo + slot * 16 + half * 8) = vl;
        }
        for (int i = tid; i < 576; i += 256) {
            int t = i >> 6, r = i & 63;
            ((uint4*)wHi)[t * 64 + r] = ((const uint4*)g_cwhi)[(t * 16 + chk) * 64 + r];
            ((uint4*)wLo)[t * 64 + r] = ((const uint4*)g_cwlo)[(t * 16 + chk) * 64 + r];
        }
        __syncthreads();
#pragma unroll
        for (int tap = 0; tap < 9; tap++) {
            int r = tap / 3, s = tap - 3 * (tap / 3);
            uint32_t bh[4][2], bl[4][2];
#pragma unroll
            for (int nt = 0; nt < 4; nt++) {
                int pxl = wid * 32 + nt * 8 + g;
                int y = (pxl >> 4) + r, x = (pxl & 15) + s;
                const __nv_bfloat16* ph = hHi + (y * 18 + x) * 16 + 2 * c4;
                const __nv_bfloat16* pl = hLo + (y * 18 + x) * 16 + 2 * c4;
                bh[nt][0] = *(const uint32_t*)ph;
                bh[nt][1] = *(const uint32_t*)(ph + 8);
                bl[nt][0] = *(const uint32_t*)pl;
                bl[nt][1] = *(const uint32_t*)(pl + 8);
            }
#pragma unroll
            for (int mt = 0; mt < 2; mt++) {
                const __nv_bfloat16* qh = wHi + (tap * 32 + mt * 16 + g) * 16 + 2 * c4;
                const __nv_bfloat16* ql = wLo + (tap * 32 + mt * 16 + g) * 16 + 2 * c4;
                uint32_t ah0 = *(const uint32_t*)qh;
                uint32_t ah1 = *(const uint32_t*)(qh + 128);
                uint32_t ah2 = *(const uint32_t*)(qh + 8);
                uint32_t ah3 = *(const uint32_t*)(qh + 136);
                uint32_t al0 = *(const uint32_t*)ql;
                uint32_t al1 = *(const uint32_t*)(ql + 128);
                uint32_t al2 = *(const uint32_t*)(ql + 8);
                uint32_t al3 = *(const uint32_t*)(ql + 136);
#pragma unroll
                for (int nt = 0; nt < 4; nt++) {
                    mma16816(d[mt][nt], ah0, ah1, ah2, ah3, bh[nt][0], bh[nt][1]);
                    mma16816(d[mt][nt], ah0, ah1, ah2, ah3, bl[nt][0], bl[nt][1]);
                    mma16816(d[mt][nt], al0, al1, al2, al3, bh[nt][0], bh[nt][1]);
                }
            }
        }
    }
#pragma unroll
    for (int mt = 0; mt < 2; mt++)
#pragma unroll
        for (int nt = 0; nt < 4; nt++)
#pragma unroll
            for (int e = 0; e < 4; e++)
                d[mt][nt][e] += bsm[mt * 16 + g + (e >> 1) * 8];
#pragma unroll
    for (int nt = 0; nt < 4; nt++) {
#pragma unroll
        for (int e1 = 0; e1 < 2; e1++) {
            float v00 = d[0][nt][e1], v01 = d[0][nt][e1 + 2];
            float v10 = d[1][nt][e1], v11 = d[1][nt][e1 + 2];
            float m = fmaxf(fmaxf(v00, v01), fmaxf(v10, v11));
            m = fmaxf(m, __shfl_xor_sync(0xffffffffu, m, 4));
            m = fmaxf(m, __shfl_xor_sync(0xffffffffu, m, 8));
            m = fmaxf(m, __shfl_xor_sync(0xffffffffu, m, 16));
            float e00 = __expf(v00 - m), e01 = __expf(v01 - m);
            float e10 = __expf(v10 - m), e11 = __expf(v11 - m);
            float s = e00 + e01 + e10 + e11;
            s += __shfl_xor_sync(0xffffffffu, s, 4);
            s += __shfl_xor_sync(0xffffffffu, s, 8);
            s += __shfl_xor_sync(0xffffffffu, s, 16);
            float inv = 1.f / s;
            int px = wid * 32 + nt * 8 + 2 * c4 + e1;
            int gy = ty0 + (px >> 4), gx = tx0 + (px & 15);
            size_t base = ((size_t)n * KK) * LL + gy * 64 + gx;
            g_sa[base + (size_t)g * LL]        = e00 * inv;
            g_sa[base + (size_t)(g + 8) * LL]  = e01 * inv;
            g_sa[base + (size_t)(g + 16) * LL] = e10 * inv;
            g_sa[base + (size_t)(g + 24) * LL] = e11 * inv;
        }
    }
}

// ---------------- kernel 4: einsum partials, l-innermost float4 + fused ssum ----------------
#define XP 68
__global__ __launch_bounds__(256) void k_up0() {
    int n = blockIdx.y;
    int c0 = blockIdx.x * 128;
    int sp = blockIdx.z;
    int lbase = sp * (LL / SPL);
    __shared__ float sas[KK][XP];
    __shared__ float xcs[128][XP];
    int tid = threadIdx.x;
    int kt = tid >> 4, ct = tid & 15;
    float acc[2][8];
#pragma unroll
    for (int i = 0; i < 2; i++)
#pragma unroll
        for (int j = 0; j < 8; j++) acc[i][j] = 0.f;
    float ss = 0.f;
#pragma unroll 1
    for (int ch = 0; ch < 4; ch++) {
        int l0 = lbase + ch * 64;
        __syncthreads();
        for (int i = tid; i < 32 * 16; i += 256) {
            int k = i >> 4, l4 = (i & 15) << 2;
            *(float4*)&sas[k][l4] = *(const float4*)(g_sa + (size_t)(n * KK + k) * LL + l0 + l4);
        }
        for (int i = tid; i < 128 * 16; i += 256) {
            int c = i >> 4, l4 = (i & 15) << 2;
            *(float4*)&xcs[c][l4] = *(const float4*)(g_xn + (size_t)(n * CC + c0 + c) * LL + l0 + l4);
        }
        __syncthreads();
        if (blockIdx.x == 0 && tid < 32) {
#pragma unroll 8
            for (int l = 0; l < 64; l++) ss += sas[tid][l];
        }
#pragma unroll 4
        for (int l4 = 0; l4 < 64; l4 += 4) {
            float4 a0 = *(const float4*)&sas[kt][l4];
            float4 a1 = *(const float4*)&sas[kt + 16][l4];
#pragma unroll
            for (int cj = 0; cj < 8; cj++) {
                float4 b = *(const float4*)&xcs[ct + 16 * cj][l4];
                acc[0][cj] += a0.x * b.x + a0.y * b.y + a0.z * b.z + a0.w * b.w;
                acc[1][cj] += a1.x * b.x + a1.y * b.y + a1.z * b.z + a1.w * b.w;
            }
        }
    }
    size_t ob = ((size_t)sp * NN + n) * (KK * CC);
#pragma unroll
    for (int cj = 0; cj < 8; cj++) {
        g_up0p[ob + kt * CC + c0 + ct + 16 * cj] = acc[0][cj];
        g_up0p[ob + (kt + 16) * CC + c0 + ct + 16 * cj] = acc[1][cj];
    }
    if (blockIdx.x == 0 && tid < 32)
        g_ssump[(sp * NN + n) * KK + tid] = ss;
}

__global__ __launch_bounds__(256) void k_up0red() {
    int i = blockIdx.x * 256 + threadIdx.x;
    float s = 0.f;
#pragma unroll
    for (int sp = 0; sp < SPL; sp++)
        s += g_up0p[(size_t)sp * (NN * KK * CC) + i];
    g_up0[i] = s;
}

// ---------------- kernel 5a: centroid-sub + row norm + global norm -> g_upn ----------------
__global__ __launch_bounds__(256) void k_upnorm(const float* __restrict__ cent) {
    int n = blockIdx.x;
    int tid = threadIdx.x;
    int lane = tid & 31, wp = tid >> 5;
    __shared__ float upn[KK * CC];
    __shared__ float red[8];
    __shared__ float ssk[KK];
    __shared__ float gtot;

    if (tid < KK) {
        float s = 0.f;
#pragma unroll
        for (int sp = 0; sp < SPL; sp++)
            s += g_ssump[(sp * NN + n) * KK + tid];
        ssk[tid] = s;
    }
    __syncthreads();

    for (int k = wp; k < KK; k += 8) {
        float sk = ssk[k];
        float vals[8];
        float sq = 0.f;
#pragma unroll
        for (int j = 0; j < 8; j++) {
            int c = lane + 32 * j;
            float u = g_up0[(n * KK + k) * CC + c] - sk * cent[k * CC + c];
            vals[j] = u;
            sq += u * u;
        }
        for (int off = 16; off; off >>= 1) sq += __shfl_xor_sync(0xffffffffu, sq, off);
        float inv = 1.f / fmaxf(sqrtf(sq), EPSV);
#pragma unroll
        for (int j = 0; j < 8; j++) upn[k * CC + lane + 32 * j] = vals[j] * inv;
    }
    __syncthreads();
    float gs = 0.f;
#pragma unroll 4
    for (int j = 0; j < 32; j++) {
        float v = upn[j * 256 + tid];
        gs += v * v;
    }
    for (int off = 16; off; off >>= 1) gs += __shfl_xor_sync(0xffffffffu, gs, off);
    if (!lane) red[wp] = gs;
    __syncthreads();
    if (tid == 0) {
        float t = 0.f;
        for (int i = 0; i < 8; i++) t += red[i];
        gtot = 1.f / fmaxf(sqrtf(t), EPSV);
    }
    __syncthreads();
    float ginv = gtot;
#pragma unroll 4
    for (int j = 0; j < 32; j++)
        g_upn[n * (KK * CC) + j * 256 + tid] = upn[j * 256 + tid] * ginv;
}

// ---------------- kernel 5b: FC partials ----------------
#define FCP 264
__global__ __launch_bounds__(256) void k_fc(const float* __restrict__ wfc) {
    __shared__ float ws[16][FCP];
    __shared__ float us[16][FCP];
    int ot = blockIdx.x * 16;
    int j0 = blockIdx.y * 256;
    int tid = threadIdx.x;
    for (int i = tid; i < 16 * 64; i += 256) {
        int row = i >> 6, j4 = (i & 63) << 2;
        *(float4*)&ws[row][j4] = *(const float4*)(wfc + (size_t)(ot + row) * (KK * CC) + j0 + j4);
        *(float4*)&us[row][j4] = *(const float4*)(g_upn + (size_t)row * (KK * CC) + j0 + j4);
    }
    __syncthreads();
    int o = tid & 15, n = tid >> 4;
    float s = 0.f;
#pragma unroll 8
    for (int jj = 0; jj < 64; jj++) {
        float4 a = *(const float4*)&ws[o][jj * 4];
        float4 b = *(const float4*)&us[n][jj * 4];
        s += a.x * b.x + a.y * b.y + a.z * b.z + a.w * b.w;
    }
    g_fcp[(size_t)(blockIdx.y * NN + n) * CC + ot + o] = s;
}

__global__ __launch_bounds__(256) void k_fcred(const float* __restrict__ bfc) {
    int n = blockIdx.x, o = threadIdx.x;
    float s = 0.f;
#pragma unroll
    for (int js = 0; js < JS; js++)
        s += g_fcp[(size_t)(js * NN + n) * CC + o];
    g_ufc[n * CC + o] = s + bfc[o];
}

__global__ __launch_bounds__(256) void k_bias1(const float* __restrict__ t1w,
                                               const float* __restrict__ t1b) {
    int n = blockIdx.y;
    int o = blockIdx.x * 32 + (threadIdx.x >> 3);
    int grp = threadIdx.x & 7;
    float s = 0.f;
#pragma unroll
    for (int q = 0; q < 8; q++) {
        int c = grp * 32 + q * 4;
        float4 wv = *(const float4*)(t1w + (size_t)o * 512 + 256 + c);
        float4 uv = *(const float4*)(g_ufc + n * CC + c);
        s += wv.x * uv.x + wv.y * uv.y + wv.z * uv.z + wv.w * uv.w;
    }
#pragma unroll
    for (int off = 4; off; off >>= 1)
        s += __shfl_down_sync(0xffffffffu, s, off, 8);
    if (grp == 0) g_bias1[n * CC + o] = t1b[o] + s;
}

// ---------------- prep: split t1/t2 weights ----------------
__global__ __launch_bounds__(256) void k_wsplit(const float* __restrict__ t1w,
                                                const float* __restrict__ t2w) {
    int i = blockIdx.x * 256 + threadIdx.x;
    int o = i >> 8, c = i & 255;
    {
        float x = t1w[(size_t)o * 512 + c];
        __nv_bfloat16 h = __float2bfloat16_rn(x);
        g_w1hi[i] = h;
        g_w1lo[i] = __float2bfloat16_rn(x - __bfloat162float(h));
    }
    {
        float x = t2w[i];
        __nv_bfloat16 h = __float2bfloat16_rn(x);
        g_w2hi[i] = h;
        g_w2lo[i] = __float2bfloat16_rn(x - __bfloat162float(h));
    }
}

// ---------------- kernel 6: mma.sync fused transform (A direct from g_fci — RAW feature) ----------------
#define SM_B1   0
#define SM_B2   1024
#define SM_WHI  2048
#define SM_WLO  38912
#define SM_XHI  75776
#define SM_XLO  84992
#define SM_H    94208
#define SM_TOT  163840
#define WPITCH  144
#define HPITCH  528

__global__ __launch_bounds__(256, 1) void k_transform_mma(const float* __restrict__ t2b,
                                                          float* __restrict__ out) {
    extern __shared__ char sm[];
    float* b1s = (float*)(sm + SM_B1);
    float* b2s = (float*)(sm + SM_B2);
    int tid = threadIdx.x;
    int wid = tid >> 5, lane = tid & 31;
    int g = lane >> 2, c4 = lane & 3;
    int ow = (wid >> 1) * 64;
    int pxw = (wid & 1) * 32;
    int n = blockIdx.y;
    int p0 = blockIdx.x * 64;

    b1s[tid] = g_bias1[n * CC + tid];
    b2s[tid] = t2b[tid];

    float d[4][4][4];
#pragma unroll
    for (int mt = 0; mt < 4; mt++)
#pragma unroll
        for (int nt = 0; nt < 4; nt++)
#pragma unroll
            for (int e = 0; e < 4; e++) d[mt][nt][e] = 0.f;

#pragma unroll 1
    for (int kc = 0; kc < 4; kc++) {
        int k0 = kc * 64;
        __syncthreads();
        // A/X tile direct from g_fci (RAW feature, bf16 split, [px][c] layout)
        for (int i = tid; i < 512; i += 256) {
            int px = i >> 3, j = i & 7;
            size_t off = ((size_t)n * LL + p0 + px) * CC + k0 + j * 8;
            *(uint4*)(sm + SM_XHI + px * WPITCH + j * 16) = *(const uint4*)(g_fci_hi + off);
            *(uint4*)(sm + SM_XLO + px * WPITCH + j * 16) = *(const uint4*)(g_fci_lo + off);
        }
        for (int i = tid; i < 2048; i += 256) {
            int row = i >> 3, j = i & 7;
            *(uint4*)(sm + SM_WHI + row * WPITCH + j * 16) =
                ((const uint4*)g_w1hi)[row * 32 + (k0 >> 3) + j];
            *(uint4*)(sm + SM_WLO + row * WPITCH + j * 16) =
                ((const uint4*)g_w1lo)[row * 32 + (k0 >> 3) + j];
        }
        __syncthreads();
#pragma unroll
        for (int kk = 0; kk < 4; kk++) {
            int kb = kk * 32 + c4 * 4;
            uint32_t bh[4][2], bl[4][2];
#pragma unroll
            for (int nt = 0; nt < 4; nt++) {
                int prow = pxw + nt * 8 + g;
                bh[nt][0] = *(const uint32_t*)(sm + SM_XHI + prow * WPITCH + kb);
                bh[nt][1] = *(const uint32_t*)(sm + SM_XHI + prow * WPITCH + kb + 16);
                bl[nt][0] = *(const uint32_t*)(sm + SM_XLO + prow * WPITCH + kb);
                bl[nt][1] = *(const uint32_t*)(sm + SM_XLO + prow * WPITCH + kb + 16);
            }
#pragma unroll
            for (int mt = 0; mt < 4; mt++) {
                int orow = ow + mt * 16 + g;
                const char* wh = sm + SM_WHI + orow * WPITCH + kb;
                const char* wl = sm + SM_WLO + orow * WPITCH + kb;
                uint32_t ah0 = *(const uint32_t*)(wh);
                uint32_t ah1 = *(const uint32_t*)(wh + 8 * WPITCH);
                uint32_t ah2 = *(const uint32_t*)(wh + 16);
                uint32_t ah3 = *(const uint32_t*)(wh + 8 * WPITCH + 16);
                uint32_t al0 = *(const uint32_t*)(wl);
                uint32_t al1 = *(const uint32_t*)(wl + 8 * WPITCH);
                uint32_t al2 = *(const uint32_t*)(wl + 16);
                uint32_t al3 = *(const uint32_t*)(wl + 8 * WPITCH + 16);
#pragma unroll
                for (int nt = 0; nt < 4; nt++) {
                    mma16816(d[mt][nt], ah0, ah1, ah2, ah3, bh[nt][0], bh[nt][1]);
                    mma16816(d[mt][nt], ah0, ah1, ah2, ah3, bl[nt][0], bl[nt][1]);
                    mma16816(d[mt][nt], al0, al1, al2, al3, bh[nt][0], bh[nt][1]);
                }
            }
        }
    }
    __syncthreads();
    {
        __nv_bfloat16* hh = (__nv_bfloat16*)(sm + SM_H);
        __nv_bfloat16* hl = (__nv_bfloat16*)(sm + SM_H + 64 * HPITCH);
#pragma unroll
        for (int mt = 0; mt < 4; mt++) {
#pragma unroll
            for (int nt = 0; nt < 4; nt++) {
                int oa = ow + mt * 16 + g, ob = oa + 8;
                int pa = pxw + nt * 8 + 2 * c4, pb = pa + 1;
                float v0 = fmaxf(d[mt][nt][0] + b1s[oa], 0.f);
                float v1 = fmaxf(d[mt][nt][1] + b1s[oa], 0.f);
                float v2 = fmaxf(d[mt][nt][2] + b1s[ob], 0.f);
                float v3 = fmaxf(d[mt][nt][3] + b1s[ob], 0.f);
                __nv_bfloat16 h0 = __float2bfloat16_rn(v0);
                __nv_bfloat16 h1 = __float2bfloat16_rn(v1);
                __nv_bfloat16 h2 = __float2bfloat16_rn(v2);
                __nv_bfloat16 h3 = __float2bfloat16_rn(v3);
                hh[pa * (HPITCH / 2) + oa] = h0;
                hh[pb * (HPITCH / 2) + oa] = h1;
                hh[pa * (HPITCH / 2) + ob] = h2;
                hh[pb * (HPITCH / 2) + ob] = h3;
                hl[pa * (HPITCH / 2) + oa] = __float2bfloat16_rn(v0 - __bfloat162float(h0));
                hl[pb * (HPITCH / 2) + oa] = __float2bfloat16_rn(v1 - __bfloat162float(h1));
                hl[pa * (HPITCH / 2) + ob] = __float2bfloat16_rn(v2 - __bfloat162float(h2));
                hl[pb * (HPITCH / 2) + ob] = __float2bfloat16_rn(v3 - __bfloat162float(h3));
                d[mt][nt][0] = 0.f; d[mt][nt][1] = 0.f;
                d[mt][nt][2] = 0.f; d[mt][nt][3] = 0.f;
            }
        }
    }

#pragma unroll 1
    for (int kc = 0; kc < 4; kc++) {
        int k0 = kc * 64;
        __syncthreads();
        for (int i = tid; i < 2048; i += 256) {
            int row = i >> 3, j = i & 7;
            *(uint4*)(sm + SM_WHI + row * WPITCH + j * 16) =
                ((const uint4*)g_w2hi)[row * 32 + (k0 >> 3) + j];
            *(uint4*)(sm + SM_WLO + row * WPITCH + j * 16) =
                ((const uint4*)g_w2lo)[row * 32 + (k0 >> 3) + j];
        }
        __syncthreads();
#pragma unroll
        for (int kk = 0; kk < 4; kk++) {
            int kb = k0 * 2 + kk * 32 + c4 * 4;
            uint32_t bh[4][2], bl[4][2];
#pragma unroll
            for (int nt = 0; nt < 4; nt++) {
                int prow = pxw + nt * 8 + g;
                bh[nt][0] = *(const uint32_t*)(sm + SM_H + prow * HPITCH + kb);
                bh[nt][1] = *(const uint32_t*)(sm + SM_H + prow * HPITCH + kb + 16);
                bl[nt][0] = *(const uint32_t*)(sm + SM_H + 64 * HPITCH + prow * HPITCH + kb);
                bl[nt][1] = *(const uint32_t*)(sm + SM_H + 64 * HPITCH + prow * HPITCH + kb + 16);
            }
            int kbw = kk * 32 + c4 * 4;
#pragma unroll
            for (int mt = 0; mt < 4; mt++) {
                int orow = ow + mt * 16 + g;
                const char* wh = sm + SM_WHI + orow * WPITCH + kbw;
                const char* wl = sm + SM_WLO + orow * WPITCH + kbw;
                uint32_t ah0 = *(const uint32_t*)(wh);
                uint32_t ah1 = *(const uint32_t*)(wh + 8 * WPITCH);
                uint32_t ah2 = *(const uint32_t*)(wh + 16);
                uint32_t ah3 = *(const uint32_t*)(wh + 8 * WPITCH + 16);
                uint32_t al0 = *(const uint32_t*)(wl);
                uint32_t al1 = *(const uint32_t*)(wl + 8 * WPITCH);
                uint32_t al2 = *(const uint32_t*)(wl + 16);
                uint32_t al3 = *(const uint32_t*)(wl + 8 * WPITCH + 16);
#pragma unroll
                for (int nt = 0; nt < 4; nt++) {
                    mma16816(d[mt][nt], ah0, ah1, ah2, ah3, bh[nt][0], bh[nt][1]);
                    mma16816(d[mt][nt], ah0, ah1, ah2, ah3, bl[nt][0], bl[nt][1]);
                    mma16816(d[mt][nt], al0, al1, al2, al3, bh[nt][0], bh[nt][1]);
                }
            }
        }
    }
    __syncthreads();
    {
        float* epi = (float*)(sm + SM_H);
#pragma unroll
        for (int mt = 0; mt < 4; mt++) {
#pragma unroll
            for (int nt = 0; nt < 4; nt++) {
                int oa = ow + mt * 16 + g, ob = oa + 8;
                int pa = pxw + nt * 8 + 2 * c4, pb = pa + 1;
                epi[oa * 68 + pa] = fmaxf(d[mt][nt][0] + b2s[oa], 0.f);
                epi[oa * 68 + pb] = fmaxf(d[mt][nt][1] + b2s[oa], 0.f);
                epi[ob * 68 + pa] = fmaxf(d[mt][nt][2] + b2s[ob], 0.f);
                epi[ob * 68 + pb] = fmaxf(d[mt][nt][3] + b2s[ob], 0.f);
            }
        }
        __syncthreads();
        for (int i = tid; i < 16384; i += 256) {
            int o = i >> 6, px = i & 63;
            out[(size_t)(n * CC + o) * LL + p0 + px] = epi[o * 68 + px];
        }
    }
}

// ---------------- launch ----------------
extern "C" void kernel_launch(void* const* d_in, const int* in_sizes, int n_in,
                              void* d_out, int out_size) {
    (void)in_sizes; (void)n_in; (void)out_size;
    const float* feature   = (const float*)d_in[0];
    const float* conv_up_w = (const float*)d_in[1];
    const float* conv_up_b = (const float*)d_in[2];
    const float* centroids = (const float*)d_in[3];
    const float* upfc_w    = (const float*)d_in[4];
    const float* upfc_b    = (const float*)d_in[5];
    const float* t1_w      = (const float*)d_in[6];
    const float* t1_b      = (const float*)d_in[7];
    const float* t2_w      = (const float*)d_in[8];
    const float* t2_b      = (const float*)d_in[9];
    float* out = (float*)d_out;

    cudaFuncSetAttribute(k_transform_mma, cudaFuncAttributeMaxDynamicSharedMemorySize, SM_TOT);

    k_wprep<<<288, 256>>>(conv_up_w);
    k_l2norm<<<dim3(16, 16), 256>>>(feature);
    k_conv_mma<<<dim3(4, 4, 16), 256>>>(conv_up_b);
    k_up0<<<dim3(2, 16, SPL), 256>>>();
    k_up0red<<<NN * KK * CC / 256, 256>>>();
    k_upnorm<<<NN, 256>>>(centroids);
    k_fc<<<dim3(16, JS), 256>>>(upfc_w);
    k_fcred<<<NN, 256>>>(upfc_b);
    k_bias1<<<dim3(8, 16), 256>>>(t1_w, t1_b);
    k_wsplit<<<256, 256>>>(t1_w, t2_w);
    k_transform_mma<<<dim3(64, 16), 256, SM_TOT>>>(t2_b, out);
}

// round 9
// speedup vs baseline: 2.7836x; 1.0061x over previous
#include <cuda_runtime.h>
#include <cuda_bf16.h>
#include <cstdint>
#include <math.h>

#define NN 16
#define CC 256
#define HH 64
#define WW 64
#define LL 4096
#define KK 32
#define EPSV 1e-12f
#define SPL 16   // L-splits for k_up0
#define JS  32   // j-splits for FC

// ---------------- scratch (device globals; no allocation) ----------------
__device__ float g_xn[NN * CC * LL];          // 64 MB: l2-normalized feature (planar)
__device__ __nv_bfloat16 g_xci_hi[(size_t)NN * LL * CC];  // 32 MB: xn bf16 hi, [n][l][c]
__device__ __nv_bfloat16 g_xci_lo[(size_t)NN * LL * CC];  // 32 MB: xn bf16 lo
__device__ __nv_bfloat16 g_fci_hi[(size_t)NN * LL * CC];  // 32 MB: RAW feature bf16 hi
__device__ __nv_bfloat16 g_fci_lo[(size_t)NN * LL * CC];  // 32 MB: RAW feature bf16 lo
__device__ float g_sa[NN * KK * LL];          // 8 MB : softmax assignment
__device__ float g_ssump[SPL * NN * KK];      // ssum partials per L-split
__device__ float g_up0p[SPL * NN * KK * CC];  // 8 MB : einsum partials per L-split
__device__ float g_upn[NN * KK * CC];         // fully normalized up
__device__ float g_fcp[JS * NN * CC];         // FC partials
__device__ float g_ufc[NN * CC];              // FC result
__device__ float g_bias1[NN * CC];            // effective t1 bias
__device__ __nv_bfloat16 g_cwhi[9 * 16 * 32 * 16];  // conv W split: [tap][chunk][m][k]
__device__ __nv_bfloat16 g_cwlo[9 * 16 * 32 * 16];
__device__ __nv_bfloat16 g_w1hi[CC * CC];     // t1_w (first 256 in-chans) split
__device__ __nv_bfloat16 g_w1lo[CC * CC];
__device__ __nv_bfloat16 g_w2hi[CC * CC];     // t2_w split
__device__ __nv_bfloat16 g_w2lo[CC * CC];

static __device__ __forceinline__ uint32_t pk2(__nv_bfloat16 a, __nv_bfloat16 b) {
    return (uint32_t)__bfloat16_as_ushort(a) | ((uint32_t)__bfloat16_as_ushort(b) << 16);
}
static __device__ __forceinline__ void mma16816(float* d,
                                                uint32_t a0, uint32_t a1, uint32_t a2, uint32_t a3,
                                                uint32_t b0, uint32_t b1) {
    asm volatile("mma.sync.aligned.m16n8k16.row.col.f32.bf16.bf16.f32 "
                 "{%0,%1,%2,%3}, {%4,%5,%6,%7}, {%8,%9}, {%0,%1,%2,%3};"
                 : "+f"(d[0]), "+f"(d[1]), "+f"(d[2]), "+f"(d[3])
                 : "r"(a0), "r"(a1), "r"(a2), "r"(a3), "r"(b0), "r"(b1));
}
__device__ __forceinline__ uint32_t smem_u32(const void* p) {
    uint32_t a;
    asm("{ .reg .u64 t; cvta.to.shared.u64 t, %1; cvt.u32.u64 %0, t; }" : "=r"(a) : "l"(p));
    return a;
}
#define CP16(dst, src) asm volatile("cp.async.cg.shared.global [%0], [%1], 16;" :: "r"(dst), "l"(src) : "memory")
#define CP_COMMIT()    asm volatile("cp.async.commit_group;" ::: "memory")
#define CP_WAIT1()     asm volatile("cp.async.wait_group 1;" ::: "memory")
#define CP_WAIT0()     asm volatile("cp.async.wait_group 0;" ::: "memory")

// ---------------- kernel 1: L2 norm; emit planar f32 xn + bf16 splits of xn AND raw feature ----------------
__global__ __launch_bounds__(256) void k_l2norm(const float* __restrict__ f) {
    int n = blockIdx.y;
    int l = blockIdx.x * 256 + threadIdx.x;
    size_t base = (size_t)n * CC * LL + l;
    float s = 0.f;
#pragma unroll 8
    for (int c = 0; c < CC; c++) {
        float v = f[base + (size_t)c * LL];
        s += v * v;
    }
    float inv = 1.f / fmaxf(sqrtf(s), EPSV);
    size_t cib = ((size_t)n * LL + l) * CC;
    __align__(16) unsigned short hbuf[16], lbuf[16], fhb[16], flb[16];
#pragma unroll 4
    for (int c = 0; c < CC; c++) {
        float vr = f[base + (size_t)c * LL];
        float v = vr * inv;
        g_xn[base + (size_t)c * LL] = v;
        __nv_bfloat16 h = __float2bfloat16_rn(v);
        hbuf[c & 15] = __bfloat16_as_ushort(h);
        lbuf[c & 15] = __bfloat16_as_ushort(__float2bfloat16_rn(v - __bfloat162float(h)));
        __nv_bfloat16 fh = __float2bfloat16_rn(vr);
        fhb[c & 15] = __bfloat16_as_ushort(fh);
        flb[c & 15] = __bfloat16_as_ushort(__float2bfloat16_rn(vr - __bfloat162float(fh)));
        if ((c & 15) == 15) {
            *(uint4*)(g_xci_hi + cib + c - 15) = *(uint4*)hbuf;
            *(uint4*)(g_xci_hi + cib + c - 7)  = *(uint4*)(hbuf + 8);
            *(uint4*)(g_xci_lo + cib + c - 15) = *(uint4*)lbuf;
            *(uint4*)(g_xci_lo + cib + c - 7)  = *(uint4*)(lbuf + 8);
            *(uint4*)(g_fci_hi + cib + c - 15) = *(uint4*)fhb;
            *(uint4*)(g_fci_hi + cib + c - 7)  = *(uint4*)(fhb + 8);
            *(uint4*)(g_fci_lo + cib + c - 15) = *(uint4*)flb;
            *(uint4*)(g_fci_lo + cib + c - 7)  = *(uint4*)(flb + 8);
        }
    }
}

// ---------------- prep: conv weights -> [tap][chunk][m][k] bf16 hi/lo ----------------
__global__ __launch_bounds__(256) void k_wprep(const float* __restrict__ w) {
    int i = blockIdx.x * 256 + threadIdx.x;   // 73728
    int t = i >> 13;
    int r = i & 8191;
    int chn = r >> 9;
    int m = (r >> 4) & 31;
    int kk = r & 15;
    int c = chn * 16 + kk;
    float x = w[((size_t)m * CC + c) * 9 + t];
    __nv_bfloat16 h = __float2bfloat16_rn(x);
    g_cwhi[i] = h;
    g_cwlo[i] = __float2bfloat16_rn(x - __bfloat162float(h));
}

// ---------------- kernel 2: 3x3 conv via mma.sync + fused softmax ----------------
__global__ __launch_bounds__(256) void k_conv_mma(const float* __restrict__ bias) {
    __shared__ __align__(16) __nv_bfloat16 hHi[18 * 18 * 16];
    __shared__ __align__(16) __nv_bfloat16 hLo[18 * 18 * 16];
    __shared__ __align__(16) __nv_bfloat16 wHi[9 * 32 * 16];
    __shared__ __align__(16) __nv_bfloat16 wLo[9 * 32 * 16];
    __shared__ float bsm[32];
    int n = blockIdx.z;
    int ty0 = blockIdx.y * 16, tx0 = blockIdx.x * 16;
    int tid = threadIdx.x, wid = tid >> 5, lane = tid & 31;
    int g = lane >> 2, c4 = lane & 3;
    if (tid < 32) bsm[tid] = bias[tid];

    float d[2][4][4];
#pragma unroll
    for (int mt = 0; mt < 2; mt++)
#pragma unroll
        for (int nt = 0; nt < 4; nt++)
#pragma unroll
            for (int e = 0; e < 4; e++) d[mt][nt][e] = 0.f;

#pragma unroll 1
    for (int chk = 0; chk < 16; chk++) {
        int c0 = chk * 16;
        __syncthreads();
        for (int i = tid; i < 648; i += 256) {
            int slot = i >> 1, half = i & 1;
            int y = slot / 18, x = slot - y * 18;
            int gy = ty0 + y - 1, gx = tx0 + x - 1;
            uint4 vh = make_uint4(0, 0, 0, 0), vl = make_uint4(0, 0, 0, 0);
            if ((unsigned)gy < 64u && (unsigned)gx < 64u) {
                size_t off = ((size_t)n * LL + gy * 64 + gx) * CC + c0 + half * 8;
                vh = *(const uint4*)(g_xci_hi + off);
                vl = *(const uint4*)(g_xci_lo + off);
            }
            *(uint4*)(hHi + slot * 16 + half * 8) = vh;
            *(uint4*)(hLo + slot * 16 + half * 8) = vl;
        }
        for (int i = tid; i < 576; i += 256) {
            int t = i >> 6, r = i & 63;
            ((uint4*)wHi)[t * 64 + r] = ((const uint4*)g_cwhi)[(t * 16 + chk) * 64 + r];
            ((uint4*)wLo)[t * 64 + r] = ((const uint4*)g_cwlo)[(t * 16 + chk) * 64 + r];
        }
        __syncthreads();
#pragma unroll
        for (int tap = 0; tap < 9; tap++) {
            int r = tap / 3, s = tap - 3 * (tap / 3);
            uint32_t bh[4][2], bl[4][2];
#pragma unroll
            for (int nt = 0; nt < 4; nt++) {
                int pxl = wid * 32 + nt * 8 + g;
                int y = (pxl >> 4) + r, x = (pxl & 15) + s;
                const __nv_bfloat16* ph = hHi + (y * 18 + x) * 16 + 2 * c4;
                const __nv_bfloat16* pl = hLo + (y * 18 + x) * 16 + 2 * c4;
                bh[nt][0] = *(const uint32_t*)ph;
                bh[nt][1] = *(const uint32_t*)(ph + 8);
                bl[nt][0] = *(const uint32_t*)pl;
                bl[nt][1] = *(const uint32_t*)(pl + 8);
            }
#pragma unroll
            for (int mt = 0; mt < 2; mt++) {
                const __nv_bfloat16* qh = wHi + (tap * 32 + mt * 16 + g) * 16 + 2 * c4;
                const __nv_bfloat16* ql = wLo + (tap * 32 + mt * 16 + g) * 16 + 2 * c4;
                uint32_t ah0 = *(const uint32_t*)qh;
                uint32_t ah1 = *(const uint32_t*)(qh + 128);
                uint32_t ah2 = *(const uint32_t*)(qh + 8);
                uint32_t ah3 = *(const uint32_t*)(qh + 136);
                uint32_t al0 = *(const uint32_t*)ql;
                uint32_t al1 = *(const uint32_t*)(ql + 128);
                uint32_t al2 = *(const uint32_t*)(ql + 8);
                uint32_t al3 = *(const uint32_t*)(ql + 136);
#pragma unroll
                for (int nt = 0; nt < 4; nt++) {
                    mma16816(d[mt][nt], ah0, ah1, ah2, ah3, bh[nt][0], bh[nt][1]);
                    mma16816(d[mt][nt], ah0, ah1, ah2, ah3, bl[nt][0], bl[nt][1]);
                    mma16816(d[mt][nt], al0, al1, al2, al3, bh[nt][0], bh[nt][1]);
                }
            }
        }
    }
#pragma unroll
    for (int mt = 0; mt < 2; mt++)
#pragma unroll
        for (int nt = 0; nt < 4; nt++)
#pragma unroll
            for (int e = 0; e < 4; e++)
                d[mt][nt][e] += bsm[mt * 16 + g + (e >> 1) * 8];
#pragma unroll
    for (int nt = 0; nt < 4; nt++) {
#pragma unroll
        for (int e1 = 0; e1 < 2; e1++) {
            float v00 = d[0][nt][e1], v01 = d[0][nt][e1 + 2];
            float v10 = d[1][nt][e1], v11 = d[1][nt][e1 + 2];
            float m = fmaxf(fmaxf(v00, v01), fmaxf(v10, v11));
            m = fmaxf(m, __shfl_xor_sync(0xffffffffu, m, 4));
            m = fmaxf(m, __shfl_xor_sync(0xffffffffu, m, 8));
            m = fmaxf(m, __shfl_xor_sync(0xffffffffu, m, 16));
            float e00 = __expf(v00 - m), e01 = __expf(v01 - m);
            float e10 = __expf(v10 - m), e11 = __expf(v11 - m);
            float s = e00 + e01 + e10 + e11;
            s += __shfl_xor_sync(0xffffffffu, s, 4);
            s += __shfl_xor_sync(0xffffffffu, s, 8);
            s += __shfl_xor_sync(0xffffffffu, s, 16);
            float inv = 1.f / s;
            int px = wid * 32 + nt * 8 + 2 * c4 + e1;
            int gy = ty0 + (px >> 4), gx = tx0 + (px & 15);
            size_t base = ((size_t)n * KK) * LL + gy * 64 + gx;
            g_sa[base + (size_t)g * LL]        = e00 * inv;
            g_sa[base + (size_t)(g + 8) * LL]  = e01 * inv;
            g_sa[base + (size_t)(g + 16) * LL] = e10 * inv;
            g_sa[base + (size_t)(g + 24) * LL] = e11 * inv;
        }
    }
}

// ---------------- kernel 4: einsum partials, l-innermost float4 + fused ssum ----------------
#define XP 68
__global__ __launch_bounds__(256, 4) void k_up0() {
    int n = blockIdx.y;
    int c0 = blockIdx.x * 128;
    int sp = blockIdx.z;
    int lbase = sp * (LL / SPL);
    __shared__ float sas[KK][XP];
    __shared__ float xcs[128][XP];
    int tid = threadIdx.x;
    int kt = tid >> 4, ct = tid & 15;
    float acc[2][8];
#pragma unroll
    for (int i = 0; i < 2; i++)
#pragma unroll
        for (int j = 0; j < 8; j++) acc[i][j] = 0.f;
    float ss = 0.f;
#pragma unroll 1
    for (int ch = 0; ch < 4; ch++) {
        int l0 = lbase + ch * 64;
        __syncthreads();
        for (int i = tid; i < 32 * 16; i += 256) {
            int k = i >> 4, l4 = (i & 15) << 2;
            *(float4*)&sas[k][l4] = *(const float4*)(g_sa + (size_t)(n * KK + k) * LL + l0 + l4);
        }
        for (int i = tid; i < 128 * 16; i += 256) {
            int c = i >> 4, l4 = (i & 15) << 2;
            *(float4*)&xcs[c][l4] = *(const float4*)(g_xn + (size_t)(n * CC + c0 + c) * LL + l0 + l4);
        }
        __syncthreads();
        if (blockIdx.x == 0 && tid < 32) {
#pragma unroll 8
            for (int l = 0; l < 64; l++) ss += sas[tid][l];
        }
#pragma unroll 4
        for (int l4 = 0; l4 < 64; l4 += 4) {
            float4 a0 = *(const float4*)&sas[kt][l4];
            float4 a1 = *(const float4*)&sas[kt + 16][l4];
#pragma unroll
            for (int cj = 0; cj < 8; cj++) {
                float4 b = *(const float4*)&xcs[ct + 16 * cj][l4];
                acc[0][cj] += a0.x * b.x + a0.y * b.y + a0.z * b.z + a0.w * b.w;
                acc[1][cj] += a1.x * b.x + a1.y * b.y + a1.z * b.z + a1.w * b.w;
            }
        }
    }
    size_t ob = ((size_t)sp * NN + n) * (KK * CC);
#pragma unroll
    for (int cj = 0; cj < 8; cj++) {
        g_up0p[ob + kt * CC + c0 + ct + 16 * cj] = acc[0][cj];
        g_up0p[ob + (kt + 16) * CC + c0 + ct + 16 * cj] = acc[1][cj];
    }
    if (blockIdx.x == 0 && tid < 32)
        g_ssump[(sp * NN + n) * KK + tid] = ss;
}

// ---------------- kernel 5a: reduce partials + centroid-sub + norms -> g_upn ----------------
__global__ __launch_bounds__(256) void k_upnorm(const float* __restrict__ cent) {
    int n = blockIdx.x;
    int tid = threadIdx.x;
    int lane = tid & 31, wp = tid >> 5;
    __shared__ float upn[KK * CC];
    __shared__ float red[8];
    __shared__ float ssk[KK];
    __shared__ float gtot;

    if (tid < KK) {
        float s = 0.f;
#pragma unroll
        for (int sp = 0; sp < SPL; sp++)
            s += g_ssump[(sp * NN + n) * KK + tid];
        ssk[tid] = s;
    }
    __syncthreads();

    for (int k = wp; k < KK; k += 8) {
        float sk = ssk[k];
        float vals[8];
        float sq = 0.f;
#pragma unroll
        for (int j = 0; j < 8; j++) {
            int c = lane + 32 * j;
            float u = 0.f;
#pragma unroll
            for (int sp = 0; sp < SPL; sp++)
                u += g_up0p[((size_t)sp * NN + n) * (KK * CC) + k * CC + c];
            u -= sk * cent[k * CC + c];
            vals[j] = u;
            sq += u * u;
        }
        for (int off = 16; off; off >>= 1) sq += __shfl_xor_sync(0xffffffffu, sq, off);
        float inv = 1.f / fmaxf(sqrtf(sq), EPSV);
#pragma unroll
        for (int j = 0; j < 8; j++) upn[k * CC + lane + 32 * j] = vals[j] * inv;
    }
    __syncthreads();
    float gs = 0.f;
#pragma unroll 4
    for (int j = 0; j < 32; j++) {
        float v = upn[j * 256 + tid];
        gs += v * v;
    }
    for (int off = 16; off; off >>= 1) gs += __shfl_xor_sync(0xffffffffu, gs, off);
    if (!lane) red[wp] = gs;
    __syncthreads();
    if (tid == 0) {
        float t = 0.f;
        for (int i = 0; i < 8; i++) t += red[i];
        gtot = 1.f / fmaxf(sqrtf(t), EPSV);
    }
    __syncthreads();
    float ginv = gtot;
#pragma unroll 4
    for (int j = 0; j < 32; j++)
        g_upn[n * (KK * CC) + j * 256 + tid] = upn[j * 256 + tid] * ginv;
}

// ---------------- kernel 5b: FC partials ----------------
#define FCP 264
__global__ __launch_bounds__(256) void k_fc(const float* __restrict__ wfc) {
    __shared__ float ws[16][FCP];
    __shared__ float us[16][FCP];
    int ot = blockIdx.x * 16;
    int j0 = blockIdx.y * 256;
    int tid = threadIdx.x;
    for (int i = tid; i < 16 * 64; i += 256) {
        int row = i >> 6, j4 = (i & 63) << 2;
        *(float4*)&ws[row][j4] = *(const float4*)(wfc + (size_t)(ot + row) * (KK * CC) + j0 + j4);
        *(float4*)&us[row][j4] = *(const float4*)(g_upn + (size_t)row * (KK * CC) + j0 + j4);
    }
    __syncthreads();
    int o = tid & 15, n = tid >> 4;
    float s = 0.f;
#pragma unroll 8
    for (int jj = 0; jj < 64; jj++) {
        float4 a = *(const float4*)&ws[o][jj * 4];
        float4 b = *(const float4*)&us[n][jj * 4];
        s += a.x * b.x + a.y * b.y + a.z * b.z + a.w * b.w;
    }
    g_fcp[(size_t)(blockIdx.y * NN + n) * CC + ot + o] = s;
}

__global__ __launch_bounds__(256) void k_fcred(const float* __restrict__ bfc) {
    int n = blockIdx.x, o = threadIdx.x;
    float s = 0.f;
#pragma unroll
    for (int js = 0; js < JS; js++)
        s += g_fcp[(size_t)(js * NN + n) * CC + o];
    g_ufc[n * CC + o] = s + bfc[o];
}

__global__ __launch_bounds__(256) void k_bias1(const float* __restrict__ t1w,
                                               const float* __restrict__ t1b) {
    int n = blockIdx.y;
    int o = blockIdx.x * 32 + (threadIdx.x >> 3);
    int grp = threadIdx.x & 7;
    float s = 0.f;
#pragma unroll
    for (int q = 0; q < 8; q++) {
        int c = grp * 32 + q * 4;
        float4 wv = *(const float4*)(t1w + (size_t)o * 512 + 256 + c);
        float4 uv = *(const float4*)(g_ufc + n * CC + c);
        s += wv.x * uv.x + wv.y * uv.y + wv.z * uv.z + wv.w * uv.w;
    }
#pragma unroll
    for (int off = 4; off; off >>= 1)
        s += __shfl_down_sync(0xffffffffu, s, off, 8);
    if (grp == 0) g_bias1[n * CC + o] = t1b[o] + s;
}

// ---------------- prep: split t1/t2 weights ----------------
__global__ __launch_bounds__(256) void k_wsplit(const float* __restrict__ t1w,
                                                const float* __restrict__ t2w) {
    int i = blockIdx.x * 256 + threadIdx.x;
    int o = i >> 8, c = i & 255;
    {
        float x = t1w[(size_t)o * 512 + c];
        __nv_bfloat16 h = __float2bfloat16_rn(x);
        g_w1hi[i] = h;
        g_w1lo[i] = __float2bfloat16_rn(x - __bfloat162float(h));
    }
    {
        float x = t2w[i];
        __nv_bfloat16 h = __float2bfloat16_rn(x);
        g_w2hi[i] = h;
        g_w2lo[i] = __float2bfloat16_rn(x - __bfloat162float(h));
    }
}

// ---------------- kernel 6: mma.sync transform, cp.async double-buffered ----------------
// 8 k-chunks of 32 per stage; W row pitch 80 B (conflict-free: (20g+c4)%32 all-distinct).
// smem: [0,1024) bias1, [1024,2048) t2b,
//       [2048, 2048+2*40960)  W bufs (each: hi 256x80, lo 256x80)
//       [83968, 83968+2*10240) X bufs (each: hi 64x80, lo 64x80)
//       [104448, +69632) H (hi 64x528 + lo 64x528) / epi f32 256x68
#define W2P    80
#define SM_WOF 2048
#define SM_XOF 83968
#define SM_HOF 104448
#define SM_TOT 174080
#define HPITCH 528

__global__ __launch_bounds__(256, 1) void k_transform_mma(const float* __restrict__ t2b,
                                                          float* __restrict__ out) {
    extern __shared__ char sm[];
    uint32_t sb = smem_u32(sm);
    float* b1s = (float*)sm;
    float* b2s = (float*)(sm + 1024);
    int tid = threadIdx.x;
    int wid = tid >> 5, lane = tid & 31;
    int g = lane >> 2, c4 = lane & 3;
    int ow = (wid >> 1) * 64;
    int pxw = (wid & 1) * 32;
    int n = blockIdx.y;
    int p0 = blockIdx.x * 64;

    b1s[tid] = g_bias1[n * CC + tid];
    b2s[tid] = t2b[tid];

    // --- prefetch issue helpers (inlined loops) ---
    // W chunk kc into buf b from whi/wlo
#define ISSUE_W(whi, wlo, kc, b)                                                   \
    do {                                                                           \
        uint32_t wb_ = sb + SM_WOF + (b) * 40960;                                  \
        for (int i_ = tid; i_ < 2048; i_ += 256) {                                 \
            int half_ = i_ >> 10;                                                  \
            int r_ = i_ & 1023;                                                    \
            int o_ = r_ >> 2, j_ = r_ & 3;                                         \
            const __nv_bfloat16* s_ = (half_ ? (wlo) : (whi)) + o_ * 256 + (kc) * 32 + j_ * 8; \
            CP16(wb_ + half_ * 20480 + o_ * W2P + j_ * 16, s_);                    \
        }                                                                          \
    } while (0)
    // X chunk kc into buf b (stage 1 only)
#define ISSUE_X(kc, b)                                                             \
    do {                                                                           \
        uint32_t xb_ = sb + SM_XOF + (b) * 10240;                                  \
        for (int i_ = tid; i_ < 512; i_ += 256) {                                  \
            int half_ = i_ >> 8;                                                   \
            int r_ = i_ & 255;                                                     \
            int px_ = r_ >> 2, j_ = r_ & 3;                                        \
            const __nv_bfloat16* s_ = (half_ ? g_fci_lo : g_fci_hi)                \
                + ((size_t)n * LL + p0 + px_) * CC + (kc) * 32 + j_ * 8;           \
            CP16(xb_ + half_ * 5120 + px_ * W2P + j_ * 16, s_);                    \
        }                                                                          \
    } while (0)

    float d[4][4][4];
#pragma unroll
    for (int mt = 0; mt < 4; mt++)
#pragma unroll
        for (int nt = 0; nt < 4; nt++)
#pragma unroll
            for (int e = 0; e < 4; e++) d[mt][nt][e] = 0.f;

    // ================= stage 1: D1 = W1 @ X  (8 chunks of 32 k) =================
    ISSUE_W(g_w1hi, g_w1lo, 0, 0);
    ISSUE_X(0, 0);
    CP_COMMIT();
#pragma unroll 1
    for (int kc = 0; kc < 8; kc++) {
        int b = kc & 1;
        if (kc < 7) {
            ISSUE_W(g_w1hi, g_w1lo, kc + 1, 1 - b);
            ISSUE_X(kc + 1, 1 - b);
            CP_COMMIT();
            CP_WAIT1();
        } else {
            CP_WAIT0();
        }
        __syncthreads();
        const char* wb = sm + SM_WOF + b * 40960;
        const char* xb = sm + SM_XOF + b * 10240;
#pragma unroll
        for (int kk = 0; kk < 2; kk++) {
            int kb = kk * 32 + c4 * 4;
            uint32_t bh[4][2], bl[4][2];
#pragma unroll
            for (int nt = 0; nt < 4; nt++) {
                int prow = pxw + nt * 8 + g;
                bh[nt][0] = *(const uint32_t*)(xb + prow * W2P + kb);
                bh[nt][1] = *(const uint32_t*)(xb + prow * W2P + kb + 16);
                bl[nt][0] = *(const uint32_t*)(xb + 5120 + prow * W2P + kb);
                bl[nt][1] = *(const uint32_t*)(xb + 5120 + prow * W2P + kb + 16);
            }
#pragma unroll
            for (int mt = 0; mt < 4; mt++) {
                int orow = ow + mt * 16 + g;
                const char* wh = wb + orow * W2P + kb;
                const char* wl = wb + 20480 + orow * W2P + kb;
                uint32_t ah0 = *(const uint32_t*)(wh);
                uint32_t ah1 = *(const uint32_t*)(wh + 8 * W2P);
                uint32_t ah2 = *(const uint32_t*)(wh + 16);
                uint32_t ah3 = *(const uint32_t*)(wh + 8 * W2P + 16);
                uint32_t al0 = *(const uint32_t*)(wl);
                uint32_t al1 = *(const uint32_t*)(wl + 8 * W2P);
                uint32_t al2 = *(const uint32_t*)(wl + 16);
                uint32_t al3 = *(const uint32_t*)(wl + 8 * W2P + 16);
#pragma unroll
                for (int nt = 0; nt < 4; nt++) {
                    mma16816(d[mt][nt], ah0, ah1, ah2, ah3, bh[nt][0], bh[nt][1]);
                    mma16816(d[mt][nt], ah0, ah1, ah2, ah3, bl[nt][0], bl[nt][1]);
                    mma16816(d[mt][nt], al0, al1, al2, al3, bh[nt][0], bh[nt][1]);
                }
            }
        }
        __syncthreads();
    }
    // h = relu(D1 + bias1) -> smem [px][o] bf16 hi/lo
    {
        __nv_bfloat16* hh = (__nv_bfloat16*)(sm + SM_HOF);
        __nv_bfloat16* hl = (__nv_bfloat16*)(sm + SM_HOF + 64 * HPITCH);
#pragma unroll
        for (int mt = 0; mt < 4; mt++) {
#pragma unroll
            for (int nt = 0; nt < 4; nt++) {
                int oa = ow + mt * 16 + g, ob = oa + 8;
                int pa = pxw + nt * 8 + 2 * c4, pb = pa + 1;
                float v0 = fmaxf(d[mt][nt][0] + b1s[oa], 0.f);
                float v1 = fmaxf(d[mt][nt][1] + b1s[oa], 0.f);
                float v2 = fmaxf(d[mt][nt][2] + b1s[ob], 0.f);
                float v3 = fmaxf(d[mt][nt][3] + b1s[ob], 0.f);
                __nv_bfloat16 h0 = __float2bfloat16_rn(v0);
                __nv_bfloat16 h1 = __float2bfloat16_rn(v1);
                __nv_bfloat16 h2 = __float2bfloat16_rn(v2);
                __nv_bfloat16 h3 = __float2bfloat16_rn(v3);
                hh[pa * (HPITCH / 2) + oa] = h0;
                hh[pb * (HPITCH / 2) + oa] = h1;
                hh[pa * (HPITCH / 2) + ob] = h2;
                hh[pb * (HPITCH / 2) + ob] = h3;
                hl[pa * (HPITCH / 2) + oa] = __float2bfloat16_rn(v0 - __bfloat162float(h0));
                hl[pb * (HPITCH / 2) + oa] = __float2bfloat16_rn(v1 - __bfloat162float(h1));
                hl[pa * (HPITCH / 2) + ob] = __float2bfloat16_rn(v2 - __bfloat162float(h2));
                hl[pb * (HPITCH / 2) + ob] = __float2bfloat16_rn(v3 - __bfloat162float(h3));
                d[mt][nt][0] = 0.f; d[mt][nt][1] = 0.f;
                d[mt][nt][2] = 0.f; d[mt][nt][3] = 0.f;
            }
        }
    }
    __syncthreads();

    // ================= stage 2: D2 = W2 @ h =================
    ISSUE_W(g_w2hi, g_w2lo, 0, 0);
    CP_COMMIT();
#pragma unroll 1
    for (int kc = 0; kc < 8; kc++) {
        int b = kc & 1;
        if (kc < 7) {
            ISSUE_W(g_w2hi, g_w2lo, kc + 1, 1 - b);
            CP_COMMIT();
            CP_WAIT1();
        } else {
            CP_WAIT0();
        }
        __syncthreads();
        const char* wb = sm + SM_WOF + b * 40960;
#pragma unroll
        for (int kk = 0; kk < 2; kk++) {
            int kb = kk * 32 + c4 * 4;
            int kbh = kc * 64 + kk * 32 + c4 * 4;
            uint32_t bh[4][2], bl[4][2];
#pragma unroll
            for (int nt = 0; nt < 4; nt++) {
                int prow = pxw + nt * 8 + g;
                bh[nt][0] = *(const uint32_t*)(sm + SM_HOF + prow * HPITCH + kbh);
                bh[nt][1] = *(const uint32_t*)(sm + SM_HOF + prow * HPITCH + kbh + 16);
                bl[nt][0] = *(const uint32_t*)(sm + SM_HOF + 64 * HPITCH + prow * HPITCH + kbh);
                bl[nt][1] = *(const uint32_t*)(sm + SM_HOF + 64 * HPITCH + prow * HPITCH + kbh + 16);
            }
#pragma unroll
            for (int mt = 0; mt < 4; mt++) {
                int orow = ow + mt * 16 + g;
                const char* wh = wb + orow * W2P + kb;
                const char* wl = wb + 20480 + orow * W2P + kb;
                uint32_t ah0 = *(const uint32_t*)(wh);
                uint32_t ah1 = *(const uint32_t*)(wh + 8 * W2P);
                uint32_t ah2 = *(const uint32_t*)(wh + 16);
                uint32_t ah3 = *(const uint32_t*)(wh + 8 * W2P + 16);
                uint32_t al0 = *(const uint32_t*)(wl);
                uint32_t al1 = *(const uint32_t*)(wl + 8 * W2P);
                uint32_t al2 = *(const uint32_t*)(wl + 16);
                uint32_t al3 = *(const uint32_t*)(wl + 8 * W2P + 16);
#pragma unroll
                for (int nt = 0; nt < 4; nt++) {
                    mma16816(d[mt][nt], ah0, ah1, ah2, ah3, bh[nt][0], bh[nt][1]);
                    mma16816(d[mt][nt], ah0, ah1, ah2, ah3, bl[nt][0], bl[nt][1]);
                    mma16816(d[mt][nt], al0, al1, al2, al3, bh[nt][0], bh[nt][1]);
                }
            }
        }
        __syncthreads();
    }
    // epilogue: relu(D2 + t2b) -> staging [o][px] f32 -> coalesced out
    {
        float* epi = (float*)(sm + SM_HOF);
#pragma unroll
        for (int mt = 0; mt < 4; mt++) {
#pragma unroll
            for (int nt = 0; nt < 4; nt++) {
                int oa = ow + mt * 16 + g, ob = oa + 8;
                int pa = pxw + nt * 8 + 2 * c4, pb = pa + 1;
                epi[oa * 68 + pa] = fmaxf(d[mt][nt][0] + b2s[oa], 0.f);
                epi[oa * 68 + pb] = fmaxf(d[mt][nt][1] + b2s[oa], 0.f);
                epi[ob * 68 + pa] = fmaxf(d[mt][nt][2] + b2s[ob], 0.f);
                epi[ob * 68 + pb] = fmaxf(d[mt][nt][3] + b2s[ob], 0.f);
            }
        }
        __syncthreads();
        for (int i = tid; i < 16384; i += 256) {
            int o = i >> 6, px = i & 63;
            out[(size_t)(n * CC + o) * LL + p0 + px] = epi[o * 68 + px];
        }
    }
#undef ISSUE_W
#undef ISSUE_X
}

// ---------------- launch ----------------
extern "C" void kernel_launch(void* const* d_in, const int* in_sizes, int n_in,
                              void* d_out, int out_size) {
    (void)in_sizes; (void)n_in; (void)out_size;
    const float* feature   = (const float*)d_in[0];
    const float* conv_up_w = (const float*)d_in[1];
    const float* conv_up_b = (const float*)d_in[2];
    const float* centroids = (const float*)d_in[3];
    const float* upfc_w    = (const float*)d_in[4];
    const float* upfc_b    = (const float*)d_in[5];
    const float* t1_w      = (const float*)d_in[6];
    const float* t1_b      = (const float*)d_in[7];
    const float* t2_w      = (const float*)d_in[8];
    const float* t2_b      = (const float*)d_in[9];
    float* out = (float*)d_out;

    cudaFuncSetAttribute(k_transform_mma, cudaFuncAttributeMaxDynamicSharedMemorySize, SM_TOT);

    k_wprep<<<288, 256>>>(conv_up_w);
    k_l2norm<<<dim3(16, 16), 256>>>(feature);
    k_conv_mma<<<dim3(4, 4, 16), 256>>>(conv_up_b);
    k_up0<<<dim3(2, 16, SPL), 256>>>();
    k_upnorm<<<NN, 256>>>(centroids);
    k_fc<<<dim3(16, JS), 256>>>(upfc_w);
    k_fcred<<<NN, 256>>>(upfc_b);
    k_bias1<<<dim3(8, 16), 256>>>(t1_w, t1_b);
    k_wsplit<<<256, 256>>>(t1_w, t2_w);
    k_transform_mma<<<dim3(64, 16), 256, SM_TOT>>>(t2_b, out);
}

// round 10
// speedup vs baseline: 3.1480x; 1.1309x over previous
#include <cuda_runtime.h>
#include <cuda_bf16.h>
#include <cstdint>
#include <math.h>

#define NN 16
#define CC 256
#define HH 64
#define WW 64
#define LL 4096
#define KK 32
#define EPSV 1e-12f
#define SPL 16   // L-splits for k_up0
#define JS  32   // j-splits for FC

// ---------------- scratch (device globals; no allocation) ----------------
__device__ __nv_bfloat16 g_fci_hi[(size_t)NN * LL * CC];  // 32 MB: RAW feature bf16 hi, [n][l][c]
__device__ __nv_bfloat16 g_fci_lo[(size_t)NN * LL * CC];  // 32 MB: RAW feature bf16 lo
__device__ float g_inv[NN * LL];              // per-pixel 1/||f||
__device__ float g_sa[NN * KK * LL];          // 8 MB : sa' = softmax * inv[pixel]
__device__ float g_ssumc[NN * 16 * KK];       // ssum partials per conv CTA tile
__device__ float g_up0p[SPL * NN * KK * CC];  // 8 MB : einsum partials per L-split
__device__ float g_upn[NN * KK * CC];         // fully normalized up
__device__ float g_fcp[JS * NN * CC];         // FC partials
__device__ float g_ufc[NN * CC];              // FC result
__device__ float g_bias1[NN * CC];            // effective t1 bias
__device__ __nv_bfloat16 g_cwhi[9 * 16 * 32 * 16];  // conv W split: [tap][chunk][m][k]
__device__ __nv_bfloat16 g_cwlo[9 * 16 * 32 * 16];
__device__ __nv_bfloat16 g_w1hi[CC * CC];     // t1_w (first 256 in-chans) split
__device__ __nv_bfloat16 g_w1lo[CC * CC];
__device__ __nv_bfloat16 g_w2hi[CC * CC];     // t2_w split
__device__ __nv_bfloat16 g_w2lo[CC * CC];

static __device__ __forceinline__ uint32_t pk2(__nv_bfloat16 a, __nv_bfloat16 b) {
    return (uint32_t)__bfloat16_as_ushort(a) | ((uint32_t)__bfloat16_as_ushort(b) << 16);
}
static __device__ __forceinline__ void mma16816(float* d,
                                                uint32_t a0, uint32_t a1, uint32_t a2, uint32_t a3,
                                                uint32_t b0, uint32_t b1) {
    asm volatile("mma.sync.aligned.m16n8k16.row.col.f32.bf16.bf16.f32 "
                 "{%0,%1,%2,%3}, {%4,%5,%6,%7}, {%8,%9}, {%0,%1,%2,%3};"
                 : "+f"(d[0]), "+f"(d[1]), "+f"(d[2]), "+f"(d[3])
                 : "r"(a0), "r"(a1), "r"(a2), "r"(a3), "r"(b0), "r"(b1));
}
__device__ __forceinline__ uint32_t smem_u32(const void* p) {
    uint32_t a;
    asm("{ .reg .u64 t; cvta.to.shared.u64 t, %1; cvt.u32.u64 %0, t; }" : "=r"(a) : "l"(p));
    return a;
}
#define CP16(dst, src) asm volatile("cp.async.cg.shared.global [%0], [%1], 16;" :: "r"(dst), "l"(src) : "memory")
#define CP_COMMIT()    asm volatile("cp.async.commit_group;" ::: "memory")
#define CP_WAIT1()     asm volatile("cp.async.wait_group 1;" ::: "memory")
#define CP_WAIT0()     asm volatile("cp.async.wait_group 0;" ::: "memory")

// ---------------- kernel 1: prep — raw bf16 split + per-pixel inv norm (ONE pass) ----------------
__global__ __launch_bounds__(256) void k_prep(const float* __restrict__ f) {
    int n = blockIdx.y;
    int l = blockIdx.x * 256 + threadIdx.x;
    size_t base = (size_t)n * CC * LL + l;
    size_t cib = ((size_t)n * LL + l) * CC;
    float s = 0.f;
    __align__(16) unsigned short fhb[16], flb[16];
#pragma unroll 4
    for (int c = 0; c < CC; c++) {
        float vr = f[base + (size_t)c * LL];
        s += vr * vr;
        __nv_bfloat16 fh = __float2bfloat16_rn(vr);
        fhb[c & 15] = __bfloat16_as_ushort(fh);
        flb[c & 15] = __bfloat16_as_ushort(__float2bfloat16_rn(vr - __bfloat162float(fh)));
        if ((c & 15) == 15) {
            *(uint4*)(g_fci_hi + cib + c - 15) = *(uint4*)fhb;
            *(uint4*)(g_fci_hi + cib + c - 7)  = *(uint4*)(fhb + 8);
            *(uint4*)(g_fci_lo + cib + c - 15) = *(uint4*)flb;
            *(uint4*)(g_fci_lo + cib + c - 7)  = *(uint4*)(flb + 8);
        }
    }
    g_inv[n * LL + l] = 1.f / fmaxf(sqrtf(s), EPSV);
}

// ---------------- prep: conv weights -> [tap][chunk][m][k] bf16 hi/lo ----------------
__global__ __launch_bounds__(256) void k_wprep(const float* __restrict__ w) {
    int i = blockIdx.x * 256 + threadIdx.x;   // 73728
    int t = i >> 13;
    int r = i & 8191;
    int chn = r >> 9;
    int m = (r >> 4) & 31;
    int kk = r & 15;
    int c = chn * 16 + kk;
    float x = w[((size_t)m * CC + c) * 9 + t];
    __nv_bfloat16 h = __float2bfloat16_rn(x);
    g_cwhi[i] = h;
    g_cwlo[i] = __float2bfloat16_rn(x - __bfloat162float(h));
}

// ---------------- kernel 2: 3x3 conv on normalized-on-the-fly input + fused softmax ----------------
// Reads RAW g_fci halo, scales by g_inv per pixel, re-splits. Emits sa' = sa*inv[pixel]
// and per-CTA unscaled ssum partials.
__global__ __launch_bounds__(256) void k_conv_mma(const float* __restrict__ bias) {
    __shared__ __align__(16) __nv_bfloat16 hHi[18 * 18 * 16];
    __shared__ __align__(16) __nv_bfloat16 hLo[18 * 18 * 16];
    __shared__ __align__(16) __nv_bfloat16 wHi[9 * 32 * 16];
    __shared__ __align__(16) __nv_bfloat16 wLo[9 * 32 * 16];
    __shared__ float sInv[324];
    __shared__ float sred[8][33];
    __shared__ float bsm[32];
    int n = blockIdx.z;
    int ty0 = blockIdx.y * 16, tx0 = blockIdx.x * 16;
    int tid = threadIdx.x, wid = tid >> 5, lane = tid & 31;
    int g = lane >> 2, c4 = lane & 3;
    if (tid < 32) bsm[tid] = bias[tid];
    // per-halo-pixel inv (0 for OOB; OOB data is zeroed anyway)
    for (int i = tid; i < 324; i += 256) {
        int y = i / 18, x = i - 18 * y;
        int gy = ty0 + y - 1, gx = tx0 + x - 1;
        sInv[i] = ((unsigned)gy < 64u && (unsigned)gx < 64u) ? g_inv[n * LL + gy * 64 + gx] : 0.f;
    }

    float d[2][4][4];
#pragma unroll
    for (int mt = 0; mt < 2; mt++)
#pragma unroll
        for (int nt = 0; nt < 4; nt++)
#pragma unroll
            for (int e = 0; e < 4; e++) d[mt][nt][e] = 0.f;

#pragma unroll 1
    for (int chk = 0; chk < 16; chk++) {
        int c0 = chk * 16;
        __syncthreads();
        // halo: raw bf16 hi/lo -> reconstruct f32, * inv, re-split
        for (int i = tid; i < 648; i += 256) {
            int slot = i >> 1, half = i & 1;
            int y = slot / 18, x = slot - y * 18;
            int gy = ty0 + y - 1, gx = tx0 + x - 1;
            uint4 vh = make_uint4(0, 0, 0, 0), vl = make_uint4(0, 0, 0, 0);
            if ((unsigned)gy < 64u && (unsigned)gx < 64u) {
                size_t off = ((size_t)n * LL + gy * 64 + gx) * CC + c0 + half * 8;
                vh = *(const uint4*)(g_fci_hi + off);
                vl = *(const uint4*)(g_fci_lo + off);
            }
            float iv = sInv[slot];
            uint32_t oh[4], ol[4];
            const uint32_t* ph = (const uint32_t*)&vh;
            const uint32_t* pl = (const uint32_t*)&vl;
#pragma unroll
            for (int j = 0; j < 4; j++) {
                uint32_t h2 = ph[j], l2 = pl[j];
                float x0 = __bfloat162float(__ushort_as_bfloat16((unsigned short)(h2 & 0xffff)))
                         + __bfloat162float(__ushort_as_bfloat16((unsigned short)(l2 & 0xffff)));
                float x1 = __bfloat162float(__ushort_as_bfloat16((unsigned short)(h2 >> 16)))
                         + __bfloat162float(__ushort_as_bfloat16((unsigned short)(l2 >> 16)));
                x0 *= iv; x1 *= iv;
                __nv_bfloat16 n0 = __float2bfloat16_rn(x0), n1 = __float2bfloat16_rn(x1);
                oh[j] = pk2(n0, n1);
                ol[j] = pk2(__float2bfloat16_rn(x0 - __bfloat162float(n0)),
                            __float2bfloat16_rn(x1 - __bfloat162float(n1)));
            }
            *(uint4*)(hHi + slot * 16 + half * 8) = *(uint4*)oh;
            *(uint4*)(hLo + slot * 16 + half * 8) = *(uint4*)ol;
        }
        for (int i = tid; i < 576; i += 256) {
            int t = i >> 6, r = i & 63;
            ((uint4*)wHi)[t * 64 + r] = ((const uint4*)g_cwhi)[(t * 16 + chk) * 64 + r];
            ((uint4*)wLo)[t * 64 + r] = ((const uint4*)g_cwlo)[(t * 16 + chk) * 64 + r];
        }
        __syncthreads();
#pragma unroll
        for (int tap = 0; tap < 9; tap++) {
            int r = tap / 3, s = tap - 3 * (tap / 3);
            uint32_t bh[4][2], bl[4][2];
#pragma unroll
            for (int nt = 0; nt < 4; nt++) {
                int pxl = wid * 32 + nt * 8 + g;
                int y = (pxl >> 4) + r, x = (pxl & 15) + s;
                const __nv_bfloat16* ph = hHi + (y * 18 + x) * 16 + 2 * c4;
                const __nv_bfloat16* pl = hLo + (y * 18 + x) * 16 + 2 * c4;
                bh[nt][0] = *(const uint32_t*)ph;
                bh[nt][1] = *(const uint32_t*)(ph + 8);
                bl[nt][0] = *(const uint32_t*)pl;
                bl[nt][1] = *(const uint32_t*)(pl + 8);
            }
#pragma unroll
            for (int mt = 0; mt < 2; mt++) {
                const __nv_bfloat16* qh = wHi + (tap * 32 + mt * 16 + g) * 16 + 2 * c4;
                const __nv_bfloat16* ql = wLo + (tap * 32 + mt * 16 + g) * 16 + 2 * c4;
                uint32_t ah0 = *(const uint32_t*)qh;
                uint32_t ah1 = *(const uint32_t*)(qh + 128);
                uint32_t ah2 = *(const uint32_t*)(qh + 8);
                uint32_t ah3 = *(const uint32_t*)(qh + 136);
                uint32_t al0 = *(const uint32_t*)ql;
                uint32_t al1 = *(const uint32_t*)(ql + 128);
                uint32_t al2 = *(const uint32_t*)(ql + 8);
                uint32_t al3 = *(const uint32_t*)(ql + 136);
#pragma unroll
                for (int nt = 0; nt < 4; nt++) {
                    mma16816(d[mt][nt], ah0, ah1, ah2, ah3, bh[nt][0], bh[nt][1]);
                    mma16816(d[mt][nt], ah0, ah1, ah2, ah3, bl[nt][0], bl[nt][1]);
                    mma16816(d[mt][nt], al0, al1, al2, al3, bh[nt][0], bh[nt][1]);
                }
            }
        }
    }
    // fused softmax; emit sa' = sa * inv[pixel]; accumulate unscaled ssum partials
#pragma unroll
    for (int mt = 0; mt < 2; mt++)
#pragma unroll
        for (int nt = 0; nt < 4; nt++)
#pragma unroll
            for (int e = 0; e < 4; e++)
                d[mt][nt][e] += bsm[mt * 16 + g + (e >> 1) * 8];
    float ssacc[4] = {0.f, 0.f, 0.f, 0.f};   // k = g, g+8, g+16, g+24
#pragma unroll
    for (int nt = 0; nt < 4; nt++) {
#pragma unroll
        for (int e1 = 0; e1 < 2; e1++) {
            float v00 = d[0][nt][e1], v01 = d[0][nt][e1 + 2];
            float v10 = d[1][nt][e1], v11 = d[1][nt][e1 + 2];
            float m = fmaxf(fmaxf(v00, v01), fmaxf(v10, v11));
            m = fmaxf(m, __shfl_xor_sync(0xffffffffu, m, 4));
            m = fmaxf(m, __shfl_xor_sync(0xffffffffu, m, 8));
            m = fmaxf(m, __shfl_xor_sync(0xffffffffu, m, 16));
            float e00 = __expf(v00 - m), e01 = __expf(v01 - m);
            float e10 = __expf(v10 - m), e11 = __expf(v11 - m);
            float s = e00 + e01 + e10 + e11;
            s += __shfl_xor_sync(0xffffffffu, s, 4);
            s += __shfl_xor_sync(0xffffffffu, s, 8);
            s += __shfl_xor_sync(0xffffffffu, s, 16);
            float inv = 1.f / s;
            float sa00 = e00 * inv, sa01 = e01 * inv;
            float sa10 = e10 * inv, sa11 = e11 * inv;
            ssacc[0] += sa00; ssacc[1] += sa01;
            ssacc[2] += sa10; ssacc[3] += sa11;
            int px = wid * 32 + nt * 8 + 2 * c4 + e1;
            float pxinv = sInv[((px >> 4) + 1) * 18 + (px & 15) + 1];
            int gy = ty0 + (px >> 4), gx = tx0 + (px & 15);
            size_t base = ((size_t)n * KK) * LL + gy * 64 + gx;
            g_sa[base + (size_t)g * LL]        = sa00 * pxinv;
            g_sa[base + (size_t)(g + 8) * LL]  = sa01 * pxinv;
            g_sa[base + (size_t)(g + 16) * LL] = sa10 * pxinv;
            g_sa[base + (size_t)(g + 24) * LL] = sa11 * pxinv;
        }
    }
    // reduce ssum partials: over c4 (shfl), then warps (smem), write per-CTA
#pragma unroll
    for (int j = 0; j < 4; j++) {
        ssacc[j] += __shfl_xor_sync(0xffffffffu, ssacc[j], 1);
        ssacc[j] += __shfl_xor_sync(0xffffffffu, ssacc[j], 2);
    }
    if (c4 == 0) {
        sred[wid][g]      = ssacc[0];
        sred[wid][g + 8]  = ssacc[1];
        sred[wid][g + 16] = ssacc[2];
        sred[wid][g + 24] = ssacc[3];
    }
    __syncthreads();
    if (tid < 32) {
        float t = 0.f;
#pragma unroll
        for (int w = 0; w < 8; w++) t += sred[w][tid];
        int tile = blockIdx.y * 4 + blockIdx.x;
        g_ssumc[(n * 16 + tile) * KK + tid] = t;
    }
}

// ---------------- kernel 4: einsum partials from sa' and RAW feature ----------------
#define XP 68
__global__ __launch_bounds__(256, 4) void k_up0(const float* __restrict__ f) {
    int n = blockIdx.y;
    int c0 = blockIdx.x * 128;
    int sp = blockIdx.z;
    int lbase = sp * (LL / SPL);
    __shared__ float sas[KK][XP];
    __shared__ float xcs[128][XP];
    int tid = threadIdx.x;
    int kt = tid >> 4, ct = tid & 15;
    float acc[2][8];
#pragma unroll
    for (int i = 0; i < 2; i++)
#pragma unroll
        for (int j = 0; j < 8; j++) acc[i][j] = 0.f;
#pragma unroll 1
    for (int ch = 0; ch < 4; ch++) {
        int l0 = lbase + ch * 64;
        __syncthreads();
        for (int i = tid; i < 32 * 16; i += 256) {
            int k = i >> 4, l4 = (i & 15) << 2;
            *(float4*)&sas[k][l4] = *(const float4*)(g_sa + (size_t)(n * KK + k) * LL + l0 + l4);
        }
        for (int i = tid; i < 128 * 16; i += 256) {
            int c = i >> 4, l4 = (i & 15) << 2;
            *(float4*)&xcs[c][l4] = *(const float4*)(f + (size_t)(n * CC + c0 + c) * LL + l0 + l4);
        }
        __syncthreads();
#pragma unroll 4
        for (int l4 = 0; l4 < 64; l4 += 4) {
            float4 a0 = *(const float4*)&sas[kt][l4];
            float4 a1 = *(const float4*)&sas[kt + 16][l4];
#pragma unroll
            for (int cj = 0; cj < 8; cj++) {
                float4 b = *(const float4*)&xcs[ct + 16 * cj][l4];
                acc[0][cj] += a0.x * b.x + a0.y * b.y + a0.z * b.z + a0.w * b.w;
                acc[1][cj] += a1.x * b.x + a1.y * b.y + a1.z * b.z + a1.w * b.w;
            }
        }
    }
    size_t ob = ((size_t)sp * NN + n) * (KK * CC);
#pragma unroll
    for (int cj = 0; cj < 8; cj++) {
        g_up0p[ob + kt * CC + c0 + ct + 16 * cj] = acc[0][cj];
        g_up0p[ob + (kt + 16) * CC + c0 + ct + 16 * cj] = acc[1][cj];
    }
}

// ---------------- kernel 5a: reduce partials + centroid-sub + norms -> g_upn ----------------
__global__ __launch_bounds__(256) void k_upnorm(const float* __restrict__ cent) {
    int n = blockIdx.x;
    int tid = threadIdx.x;
    int lane = tid & 31, wp = tid >> 5;
    __shared__ float upn[KK * CC];
    __shared__ float red[8];
    __shared__ float ssk[KK];
    __shared__ float gtot;

    if (tid < KK) {
        float s = 0.f;
#pragma unroll
        for (int t = 0; t < 16; t++)
            s += g_ssumc[(n * 16 + t) * KK + tid];
        ssk[tid] = s;
    }
    __syncthreads();

    for (int k = wp; k < KK; k += 8) {
        float sk = ssk[k];
        float vals[8];
        float sq = 0.f;
#pragma unroll
        for (int j = 0; j < 8; j++) {
            int c = lane + 32 * j;
            float u = 0.f;
#pragma unroll
            for (int sp = 0; sp < SPL; sp++)
                u += g_up0p[((size_t)sp * NN + n) * (KK * CC) + k * CC + c];
            u -= sk * cent[k * CC + c];
            vals[j] = u;
            sq += u * u;
        }
        for (int off = 16; off; off >>= 1) sq += __shfl_xor_sync(0xffffffffu, sq, off);
        float inv = 1.f / fmaxf(sqrtf(sq), EPSV);
#pragma unroll
        for (int j = 0; j < 8; j++) upn[k * CC + lane + 32 * j] = vals[j] * inv;
    }
    __syncthreads();
    float gs = 0.f;
#pragma unroll 4
    for (int j = 0; j < 32; j++) {
        float v = upn[j * 256 + tid];
        gs += v * v;
    }
    for (int off = 16; off; off >>= 1) gs += __shfl_xor_sync(0xffffffffu, gs, off);
    if (!lane) red[wp] = gs;
    __syncthreads();
    if (tid == 0) {
        float t = 0.f;
        for (int i = 0; i < 8; i++) t += red[i];
        gtot = 1.f / fmaxf(sqrtf(t), EPSV);
    }
    __syncthreads();
    float ginv = gtot;
#pragma unroll 4
    for (int j = 0; j < 32; j++)
        g_upn[n * (KK * CC) + j * 256 + tid] = upn[j * 256 + tid] * ginv;
}

// ---------------- kernel 5b: FC partials ----------------
#define FCP 264
__global__ __launch_bounds__(256) void k_fc(const float* __restrict__ wfc) {
    __shared__ float ws[16][FCP];
    __shared__ float us[16][FCP];
    int ot = blockIdx.x * 16;
    int j0 = blockIdx.y * 256;
    int tid = threadIdx.x;
    for (int i = tid; i < 16 * 64; i += 256) {
        int row = i >> 6, j4 = (i & 63) << 2;
        *(float4*)&ws[row][j4] = *(const float4*)(wfc + (size_t)(ot + row) * (KK * CC) + j0 + j4);
        *(float4*)&us[row][j4] = *(const float4*)(g_upn + (size_t)row * (KK * CC) + j0 + j4);
    }
    __syncthreads();
    int o = tid & 15, n = tid >> 4;
    float s = 0.f;
#pragma unroll 8
    for (int jj = 0; jj < 64; jj++) {
        float4 a = *(const float4*)&ws[o][jj * 4];
        float4 b = *(const float4*)&us[n][jj * 4];
        s += a.x * b.x + a.y * b.y + a.z * b.z + a.w * b.w;
    }
    g_fcp[(size_t)(blockIdx.y * NN + n) * CC + ot + o] = s;
}

__global__ __launch_bounds__(256) void k_fcred(const float* __restrict__ bfc) {
    int n = blockIdx.x, o = threadIdx.x;
    float s = 0.f;
#pragma unroll
    for (int js = 0; js < JS; js++)
        s += g_fcp[(size_t)(js * NN + n) * CC + o];
    g_ufc[n * CC + o] = s + bfc[o];
}

__global__ __launch_bounds__(256) void k_bias1(const float* __restrict__ t1w,
                                               const float* __restrict__ t1b) {
    int n = blockIdx.y;
    int o = blockIdx.x * 32 + (threadIdx.x >> 3);
    int grp = threadIdx.x & 7;
    float s = 0.f;
#pragma unroll
    for (int q = 0; q < 8; q++) {
        int c = grp * 32 + q * 4;
        float4 wv = *(const float4*)(t1w + (size_t)o * 512 + 256 + c);
        float4 uv = *(const float4*)(g_ufc + n * CC + c);
        s += wv.x * uv.x + wv.y * uv.y + wv.z * uv.z + wv.w * uv.w;
    }
#pragma unroll
    for (int off = 4; off; off >>= 1)
        s += __shfl_down_sync(0xffffffffu, s, off, 8);
    if (grp == 0) g_bias1[n * CC + o] = t1b[o] + s;
}

// ---------------- prep: split t1/t2 weights ----------------
__global__ __launch_bounds__(256) void k_wsplit(const float* __restrict__ t1w,
                                                const float* __restrict__ t2w) {
    int i = blockIdx.x * 256 + threadIdx.x;
    int o = i >> 8, c = i & 255;
    {
        float x = t1w[(size_t)o * 512 + c];
        __nv_bfloat16 h = __float2bfloat16_rn(x);
        g_w1hi[i] = h;
        g_w1lo[i] = __float2bfloat16_rn(x - __bfloat162float(h));
    }
    {
        float x = t2w[i];
        __nv_bfloat16 h = __float2bfloat16_rn(x);
        g_w2hi[i] = h;
        g_w2lo[i] = __float2bfloat16_rn(x - __bfloat162float(h));
    }
}

// ---------------- kernel 6: mma.sync transform, cp.async double-buffered ----------------
#define W2P    80
#define SM_WOF 2048
#define SM_XOF 83968
#define SM_HOF 104448
#define SM_TOT 174080
#define HPITCH 528

__global__ __launch_bounds__(256, 1) void k_transform_mma(const float* __restrict__ t2b,
                                                          float* __restrict__ out) {
    extern __shared__ char sm[];
    uint32_t sb = smem_u32(sm);
    float* b1s = (float*)sm;
    float* b2s = (float*)(sm + 1024);
    int tid = threadIdx.x;
    int wid = tid >> 5, lane = tid & 31;
    int g = lane >> 2, c4 = lane & 3;
    int ow = (wid >> 1) * 64;
    int pxw = (wid & 1) * 32;
    int n = blockIdx.y;
    int p0 = blockIdx.x * 64;

    b1s[tid] = g_bias1[n * CC + tid];
    b2s[tid] = t2b[tid];

#define ISSUE_W(whi, wlo, kc, b)                                                   \
    do {                                                                           \
        uint32_t wb_ = sb + SM_WOF + (b) * 40960;                                  \
        for (int i_ = tid; i_ < 2048; i_ += 256) {                                 \
            int half_ = i_ >> 10;                                                  \
            int r_ = i_ & 1023;                                                    \
            int o_ = r_ >> 2, j_ = r_ & 3;                                         \
            const __nv_bfloat16* s_ = (half_ ? (wlo) : (whi)) + o_ * 256 + (kc) * 32 + j_ * 8; \
            CP16(wb_ + half_ * 20480 + o_ * W2P + j_ * 16, s_);                    \
        }                                                                          \
    } while (0)
#define ISSUE_X(kc, b)                                                             \
    do {                                                                           \
        uint32_t xb_ = sb + SM_XOF + (b) * 10240;                                  \
        for (int i_ = tid; i_ < 512; i_ += 256) {                                  \
            int half_ = i_ >> 8;                                                   \
            int r_ = i_ & 255;                                                     \
            int px_ = r_ >> 2, j_ = r_ & 3;                                        \
            const __nv_bfloat16* s_ = (half_ ? g_fci_lo : g_fci_hi)                \
                + ((size_t)n * LL + p0 + px_) * CC + (kc) * 32 + j_ * 8;           \
            CP16(xb_ + half_ * 5120 + px_ * W2P + j_ * 16, s_);                    \
        }                                                                          \
    } while (0)

    float d[4][4][4];
#pragma unroll
    for (int mt = 0; mt < 4; mt++)
#pragma unroll
        for (int nt = 0; nt < 4; nt++)
#pragma unroll
            for (int e = 0; e < 4; e++) d[mt][nt][e] = 0.f;

    // ================= stage 1: D1 = W1 @ X =================
    ISSUE_W(g_w1hi, g_w1lo, 0, 0);
    ISSUE_X(0, 0);
    CP_COMMIT();
#pragma unroll 1
    for (int kc = 0; kc < 8; kc++) {
        int b = kc & 1;
        if (kc < 7) {
            ISSUE_W(g_w1hi, g_w1lo, kc + 1, 1 - b);
            ISSUE_X(kc + 1, 1 - b);
            CP_COMMIT();
            CP_WAIT1();
        } else {
            CP_WAIT0();
        }
        __syncthreads();
        const char* wb = sm + SM_WOF + b * 40960;
        const char* xb = sm + SM_XOF + b * 10240;
#pragma unroll
        for (int kk = 0; kk < 2; kk++) {
            int kb = kk * 32 + c4 * 4;
            uint32_t bh[4][2], bl[4][2];
#pragma unroll
            for (int nt = 0; nt < 4; nt++) {
                int prow = pxw + nt * 8 + g;
                bh[nt][0] = *(const uint32_t*)(xb + prow * W2P + kb);
                bh[nt][1] = *(const uint32_t*)(xb + prow * W2P + kb + 16);
                bl[nt][0] = *(const uint32_t*)(xb + 5120 + prow * W2P + kb);
                bl[nt][1] = *(const uint32_t*)(xb + 5120 + prow * W2P + kb + 16);
            }
#pragma unroll
            for (int mt = 0; mt < 4; mt++) {
                int orow = ow + mt * 16 + g;
                const char* wh = wb + orow * W2P + kb;
                const char* wl = wb + 20480 + orow * W2P + kb;
                uint32_t ah0 = *(const uint32_t*)(wh);
                uint32_t ah1 = *(const uint32_t*)(wh + 8 * W2P);
                uint32_t ah2 = *(const uint32_t*)(wh + 16);
                uint32_t ah3 = *(const uint32_t*)(wh + 8 * W2P + 16);
                uint32_t al0 = *(const uint32_t*)(wl);
                uint32_t al1 = *(const uint32_t*)(wl + 8 * W2P);
                uint32_t al2 = *(const uint32_t*)(wl + 16);
                uint32_t al3 = *(const uint32_t*)(wl + 8 * W2P + 16);
#pragma unroll
                for (int nt = 0; nt < 4; nt++) {
                    mma16816(d[mt][nt], ah0, ah1, ah2, ah3, bh[nt][0], bh[nt][1]);
                    mma16816(d[mt][nt], ah0, ah1, ah2, ah3, bl[nt][0], bl[nt][1]);
                    mma16816(d[mt][nt], al0, al1, al2, al3, bh[nt][0], bh[nt][1]);
                }
            }
        }
        __syncthreads();
    }
    // h = relu(D1 + bias1) -> smem [px][o] bf16 hi/lo
    {
        __nv_bfloat16* hh = (__nv_bfloat16*)(sm + SM_HOF);
        __nv_bfloat16* hl = (__nv_bfloat16*)(sm + SM_HOF + 64 * HPITCH);
#pragma unroll
        for (int mt = 0; mt < 4; mt++) {
#pragma unroll
            for (int nt = 0; nt < 4; nt++) {
                int oa = ow + mt * 16 + g, ob = oa + 8;
                int pa = pxw + nt * 8 + 2 * c4, pb = pa + 1;
                float v0 = fmaxf(d[mt][nt][0] + b1s[oa], 0.f);
                float v1 = fmaxf(d[mt][nt][1] + b1s[oa], 0.f);
                float v2 = fmaxf(d[mt][nt][2] + b1s[ob], 0.f);
                float v3 = fmaxf(d[mt][nt][3] + b1s[ob], 0.f);
                __nv_bfloat16 h0 = __float2bfloat16_rn(v0);
                __nv_bfloat16 h1 = __float2bfloat16_rn(v1);
                __nv_bfloat16 h2 = __float2bfloat16_rn(v2);
                __nv_bfloat16 h3 = __float2bfloat16_rn(v3);
                hh[pa * (HPITCH / 2) + oa] = h0;
                hh[pb * (HPITCH / 2) + oa] = h1;
                hh[pa * (HPITCH / 2) + ob] = h2;
                hh[pb * (HPITCH / 2) + ob] = h3;
                hl[pa * (HPITCH / 2) + oa] = __float2bfloat16_rn(v0 - __bfloat162float(h0));
                hl[pb * (HPITCH / 2) + oa] = __float2bfloat16_rn(v1 - __bfloat162float(h1));
                hl[pa * (HPITCH / 2) + ob] = __float2bfloat16_rn(v2 - __bfloat162float(h2));
                hl[pb * (HPITCH / 2) + ob] = __float2bfloat16_rn(v3 - __bfloat162float(h3));
                d[mt][nt][0] = 0.f; d[mt][nt][1] = 0.f;
                d[mt][nt][2] = 0.f; d[mt][nt][3] = 0.f;
            }
        }
    }
    __syncthreads();

    // ================= stage 2: D2 = W2 @ h =================
    ISSUE_W(g_w2hi, g_w2lo, 0, 0);
    CP_COMMIT();
#pragma unroll 1
    for (int kc = 0; kc < 8; kc++) {
        int b = kc & 1;
        if (kc < 7) {
            ISSUE_W(g_w2hi, g_w2lo, kc + 1, 1 - b);
            CP_COMMIT();
            CP_WAIT1();
        } else {
            CP_WAIT0();
        }
        __syncthreads();
        const char* wb = sm + SM_WOF + b * 40960;
#pragma unroll
        for (int kk = 0; kk < 2; kk++) {
            int kb = kk * 32 + c4 * 4;
            int kbh = kc * 64 + kk * 32 + c4 * 4;
            uint32_t bh[4][2], bl[4][2];
#pragma unroll
            for (int nt = 0; nt < 4; nt++) {
                int prow = pxw + nt * 8 + g;
                bh[nt][0] = *(const uint32_t*)(sm + SM_HOF + prow * HPITCH + kbh);
                bh[nt][1] = *(const uint32_t*)(sm + SM_HOF + prow * HPITCH + kbh + 16);
                bl[nt][0] = *(const uint32_t*)(sm + SM_HOF + 64 * HPITCH + prow * HPITCH + kbh);
                bl[nt][1] = *(const uint32_t*)(sm + SM_HOF + 64 * HPITCH + prow * HPITCH + kbh + 16);
            }
#pragma unroll
            for (int mt = 0; mt < 4; mt++) {
                int orow = ow + mt * 16 + g;
                const char* wh = wb + orow * W2P + kb;
                const char* wl = wb + 20480 + orow * W2P + kb;
                uint32_t ah0 = *(const uint32_t*)(wh);
                uint32_t ah1 = *(const uint32_t*)(wh + 8 * W2P);
                uint32_t ah2 = *(const uint32_t*)(wh + 16);
                uint32_t ah3 = *(const uint32_t*)(wh + 8 * W2P + 16);
                uint32_t al0 = *(const uint32_t*)(wl);
                uint32_t al1 = *(const uint32_t*)(wl + 8 * W2P);
                uint32_t al2 = *(const uint32_t*)(wl + 16);
                uint32_t al3 = *(const uint32_t*)(wl + 8 * W2P + 16);
#pragma unroll
                for (int nt = 0; nt < 4; nt++) {
                    mma16816(d[mt][nt], ah0, ah1, ah2, ah3, bh[nt][0], bh[nt][1]);
                    mma16816(d[mt][nt], ah0, ah1, ah2, ah3, bl[nt][0], bl[nt][1]);
                    mma16816(d[mt][nt], al0, al1, al2, al3, bh[nt][0], bh[nt][1]);
                }
            }
        }
        __syncthreads();
    }
    // epilogue
    {
        float* epi = (float*)(sm + SM_HOF);
#pragma unroll
        for (int mt = 0; mt < 4; mt++) {
#pragma unroll
            for (int nt = 0; nt < 4; nt++) {
                int oa = ow + mt * 16 + g, ob = oa + 8;
                int pa = pxw + nt * 8 + 2 * c4, pb = pa + 1;
                epi[oa * 68 + pa] = fmaxf(d[mt][nt][0] + b2s[oa], 0.f);
                epi[oa * 68 + pb] = fmaxf(d[mt][nt][1] + b2s[oa], 0.f);
                epi[ob * 68 + pa] = fmaxf(d[mt][nt][2] + b2s[ob], 0.f);
                epi[ob * 68 + pb] = fmaxf(d[mt][nt][3] + b2s[ob], 0.f);
            }
        }
        __syncthreads();
        for (int i = tid; i < 16384; i += 256) {
            int o = i >> 6, px = i & 63;
            out[(size_t)(n * CC + o) * LL + p0 + px] = epi[o * 68 + px];
        }
    }
#undef ISSUE_W
#undef ISSUE_X
}

// ---------------- launch ----------------
extern "C" void kernel_launch(void* const* d_in, const int* in_sizes, int n_in,
                              void* d_out, int out_size) {
    (void)in_sizes; (void)n_in; (void)out_size;
    const float* feature   = (const float*)d_in[0];
    const float* conv_up_w = (const float*)d_in[1];
    const float* conv_up_b = (const float*)d_in[2];
    const float* centroids = (const float*)d_in[3];
    const float* upfc_w    = (const float*)d_in[4];
    const float* upfc_b    = (const float*)d_in[5];
    const float* t1_w      = (const float*)d_in[6];
    const float* t1_b      = (const float*)d_in[7];
    const float* t2_w      = (const float*)d_in[8];
    const float* t2_b      = (const float*)d_in[9];
    float* out = (float*)d_out;

    cudaFuncSetAttribute(k_transform_mma, cudaFuncAttributeMaxDynamicSharedMemorySize, SM_TOT);

    k_wprep<<<288, 256>>>(conv_up_w);
    k_prep<<<dim3(16, 16), 256>>>(feature);
    k_conv_mma<<<dim3(4, 4, 16), 256>>>(conv_up_b);
    k_up0<<<dim3(2, 16, SPL), 256>>>(feature);
    k_upnorm<<<NN, 256>>>(centroids);
    k_fc<<<dim3(16, JS), 256>>>(upfc_w);
    k_fcred<<<NN, 256>>>(upfc_b);
    k_bias1<<<dim3(8, 16), 256>>>(t1_w, t1_b);
    k_wsplit<<<256, 256>>>(t1_w, t2_w);
    k_transform_mma<<<dim3(64, 16), 256, SM_TOT>>>(t2_b, out);
}